// round 5
// baseline (speedup 1.0000x reference)
#include <cuda_runtime.h>
#include <cstdint>
#include <cstddef>

#define CC   0.1f
#define SCc  0.31622776601683794f   /* sqrt(0.1) */
#define EPSc 1e-7f

#define Bd  64
#define Nd  1024
#define Dd  128
#define DX  129
#define NCd 10

// ---------------- scratch (device globals; no runtime allocation) ----------
__device__ float g_x [(size_t)Bd*Nd*DX];   // Lorentz points (B,N,129)
__device__ float g_mu[(size_t)Bd*Nd*DX];   // normalized centroids (B,N,129)
__device__ float g_y [(size_t)Bd*Nd*Dd];   // Poincare tokens (B,N,128)
__device__ float g_y2[(size_t)Bd*Nd];      // |y|^2 per token
__device__ unsigned char g_mask[(size_t)Bd*Nd];
__device__ int g_is32;

// ---------------- kernel 0a: detect mask dtype (u8 bool vs int32) ----------
__global__ void k_detect(const unsigned char* __restrict__ m)
{
    __shared__ int found;
    if (threadIdx.x == 0) found = 0;
    __syncthreads();
    int acc = 0;
    for (int i = threadIdx.x; i < Bd*Nd; i += blockDim.x)
        if ((i & 3) && m[i]) acc = 1;
    if (acc) atomicOr(&found, 1);
    __syncthreads();
    if (threadIdx.x == 0) g_is32 = found ? 0 : 1;
}

// ---------------- kernel 0b: normalize mask to uint8 -----------------------
__global__ void k_masknorm(const void* __restrict__ m)
{
    int i = blockIdx.x * blockDim.x + threadIdx.x;
    if (i >= Bd*Nd) return;
    unsigned char v;
    if (g_is32) v = (((const int*)m)[i] != 0);
    else        v = (((const unsigned char*)m)[i] != 0);
    g_mask[i] = v;
}

// ---------------- kernel 1: embedding + Lorentz expmap0 --------------------
__global__ void k_embed(const int* __restrict__ tok, const float* __restrict__ emb)
{
    int gw   = (blockIdx.x * blockDim.x + threadIdx.x) >> 5;
    int lane = threadIdx.x & 31;
    if (gw >= Bd*Nd) return;
    int t = tok[gw];
    float4 v = *(const float4*)(emb + (size_t)t*Dd + lane*4);
    float ss = v.x*v.x + v.y*v.y + v.z*v.z + v.w*v.w;
    #pragma unroll
    for (int o = 16; o; o >>= 1) ss += __shfl_xor_sync(0xffffffffu, ss, o);
    float nv   = fmaxf(sqrtf(ss), EPSc);
    float tt   = SCc * nv;
    float coef = sinhf(tt) / (SCc * nv);
    float* xr  = g_x + (size_t)gw * DX;
    if (lane == 0) xr[0] = coshf(tt) / SCc;
    xr[1 + lane*4 + 0] = coef * v.x;
    xr[1 + lane*4 + 1] = coef * v.y;
    xr[1 + lane*4 + 2] = coef * v.z;
    xr[1 + lane*4 + 3] = coef * v.w;
}

// ---------------- kernel 2: attention + Lorentz centroid -------------------
// grid (16, 64), 256 threads. Tile 64 queries x 64 keys. All exact fp32.
#define SJ 148   // row stride (floats): %4==0 (float4 aligned), %32==20 (conflict-free)
#define SE 65
#define TI 64
#define TJ 64

__global__ __launch_bounds__(256, 2)
void k_attn()
{
    extern __shared__ float sm[];
    float* Xi  = sm;                 // 64*148
    float* Xj  = Xi + TI*SJ;         // 64*148
    float* E   = Xj + TJ*SJ;         // 64*65
    float* MS  = E  + TI*SE;         // 64
    float* DEN = MS + TJ;            // 64
    float* INN = DEN + TI;           // 64

    const int tid = threadIdx.x;
    const int b   = blockIdx.y;
    const int i0  = blockIdx.x * TI;
    const float invsq = 1.0f / sqrtf(129.0f);

    if (tid < TI) { DEN[tid] = 0.f; INN[tid] = 0.f; }

    const float* xb = g_x + ((size_t)b*Nd + i0) * DX;
    for (int idx = tid; idx < TI*DX; idx += 256) {
        int i = idx / DX, k = idx - i*DX;
        float v = xb[idx];
        Xi[i*SJ + k] = (k == 0) ? v : -v;
    }
    for (int idx = tid; idx < TI*(SJ-DX); idx += 256) {
        int i = idx / (SJ-DX), k = DX + (idx - i*(SJ-DX));
        Xi[i*SJ + k] = 0.f;
        Xj[i*SJ + k] = 0.f;
    }

    const int tx = tid & 15, ty = tid >> 4;   // score mapping
    const int i2 = tid & 63, dg = tid >> 6;   // aggregation mapping
    const int d0 = dg * 36;

    float mur[36];
    #pragma unroll
    for (int m = 0; m < 36; m++) mur[m] = 0.f;
    float denp[4] = {0.f, 0.f, 0.f, 0.f};

    __syncthreads();

    for (int jt = 0; jt < Nd/TJ; jt++) {
        const float* xjb = g_x + ((size_t)b*Nd + jt*TJ) * DX;
        for (int idx = tid; idx < TJ*DX; idx += 256) {
            int j = idx / DX, k = idx - j*DX;
            Xj[j*SJ + k] = xjb[idx];
        }
        if (tid < TJ) MS[tid] = g_mask[b*Nd + jt*TJ + tid] ? 1.f : 0.f;
        __syncthreads();

        // ---- scores: thread computes rows i=ty*4+r, cols j=tx+16q ----
        float acc[4][4];
        #pragma unroll
        for (int r = 0; r < 4; r++)
            #pragma unroll
            for (int q = 0; q < 4; q++) acc[r][q] = 0.f;

        for (int k = 0; k < SJ; k += 4) {
            float4 av[4], bv[4];
            #pragma unroll
            for (int r = 0; r < 4; r++) av[r] = *(const float4*)&Xi[(ty*4+r)*SJ + k];
            #pragma unroll
            for (int q = 0; q < 4; q++) bv[q] = *(const float4*)&Xj[(tx+16*q)*SJ + k];
            #pragma unroll
            for (int r = 0; r < 4; r++)
                #pragma unroll
                for (int q = 0; q < 4; q++)
                    acc[r][q] += av[r].x*bv[q].x + av[r].y*bv[q].y
                               + av[r].z*bv[q].z + av[r].w*bv[q].w;
        }
        #pragma unroll
        for (int r = 0; r < 4; r++)
            #pragma unroll
            for (int q = 0; q < 4; q++) {
                int j = tx + 16*q;
                float e = MS[j] * __expf(acc[r][q] * invsq);
                E[(ty*4+r)*SE + j] = e;
                denp[r] += e;
            }
        __syncthreads();

        // ---- aggregation: mu[i2][d0..d0+35] += sum_j E[i2][j]*Xj[j][d] ----
        #pragma unroll 4
        for (int j = 0; j < TJ; j++) {
            float e = E[i2*SE + j];
            const float4* xr = (const float4*)&Xj[j*SJ + d0];
            #pragma unroll
            for (int m4 = 0; m4 < 9; m4++) {
                float4 xv = xr[m4];
                mur[m4*4+0] += e * xv.x;
                mur[m4*4+1] += e * xv.y;
                mur[m4*4+2] += e * xv.z;
                mur[m4*4+3] += e * xv.w;
            }
        }
        __syncthreads();
    }

    // ---- softmax denominator + Lorentz renormalization ----
    #pragma unroll
    for (int r = 0; r < 4; r++) atomicAdd(&DEN[ty*4 + r], denp[r]);
    __syncthreads();

    float id = 1.0f / DEN[i2];
    float part = 0.f;
    #pragma unroll
    for (int m = 0; m < 36; m++) {
        mur[m] *= id;
        int d = d0 + m;
        float c = mur[m] * mur[m];
        if (d < DX) part += (d == 0) ? -c : c;
    }
    atomicAdd(&INN[i2], part);
    __syncthreads();

    float s2 = 1.0f / (SCc * sqrtf(fmaxf(-INN[i2], EPSc)));
    float* mo = g_mu + ((size_t)b*Nd + i0 + i2) * DX;
    #pragma unroll
    for (int m = 0; m < 36; m++) {
        int d = d0 + m;
        if (d < DX) mo[d] = mur[m] * s2;
    }
}

// ---------------- kernel 3: output projection + Poincare expmap0 -----------
#define SW 133
__global__ __launch_bounds__(256, 2)
void k_proj(const float* __restrict__ Wo, const float* __restrict__ bo)
{
    extern __shared__ float sm[];
    float* wo  = sm;               // 128*133
    float* mus = wo  + 128*SW;     // 64*133
    float* np  = mus + 64*SW;      // 64*16
    float* fv  = np  + 64*16;      // 64
    float* bos = fv  + 64;         // 128

    const int tid = threadIdx.x;
    const size_t row0 = (size_t)blockIdx.x * 64;

    for (int idx = tid; idx < 128*DX; idx += 256) {
        int o = idx / DX, k = idx - o*DX;
        wo[o*SW + k] = Wo[idx];
    }
    const float* mb = g_mu + row0 * DX;
    for (int idx = tid; idx < 64*DX; idx += 256) {
        int i = idx / DX, k = idx - i*DX;
        mus[i*SW + k] = mb[idx];
    }
    if (tid < 128) bos[tid] = bo[tid];
    __syncthreads();

    const int tx = tid & 15, ty = tid >> 4;  // i=ty*4+r, o=tx+16q
    float acc[4][8];
    #pragma unroll
    for (int r = 0; r < 4; r++)
        #pragma unroll
        for (int q = 0; q < 8; q++) acc[r][q] = 0.f;

    for (int k = 0; k < DX; k++) {
        float mv[4], wv[8];
        #pragma unroll
        for (int r = 0; r < 4; r++) mv[r] = mus[(ty*4+r)*SW + k];
        #pragma unroll
        for (int q = 0; q < 8; q++) wv[q] = wo[(tx+16*q)*SW + k];
        #pragma unroll
        for (int r = 0; r < 4; r++)
            #pragma unroll
            for (int q = 0; q < 8; q++) acc[r][q] += mv[r]*wv[q];
    }

    #pragma unroll
    for (int r = 0; r < 4; r++) {
        float pp = 0.f;
        #pragma unroll
        for (int q = 0; q < 8; q++) {
            acc[r][q] += bos[tx + 16*q];
            pp += acc[r][q] * acc[r][q];
        }
        np[(ty*4+r)*16 + tx] = pp;
    }
    __syncthreads();

    if (tid < 64) {
        float s = 0.f;
        #pragma unroll
        for (int t = 0; t < 16; t++) s += np[tid*16 + t];
        float nu = fmaxf(sqrtf(s), EPSc);
        fv[tid] = tanhf(SCc*nu) / (SCc*nu);
    }
    __syncthreads();

    // write y = f*u, and accumulate |y|^2 from the stored y values
    float* yb = g_y + row0 * Dd;
    #pragma unroll
    for (int r = 0; r < 4; r++) {
        float f = fv[ty*4 + r];
        float pp = 0.f;
        #pragma unroll
        for (int q = 0; q < 8; q++) {
            float yv = acc[r][q] * f;
            yb[(size_t)(ty*4+r)*Dd + tx + 16*q] = yv;
            pp += yv * yv;
        }
        np[(ty*4+r)*16 + tx] = pp;
    }
    __syncthreads();
    if (tid < 64) {
        float s = 0.f;
        #pragma unroll
        for (int t = 0; t < 16; t++) s += np[tid*16 + t];
        g_y2[row0 + tid] = s;
    }
}

// ---------------- kernel 4: sequential Mobius pooling + MLR head -----------
// one warp per batch. x2 = |acc|^2 recomputed FRESH each step (dual butterfly
// with <acc,y>), and components divided by max(den,1e-12) — matches reference.
__global__ void k_pool(const float* __restrict__ Wf,
                       const float* __restrict__ bf,
                       float* __restrict__ out)
{
    const int b    = blockIdx.x;
    const int lane = threadIdx.x;
    const float* yb  = g_y  + (size_t)b*Nd*Dd;
    const float* y2b = g_y2 + (size_t)b*Nd;
    const unsigned char* mb = g_mask + (size_t)b*Nd;

    float a0=0.f, a1=0.f, a2=0.f, a3=0.f;
    int cnt = 0;

    float4 nyv = *(const float4*)(yb + lane*4);
    float  ny2 = y2b[0];

    for (int i = 0; i < Nd; i++) {
        float4 yv = nyv; float yy2 = ny2;
        int m = mb[i];
        if (i + 1 < Nd) {
            nyv = *(const float4*)(yb + (size_t)(i+1)*Dd + lane*4);
            ny2 = y2b[i+1];
        }
        if (!m) continue;
        float xy = a0*yv.x + a1*yv.y + a2*yv.z + a3*yv.w;
        float x2 = a0*a0 + a1*a1 + a2*a2 + a3*a3;
        #pragma unroll
        for (int o = 16; o; o >>= 1) {
            xy += __shfl_xor_sync(0xffffffffu, xy, o);
            x2 += __shfl_xor_sync(0xffffffffu, x2, o);
        }
        float aa  = 1.f + 2.f*CC*xy + CC*yy2;
        float bb  = 1.f - CC*x2;
        float den = fmaxf(1.f + 2.f*CC*xy + CC*CC*x2*yy2, 1e-12f);
        a0 = (aa*a0 + bb*yv.x) / den;
        a1 = (aa*a1 + bb*yv.y) / den;
        a2 = (aa*a2 + bb*yv.z) / den;
        a3 = (aa*a3 + bb*yv.w) / den;
        cnt++;
    }

    // mobius scalar-mul by 1/cnt
    float n2 = a0*a0 + a1*a1 + a2*a2 + a3*a3;
    #pragma unroll
    for (int o = 16; o; o >>= 1) n2 += __shfl_xor_sync(0xffffffffu, n2, o);
    float nrm = sqrtf(n2);
    float t   = fminf(fmaxf(SCc*nrm, EPSc), 1.f - 1e-6f);
    float r   = 1.f / fmaxf((float)cnt, 1.f);
    float fac = tanhf(r * atanhf(t)) / fmaxf(SCc*nrm, EPSc);
    float p0 = fac*a0, p1 = fac*a1, p2 = fac*a2, p3 = fac*a3;
    if (cnt == 0) {
        float4 y0 = *(const float4*)(yb + lane*4);
        p0 = y0.x; p1 = y0.y; p2 = y0.z; p3 = y0.w;
    }

    // logmap0
    float pn2 = p0*p0 + p1*p1 + p2*p2 + p3*p3;
    #pragma unroll
    for (int o = 16; o; o >>= 1) pn2 += __shfl_xor_sync(0xffffffffu, pn2, o);
    float npn = fmaxf(sqrtf(pn2), EPSc);
    float t2  = fminf(fmaxf(SCc*npn, EPSc), 1.f - 1e-6f);
    float cf  = atanhf(t2) / (SCc*npn);
    float v0 = cf*p0, v1 = cf*p1, v2 = cf*p2, v3 = cf*p3;

    // logits
    for (int k = 0; k < NCd; k++) {
        float4 w = *(const float4*)(Wf + (size_t)k*Dd + lane*4);
        float pr = v0*w.x + v1*w.y + v2*w.z + v3*w.w;
        #pragma unroll
        for (int o = 16; o; o >>= 1) pr += __shfl_xor_sync(0xffffffffu, pr, o);
        if (lane == 0) out[b*NCd + k] = pr + bf[k];
    }
}

// ---------------------------- launcher -------------------------------------
extern "C" void kernel_launch(void* const* d_in, const int* in_sizes, int n_in,
                              void* d_out, int out_size)
{
    (void)in_sizes; (void)n_in; (void)out_size;
    const int*   tok  = (const int*)d_in[0];
    const void*  mask = d_in[1];
    const float* emb  = (const float*)d_in[2];
    const float* Wo   = (const float*)d_in[3];
    const float* bo   = (const float*)d_in[4];
    const float* Wf   = (const float*)d_in[5];
    const float* bf   = (const float*)d_in[6];
    float*       out  = (float*)d_out;

    const int smem_attn = (TI*SJ + TJ*SJ + TI*SE + TJ + TI + TI) * 4;   // 93184 B
    const int smem_proj = (128*SW + 64*SW + 64*16 + 64 + 128) * 4;      // 107008 B
    cudaFuncSetAttribute(k_attn, cudaFuncAttributeMaxDynamicSharedMemorySize, smem_attn);
    cudaFuncSetAttribute(k_proj, cudaFuncAttributeMaxDynamicSharedMemorySize, smem_proj);

    k_detect  <<<1, 1024>>>((const unsigned char*)mask);
    k_masknorm<<<(Bd*Nd + 255)/256, 256>>>(mask);
    k_embed<<<(Bd*Nd)/8, 256>>>(tok, emb);
    k_attn <<<dim3(Nd/64, Bd), 256, smem_attn>>>();
    k_proj <<<(Bd*Nd)/64, 256, smem_proj>>>(Wo, bo);
    k_pool <<<Bd, 32>>>(Wf, bf, out);
}

// round 6
// speedup vs baseline: 1.1369x; 1.1369x over previous
#include <cuda_runtime.h>
#include <cstdint>
#include <cstddef>

#define CC   0.1f
#define SCc  0.31622776601683794f   /* sqrt(0.1) */
#define EPSc 1e-7f

#define Bd  64
#define Nd  1024
#define Dd  128
#define DX  129
#define NCd 10

// ---------------- packed fp32x2 helpers (Blackwell FFMA2) ------------------
__device__ __forceinline__ unsigned long long pk2(float lo, float hi)
{
    unsigned long long r;
    asm("mov.b64 %0, {%1, %2};" : "=l"(r) : "f"(lo), "f"(hi));
    return r;
}
__device__ __forceinline__ void upk2(unsigned long long v, float& lo, float& hi)
{
    asm("mov.b64 {%0, %1}, %2;" : "=f"(lo), "=f"(hi) : "l"(v));
}
__device__ __forceinline__ void fma2(unsigned long long& d,
                                     unsigned long long a, unsigned long long b)
{
    asm("fma.rn.f32x2 %0, %1, %2, %0;" : "+l"(d) : "l"(a), "l"(b));
}

// ---------------- scratch (device globals; no runtime allocation) ----------
__device__ float g_x [(size_t)Bd*Nd*DX];   // Lorentz points (B,N,129)
__device__ float g_mu[(size_t)Bd*Nd*DX];   // normalized centroids (B,N,129)
__device__ float g_y [(size_t)Bd*Nd*Dd];   // Poincare tokens (B,N,128)
__device__ float g_y2[(size_t)Bd*Nd];      // |y|^2 per token
__device__ unsigned char g_mask[(size_t)Bd*Nd];
__device__ int g_is32;

// ---------------- kernel 0a: detect mask dtype (u8 bool vs int32) ----------
__global__ void k_detect(const unsigned char* __restrict__ m)
{
    __shared__ int found;
    if (threadIdx.x == 0) found = 0;
    __syncthreads();
    int acc = 0;
    for (int i = threadIdx.x; i < Bd*Nd; i += blockDim.x)
        if ((i & 3) && m[i]) acc = 1;
    if (acc) atomicOr(&found, 1);
    __syncthreads();
    if (threadIdx.x == 0) g_is32 = found ? 0 : 1;
}

// ---------------- kernel 0b: normalize mask to uint8 -----------------------
__global__ void k_masknorm(const void* __restrict__ m)
{
    int i = blockIdx.x * blockDim.x + threadIdx.x;
    if (i >= Bd*Nd) return;
    unsigned char v;
    if (g_is32) v = (((const int*)m)[i] != 0);
    else        v = (((const unsigned char*)m)[i] != 0);
    g_mask[i] = v;
}

// ---------------- kernel 1: embedding + Lorentz expmap0 --------------------
__global__ void k_embed(const int* __restrict__ tok, const float* __restrict__ emb)
{
    int gw   = (blockIdx.x * blockDim.x + threadIdx.x) >> 5;
    int lane = threadIdx.x & 31;
    if (gw >= Bd*Nd) return;
    int t = tok[gw];
    float4 v = *(const float4*)(emb + (size_t)t*Dd + lane*4);
    float ss = v.x*v.x + v.y*v.y + v.z*v.z + v.w*v.w;
    #pragma unroll
    for (int o = 16; o; o >>= 1) ss += __shfl_xor_sync(0xffffffffu, ss, o);
    float nv   = fmaxf(sqrtf(ss), EPSc);
    float tt   = SCc * nv;
    float coef = sinhf(tt) / (SCc * nv);
    float* xr  = g_x + (size_t)gw * DX;
    if (lane == 0) xr[0] = coshf(tt) / SCc;
    xr[1 + lane*4 + 0] = coef * v.x;
    xr[1 + lane*4 + 1] = coef * v.y;
    xr[1 + lane*4 + 2] = coef * v.z;
    xr[1 + lane*4 + 3] = coef * v.w;
}

// ---------------- kernel 2: attention + Lorentz centroid -------------------
// grid (16, 64), 256 threads. Tile 64 queries x 64 keys. Exact fp32 (f32x2).
// Smem layout per row (stride SJ): slots [0..127] = spatial x1..x128,
// slot [128] = x0, slots [129..147] = 0.  Xi sign-folded (spatial negated).
#define SJ 148
#define SE 68    // E row stride: float4-aligned, group step 17 -> conflict-free
#define TI 64
#define TJ 64

__global__ __launch_bounds__(256, 2)
void k_attn()
{
    extern __shared__ float sm[];
    float* Xi  = sm;                 // 64*148
    float* Xj  = Xi + TI*SJ;         // 64*148
    float* E   = Xj + TJ*SJ;         // 64*68
    float* MS  = E  + TI*SE;         // 64 (mask; reused for mu0' at end)
    float* DEN = MS + TJ;            // 64
    float* INN = DEN + TI;           // 64
    float* MU0 = INN + TI;           // 64

    const int tid = threadIdx.x;
    const int b   = blockIdx.y;
    const int i0  = blockIdx.x * TI;
    const float invsq = 1.0f / sqrtf(129.0f);

    if (tid < TI) { DEN[tid] = 0.f; INN[tid] = 0.f; MU0[tid] = 0.f; }

    // fill Xi (permuted, sign-folded)
    const float* xb = g_x + ((size_t)b*Nd + i0) * DX;
    for (int idx = tid; idx < TI*DX; idx += 256) {
        int i = idx / DX, k = idx - i*DX;
        float v = xb[idx];
        if (k == 0) Xi[i*SJ + 128] = v;
        else        Xi[i*SJ + k-1] = -v;
    }
    for (int idx = tid; idx < TI*19; idx += 256) {
        int i = idx / 19, kk = 129 + (idx - i*19);
        Xi[i*SJ + kk] = 0.f;
        Xj[i*SJ + kk] = 0.f;
    }

    const int tx = tid & 15, ty = tid >> 4;   // score mapping: i=ty*4+r, j=tx+16q
    const int ia = tid & 63, dgrp = tid >> 6; // agg mapping: one i, 32 d's
    const int doff = dgrp * 32;

    unsigned long long mur2[16];              // 32 d accumulators as f32x2
    #pragma unroll
    for (int m = 0; m < 16; m++) mur2[m] = 0ull;
    float denp[4] = {0.f, 0.f, 0.f, 0.f};
    float acc0[4] = {0.f, 0.f, 0.f, 0.f};     // x0 (d=0) aggregation

    __syncthreads();

    for (int jt = 0; jt < Nd/TJ; jt++) {
        // ---- fill Xj (permuted, raw) + mask ----
        const float* xjb = g_x + ((size_t)b*Nd + jt*TJ) * DX;
        for (int idx = tid; idx < TJ*DX; idx += 256) {
            int j = idx / DX, k = idx - j*DX;
            float v = xjb[idx];
            if (k == 0) Xj[j*SJ + 128] = v;
            else        Xj[j*SJ + k-1] = v;
        }
        if (tid < TJ) MS[tid] = g_mask[b*Nd + jt*TJ + tid] ? 1.f : 0.f;
        __syncthreads();

        // ---- scores (f32x2 packed FMA) ----
        unsigned long long acc2[4][4];
        #pragma unroll
        for (int r = 0; r < 4; r++)
            #pragma unroll
            for (int q = 0; q < 4; q++) acc2[r][q] = 0ull;

        for (int k = 0; k < 132; k += 4) {
            ulonglong2 a2[4], b2[4];
            #pragma unroll
            for (int r = 0; r < 4; r++)
                a2[r] = *(const ulonglong2*)&Xi[(ty*4+r)*SJ + k];
            #pragma unroll
            for (int q = 0; q < 4; q++)
                b2[q] = *(const ulonglong2*)&Xj[(tx+16*q)*SJ + k];
            #pragma unroll
            for (int r = 0; r < 4; r++)
                #pragma unroll
                for (int q = 0; q < 4; q++) {
                    fma2(acc2[r][q], a2[r].x, b2[q].x);
                    fma2(acc2[r][q], a2[r].y, b2[q].y);
                }
        }

        float x0j[4];
        #pragma unroll
        for (int q = 0; q < 4; q++) x0j[q] = Xj[(tx+16*q)*SJ + 128];

        #pragma unroll
        for (int r = 0; r < 4; r++)
            #pragma unroll
            for (int q = 0; q < 4; q++) {
                float lo, hi;
                upk2(acc2[r][q], lo, hi);
                float s = lo + hi;
                int j = tx + 16*q;
                float e = MS[j] * __expf(s * invsq);
                E[(ty*4+r)*SE + j] = e;
                denp[r] += e;
                acc0[r] += e * x0j[q];
            }
        __syncthreads();

        // ---- aggregation: mur[ia][doff..doff+31] += sum_j E[ia][j]*Xj[j][d]
        // E: conflict-free float4; Xj: warp-uniform broadcast loads.
        for (int j4 = 0; j4 < TJ; j4 += 4) {
            float4 ev = *(const float4*)&E[ia*SE + j4];
            #pragma unroll
            for (int jj = 0; jj < 4; jj++) {
                float e = (jj == 0) ? ev.x : (jj == 1) ? ev.y : (jj == 2) ? ev.z : ev.w;
                unsigned long long ee = pk2(e, e);
                const ulonglong2* xp = (const ulonglong2*)&Xj[(j4+jj)*SJ + doff];
                #pragma unroll
                for (int g = 0; g < 8; g++) {
                    ulonglong2 xv = xp[g];
                    fma2(mur2[2*g+0], ee, xv.x);
                    fma2(mur2[2*g+1], ee, xv.y);
                }
            }
        }
        __syncthreads();
    }

    // ---- softmax denominator, x0 numerator ----
    #pragma unroll
    for (int r = 0; r < 4; r++) {
        atomicAdd(&DEN[ty*4 + r], denp[r]);
        atomicAdd(&MU0[ty*4 + r], acc0[r]);
    }
    __syncthreads();

    // ---- normalize + Lorentz inner ----
    float id = 1.0f / DEN[ia];
    float murf[32];
    float part = 0.f;
    #pragma unroll
    for (int g = 0; g < 16; g++) {
        float lo, hi;
        upk2(mur2[g], lo, hi);
        lo *= id; hi *= id;
        murf[2*g] = lo; murf[2*g+1] = hi;
        part += lo*lo + hi*hi;
    }
    atomicAdd(&INN[ia], part);
    if (dgrp == 0) {
        float mu0p = MU0[ia] * id;
        atomicAdd(&INN[ia], -mu0p*mu0p);
        MS[ia] = mu0p;                 // stash (mask no longer needed)
    }
    __syncthreads();

    // INN = <mu,mu>_L ; reference divides by sc*sqrt(max(-inner,eps))
    float s2 = 1.0f / (SCc * sqrtf(fmaxf(-INN[ia], EPSc)));
    float* mo = g_mu + ((size_t)b*Nd + i0 + ia) * DX;
    #pragma unroll
    for (int m = 0; m < 32; m++) mo[1 + doff + m] = murf[m] * s2;
    if (dgrp == 0) mo[0] = MS[ia] * s2;
}

// ---------------- kernel 3: output projection + Poincare expmap0 -----------
#define SW 132   // row stride: float4-aligned, zero-padded k=129..131
__global__ __launch_bounds__(256, 2)
void k_proj(const float* __restrict__ Wo, const float* __restrict__ bo)
{
    extern __shared__ float sm[];
    float* wo  = sm;               // 128*132
    float* mus = wo  + 128*SW;     // 64*132
    float* np  = mus + 64*SW;      // 64*16
    float* fv  = np  + 64*16;      // 64
    float* bos = fv  + 64;         // 128

    const int tid = threadIdx.x;
    const size_t row0 = (size_t)blockIdx.x * 64;

    for (int idx = tid; idx < 128*SW; idx += 256) {
        int o = idx / SW, k = idx - o*SW;
        wo[idx] = (k < DX) ? Wo[o*DX + k] : 0.f;
    }
    const float* mb = g_mu + row0 * DX;
    for (int idx = tid; idx < 64*SW; idx += 256) {
        int i = idx / SW, k = idx - i*SW;
        mus[idx] = (k < DX) ? mb[(size_t)i*DX + k] : 0.f;
    }
    if (tid < 128) bos[tid] = bo[tid];
    __syncthreads();

    const int tx = tid & 15, ty = tid >> 4;  // i=ty*4+r, o=tx+16q
    unsigned long long acc2[4][8];
    #pragma unroll
    for (int r = 0; r < 4; r++)
        #pragma unroll
        for (int q = 0; q < 8; q++) acc2[r][q] = 0ull;

    for (int k = 0; k < 132; k += 4) {
        ulonglong2 m2[4];
        #pragma unroll
        for (int r = 0; r < 4; r++)
            m2[r] = *(const ulonglong2*)&mus[(ty*4+r)*SW + k];
        #pragma unroll
        for (int q = 0; q < 8; q++) {
            ulonglong2 w2 = *(const ulonglong2*)&wo[(tx+16*q)*SW + k];
            #pragma unroll
            for (int r = 0; r < 4; r++) {
                fma2(acc2[r][q], m2[r].x, w2.x);
                fma2(acc2[r][q], m2[r].y, w2.y);
            }
        }
    }

    float acc[4][8];
    #pragma unroll
    for (int r = 0; r < 4; r++) {
        float pp = 0.f;
        #pragma unroll
        for (int q = 0; q < 8; q++) {
            float lo, hi;
            upk2(acc2[r][q], lo, hi);
            float a = lo + hi + bos[tx + 16*q];
            acc[r][q] = a;
            pp += a * a;
        }
        np[(ty*4+r)*16 + tx] = pp;
    }
    __syncthreads();

    if (tid < 64) {
        float s = 0.f;
        #pragma unroll
        for (int t = 0; t < 16; t++) s += np[tid*16 + t];
        float nu = fmaxf(sqrtf(s), EPSc);
        fv[tid] = tanhf(SCc*nu) / (SCc*nu);
    }
    __syncthreads();

    // write y = f*u, and |y|^2 recomputed from stored y values
    float* yb = g_y + row0 * Dd;
    #pragma unroll
    for (int r = 0; r < 4; r++) {
        float f = fv[ty*4 + r];
        float pp = 0.f;
        #pragma unroll
        for (int q = 0; q < 8; q++) {
            float yv = acc[r][q] * f;
            yb[(size_t)(ty*4+r)*Dd + tx + 16*q] = yv;
            pp += yv * yv;
        }
        np[(ty*4+r)*16 + tx] = pp;
    }
    __syncthreads();
    if (tid < 64) {
        float s = 0.f;
        #pragma unroll
        for (int t = 0; t < 16; t++) s += np[tid*16 + t];
        g_y2[row0 + tid] = s;
    }
}

// ---------------- kernel 4: sequential Mobius pooling + MLR head -----------
__global__ void k_pool(const float* __restrict__ Wf,
                       const float* __restrict__ bf,
                       float* __restrict__ out)
{
    const int b    = blockIdx.x;
    const int lane = threadIdx.x;
    const float* yb  = g_y  + (size_t)b*Nd*Dd;
    const float* y2b = g_y2 + (size_t)b*Nd;
    const unsigned char* mb = g_mask + (size_t)b*Nd;

    float a0=0.f, a1=0.f, a2=0.f, a3=0.f;
    int cnt = 0;

    float4 nyv = *(const float4*)(yb + lane*4);
    float  ny2 = y2b[0];

    for (int i = 0; i < Nd; i++) {
        float4 yv = nyv; float yy2 = ny2;
        int m = mb[i];
        if (i + 1 < Nd) {
            nyv = *(const float4*)(yb + (size_t)(i+1)*Dd + lane*4);
            ny2 = y2b[i+1];
        }
        if (!m) continue;
        float xy = a0*yv.x + a1*yv.y + a2*yv.z + a3*yv.w;
        float x2 = a0*a0 + a1*a1 + a2*a2 + a3*a3;
        #pragma unroll
        for (int o = 16; o; o >>= 1) {
            xy += __shfl_xor_sync(0xffffffffu, xy, o);
            x2 += __shfl_xor_sync(0xffffffffu, x2, o);
        }
        float aa  = 1.f + 2.f*CC*xy + CC*yy2;
        float bb  = 1.f - CC*x2;
        float den = fmaxf(1.f + 2.f*CC*xy + CC*CC*x2*yy2, 1e-12f);
        a0 = (aa*a0 + bb*yv.x) / den;
        a1 = (aa*a1 + bb*yv.y) / den;
        a2 = (aa*a2 + bb*yv.z) / den;
        a3 = (aa*a3 + bb*yv.w) / den;
        cnt++;
    }

    // mobius scalar-mul by 1/cnt
    float n2 = a0*a0 + a1*a1 + a2*a2 + a3*a3;
    #pragma unroll
    for (int o = 16; o; o >>= 1) n2 += __shfl_xor_sync(0xffffffffu, n2, o);
    float nrm = sqrtf(n2);
    float t   = fminf(fmaxf(SCc*nrm, EPSc), 1.f - 1e-6f);
    float r   = 1.f / fmaxf((float)cnt, 1.f);
    float fac = tanhf(r * atanhf(t)) / fmaxf(SCc*nrm, EPSc);
    float p0 = fac*a0, p1 = fac*a1, p2 = fac*a2, p3 = fac*a3;
    if (cnt == 0) {
        float4 y0 = *(const float4*)(yb + lane*4);
        p0 = y0.x; p1 = y0.y; p2 = y0.z; p3 = y0.w;
    }

    // logmap0
    float pn2 = p0*p0 + p1*p1 + p2*p2 + p3*p3;
    #pragma unroll
    for (int o = 16; o; o >>= 1) pn2 += __shfl_xor_sync(0xffffffffu, pn2, o);
    float npn = fmaxf(sqrtf(pn2), EPSc);
    float t2  = fminf(fmaxf(SCc*npn, EPSc), 1.f - 1e-6f);
    float cf  = atanhf(t2) / (SCc*npn);
    float v0 = cf*p0, v1 = cf*p1, v2 = cf*p2, v3 = cf*p3;

    // logits
    for (int k = 0; k < NCd; k++) {
        float4 w = *(const float4*)(Wf + (size_t)k*Dd + lane*4);
        float pr = v0*w.x + v1*w.y + v2*w.z + v3*w.w;
        #pragma unroll
        for (int o = 16; o; o >>= 1) pr += __shfl_xor_sync(0xffffffffu, pr, o);
        if (lane == 0) out[b*NCd + k] = pr + bf[k];
    }
}

// ---------------------------- launcher -------------------------------------
extern "C" void kernel_launch(void* const* d_in, const int* in_sizes, int n_in,
                              void* d_out, int out_size)
{
    (void)in_sizes; (void)n_in; (void)out_size;
    const int*   tok  = (const int*)d_in[0];
    const void*  mask = d_in[1];
    const float* emb  = (const float*)d_in[2];
    const float* Wo   = (const float*)d_in[3];
    const float* bo   = (const float*)d_in[4];
    const float* Wf   = (const float*)d_in[5];
    const float* bf   = (const float*)d_in[6];
    float*       out  = (float*)d_out;

    const int smem_attn = (TI*SJ + TJ*SJ + TI*SE + 4*64) * 4;        // 94208 B
    const int smem_proj = (128*SW + 64*SW + 64*16 + 64 + 128) * 4;   // 106240 B
    cudaFuncSetAttribute(k_attn, cudaFuncAttributeMaxDynamicSharedMemorySize, smem_attn);
    cudaFuncSetAttribute(k_proj, cudaFuncAttributeMaxDynamicSharedMemorySize, smem_proj);

    k_detect  <<<1, 1024>>>((const unsigned char*)mask);
    k_masknorm<<<(Bd*Nd + 255)/256, 256>>>(mask);
    k_embed<<<(Bd*Nd)/8, 256>>>(tok, emb);
    k_attn <<<dim3(Nd/64, Bd), 256, smem_attn>>>();
    k_proj <<<(Bd*Nd)/64, 256, smem_proj>>>(Wo, bo);
    k_pool <<<Bd, 32>>>(Wf, bf, out);
}

// round 8
// speedup vs baseline: 1.6831x; 1.4803x over previous
#include <cuda_runtime.h>
#include <cuda_fp16.h>
#include <cstdint>
#include <cstddef>

#define CC   0.1f
#define SCc  0.31622776601683794f   /* sqrt(0.1) */
#define EPSc 1e-7f

#define Bd  64
#define Nd  1024
#define Dd  128
#define DX  129
#define NCd 10

// ---------------- packed fp32x2 helpers (FFMA2, used in k_proj) ------------
__device__ __forceinline__ void upk2(unsigned long long v, float& lo, float& hi)
{
    asm("mov.b64 {%0, %1}, %2;" : "=f"(lo), "=f"(hi) : "l"(v));
}
__device__ __forceinline__ void fma2(unsigned long long& d,
                                     unsigned long long a, unsigned long long b)
{
    asm("fma.rn.f32x2 %0, %1, %2, %0;" : "+l"(d) : "l"(a), "l"(b));
}

// ---------------- warp-MMA helpers (baseline PTX, no 'a' target needed) ----
__device__ __forceinline__ uint32_t smem_u32(const void* p)
{
    uint32_t a;
    asm("{ .reg .u64 t; cvta.to.shared.u64 t, %1; cvt.u32.u64 %0, t; }"
        : "=r"(a) : "l"(p));
    return a;
}
__device__ __forceinline__ void ldsm4(uint32_t& r0, uint32_t& r1,
                                      uint32_t& r2, uint32_t& r3, uint32_t addr)
{
    asm volatile("ldmatrix.sync.aligned.m8n8.x4.shared.b16 {%0,%1,%2,%3}, [%4];"
                 : "=r"(r0), "=r"(r1), "=r"(r2), "=r"(r3) : "r"(addr));
}
__device__ __forceinline__ void mma16816(float* c, uint32_t a0, uint32_t a1,
                                         uint32_t a2, uint32_t a3,
                                         uint32_t b0, uint32_t b1)
{
    asm volatile("mma.sync.aligned.m16n8k16.row.col.f32.f16.f16.f32 "
                 "{%0,%1,%2,%3}, {%4,%5,%6,%7}, {%8,%9}, {%0,%1,%2,%3};"
                 : "+f"(c[0]), "+f"(c[1]), "+f"(c[2]), "+f"(c[3])
                 : "r"(a0), "r"(a1), "r"(a2), "r"(a3), "r"(b0), "r"(b1));
}

// ---------------- scratch (device globals; no runtime allocation) ----------
__device__ float g_x [(size_t)Bd*Nd*DX];   // Lorentz points (B,N,129)
__device__ float g_mu[(size_t)Bd*Nd*DX];   // normalized centroids (B,N,129)
__device__ float g_y [(size_t)Bd*Nd*Dd];   // Poincare tokens (B,N,128)
__device__ float g_y2[(size_t)Bd*Nd];      // |y|^2 per token
__device__ unsigned char g_mask[(size_t)Bd*Nd];
__device__ int g_is32;

// ---------------- kernel 0a/0b: mask dtype detect + normalize --------------
__global__ void k_detect(const unsigned char* __restrict__ m)
{
    __shared__ int found;
    if (threadIdx.x == 0) found = 0;
    __syncthreads();
    int acc = 0;
    for (int i = threadIdx.x; i < Bd*Nd; i += blockDim.x)
        if ((i & 3) && m[i]) acc = 1;
    if (acc) atomicOr(&found, 1);
    __syncthreads();
    if (threadIdx.x == 0) g_is32 = found ? 0 : 1;
}
__global__ void k_masknorm(const void* __restrict__ m)
{
    int i = blockIdx.x * blockDim.x + threadIdx.x;
    if (i >= Bd*Nd) return;
    unsigned char v;
    if (g_is32) v = (((const int*)m)[i] != 0);
    else        v = (((const unsigned char*)m)[i] != 0);
    g_mask[i] = v;
}

// ---------------- kernel 1: embedding + Lorentz expmap0 --------------------
__global__ void k_embed(const int* __restrict__ tok, const float* __restrict__ emb)
{
    int gw   = (blockIdx.x * blockDim.x + threadIdx.x) >> 5;
    int lane = threadIdx.x & 31;
    if (gw >= Bd*Nd) return;
    int t = tok[gw];
    float4 v = *(const float4*)(emb + (size_t)t*Dd + lane*4);
    float ss = v.x*v.x + v.y*v.y + v.z*v.z + v.w*v.w;
    #pragma unroll
    for (int o = 16; o; o >>= 1) ss += __shfl_xor_sync(0xffffffffu, ss, o);
    float nv   = fmaxf(sqrtf(ss), EPSc);
    float tt   = SCc * nv;
    float coef = sinhf(tt) / (SCc * nv);
    float* xr  = g_x + (size_t)gw * DX;
    if (lane == 0) xr[0] = coshf(tt) / SCc;
    xr[1 + lane*4 + 0] = coef * v.x;
    xr[1 + lane*4 + 1] = coef * v.y;
    xr[1 + lane*4 + 2] = coef * v.z;
    xr[1 + lane*4 + 3] = coef * v.w;
}

// ---------------- kernel 2: attention via mma.sync (fp16 2-term split) -----
// grid (8, 64): 128-query tile x batch; 8 warps, each owns 16 query rows.
// s_ij = (x0_i*x0_j - spatial)/sqrt(129); spatial & mu via fp16 hi/lo HMMA,
// x0 rank-1 term exact fp32. mu accumulated in register fragments.
#define STX 136   // f16 stride of Xi / Xj natural tiles (row = spatial d)
#define STE 72    // f16 stride of E / XjT tiles
#define OXIH 0
#define OXIL 34816
#define OXJH 69632
#define OXJL 87040
#define OTH  104448
#define OTL  122880
#define OEH  141312
#define OEL  159744
#define OX0I 178176
#define OX0J 178688
#define OMS  178944
#define ATT_SMEM 179200

__global__ void __launch_bounds__(256, 1) k_attn_mma()
{
    extern __shared__ float4 smem_f4[];
    char* smb = (char*)smem_f4;
    const uint32_t sb = smem_u32(smb);

    const int tid  = threadIdx.x;
    const int wid  = tid >> 5;
    const int lane = tid & 31;
    const int b    = blockIdx.y;
    const int i0   = blockIdx.x * 128;
    const float invsq = 1.0f / sqrtf(129.0f);

    float* x0i = (float*)(smb + OX0I);
    float* msj = (float*)(smb + OMS);

    // ---- load Xi tile (128 x 129): x0 + fp16 hi/lo spatial ----
    for (int idx = tid; idx < 128*DX; idx += 256) {
        int i = idx / DX, d = idx - i*DX;
        float v = g_x[((size_t)b*Nd + i0 + i)*DX + d];
        if (d == 0) x0i[i] = v;
        else {
            int k = d - 1;
            __half h = __float2half_rn(v);
            __half l = __float2half_rn(v - __half2float(h));
            *(__half*)(smb + OXIH + (i*STX + k)*2) = h;
            *(__half*)(smb + OXIL + (i*STX + k)*2) = l;
        }
    }
    __syncthreads();

    const int r0  = wid*16 + (lane >> 2);      // first owned row
    const int cq  = (lane & 3) * 2;            // col pair within n-frag
    const float xi0 = x0i[r0];
    const float xi1 = x0i[r0 + 8];

    // ldmatrix lane address components
    const int la_row = lane & 15;                       // A pattern
    const int la_kof = (lane >> 4) << 3;
    const int lb_n   = (lane & 7) + ((lane >> 4) << 3); // B pattern
    const int lb_kof = ((lane >> 3) & 1) << 3;

    const uint32_t aXiH = sb + OXIH + ((wid*16 + la_row)*STX + la_kof)*2;
    const uint32_t aXiL = sb + OXIL + ((wid*16 + la_row)*STX + la_kof)*2;
    const uint32_t bXjH = sb + OXJH + (lb_n*STX + lb_kof)*2;
    const uint32_t bXjL = sb + OXJL + (lb_n*STX + lb_kof)*2;
    const uint32_t aEH  = sb + OEH  + ((wid*16 + la_row)*STE + la_kof)*2;
    const uint32_t aEL  = sb + OEL  + ((wid*16 + la_row)*STE + la_kof)*2;
    const uint32_t bTH  = sb + OTH  + (lb_n*STE + lb_kof)*2;
    const uint32_t bTL  = sb + OTL  + (lb_n*STE + lb_kof)*2;

    float muc[16][4];
    #pragma unroll
    for (int f = 0; f < 16; f++)
        muc[f][0] = muc[f][1] = muc[f][2] = muc[f][3] = 0.f;
    float den0 = 0.f, den1 = 0.f, ac00 = 0.f, ac01 = 0.f;

    for (int jt = 0; jt < 16; jt++) {
        __syncthreads();   // prior mu MMAs done reading Xj tiles
        // ---- load Xj tile (64 x 129): x0j, mask, nat + transposed hi/lo ----
        for (int idx = tid; idx < 64*DX; idx += 256) {
            int j = idx / DX, d = idx - j*DX;
            float v = g_x[((size_t)b*Nd + jt*64 + j)*DX + d];
            if (d == 0) ((float*)(smb + OX0J))[j] = v;
            else {
                int k = d - 1;
                __half h = __float2half_rn(v);
                __half l = __float2half_rn(v - __half2float(h));
                *(__half*)(smb + OXJH + (j*STX + k)*2) = h;
                *(__half*)(smb + OXJL + (j*STX + k)*2) = l;
                *(__half*)(smb + OTH  + (k*STE + j)*2) = h;
                *(__half*)(smb + OTL  + (k*STE + j)*2) = l;
            }
        }
        if (tid < 64) msj[tid] = g_mask[b*Nd + jt*64 + tid] ? 1.f : 0.f;
        __syncthreads();

        // ---- score MMAs: S[16 rows x 64 j] per warp, 3 split products ----
        float c[8][4];
        #pragma unroll
        for (int q = 0; q < 8; q++)
            c[q][0] = c[q][1] = c[q][2] = c[q][3] = 0.f;

        #pragma unroll 1
        for (int s = 0; s < 3; s++) {
            uint32_t abase = (s == 2) ? aXiL : aXiH;
            uint32_t bbase = (s == 1) ? bXjL : bXjH;
            #pragma unroll
            for (int kk = 0; kk < 8; kk++) {
                uint32_t a0, a1, a2, a3;
                ldsm4(a0, a1, a2, a3, abase + kk*32);
                #pragma unroll
                for (int nb = 0; nb < 4; nb++) {
                    uint32_t b0, b1, b2, b3;
                    ldsm4(b0, b1, b2, b3, bbase + nb*(16*STX*2) + kk*32);
                    mma16816(c[nb*2],     a0, a1, a2, a3, b0, b1);
                    mma16816(c[nb*2 + 1], a0, a1, a2, a3, b2, b3);
                }
            }
        }

        // ---- epilogue: e = mask*exp((x0i*x0j - s)/sqrt129); E -> fp16 split
        #pragma unroll
        for (int q = 0; q < 8; q++) {
            float2 xj = *(float2*)(smb + OX0J + (q*8 + cq)*4);
            float2 mv = *(float2*)(smb + OMS  + (q*8 + cq)*4);
            float e00 = mv.x * __expf((xi0*xj.x - c[q][0]) * invsq);
            float e01 = mv.y * __expf((xi0*xj.y - c[q][1]) * invsq);
            float e10 = mv.x * __expf((xi1*xj.x - c[q][2]) * invsq);
            float e11 = mv.y * __expf((xi1*xj.y - c[q][3]) * invsq);
            den0 += e00 + e01;  den1 += e10 + e11;
            ac00 += e00*xj.x + e01*xj.y;
            ac01 += e10*xj.x + e11*xj.y;
            __half h00 = __float2half_rn(e00), h01 = __float2half_rn(e01);
            __half h10 = __float2half_rn(e10), h11 = __float2half_rn(e11);
            __half l00 = __float2half_rn(e00 - __half2float(h00));
            __half l01 = __float2half_rn(e01 - __half2float(h01));
            __half l10 = __float2half_rn(e10 - __half2float(h10));
            __half l11 = __float2half_rn(e11 - __half2float(h11));
            uint32_t hp0 = (uint32_t)__half_as_ushort(h00) | ((uint32_t)__half_as_ushort(h01) << 16);
            uint32_t hp1 = (uint32_t)__half_as_ushort(h10) | ((uint32_t)__half_as_ushort(h11) << 16);
            uint32_t lp0 = (uint32_t)__half_as_ushort(l00) | ((uint32_t)__half_as_ushort(l01) << 16);
            uint32_t lp1 = (uint32_t)__half_as_ushort(l10) | ((uint32_t)__half_as_ushort(l11) << 16);
            int w0 = (r0*STE + q*8 + cq) * 2;
            int w1 = ((r0 + 8)*STE + q*8 + cq) * 2;
            *(uint32_t*)(smb + OEH + w0) = hp0;
            *(uint32_t*)(smb + OEH + w1) = hp1;
            *(uint32_t*)(smb + OEL + w0) = lp0;
            *(uint32_t*)(smb + OEL + w1) = lp1;
        }
        __syncwarp();

        // ---- mu MMAs: mu[16 rows x 128 d] += E[16x64] . XjT[128x64]^T ----
        #pragma unroll 1
        for (int s = 0; s < 3; s++) {
            uint32_t abase = (s == 2) ? aEL : aEH;
            uint32_t bbase = (s == 1) ? bTL : bTH;
            #pragma unroll
            for (int kk = 0; kk < 4; kk++) {
                uint32_t a0, a1, a2, a3;
                ldsm4(a0, a1, a2, a3, abase + kk*32);
                #pragma unroll
                for (int nb = 0; nb < 8; nb++) {
                    uint32_t b0, b1, b2, b3;
                    ldsm4(b0, b1, b2, b3, bbase + nb*(16*STE*2) + kk*32);
                    mma16816(muc[nb*2],     a0, a1, a2, a3, b0, b1);
                    mma16816(muc[nb*2 + 1], a0, a1, a2, a3, b2, b3);
                }
            }
        }
    }

    // ---- finalize: quad-reduce den/acc0, Lorentz renorm, store g_mu ----
    #pragma unroll
    for (int o = 1; o < 4; o <<= 1) {
        den0 += __shfl_xor_sync(0xffffffffu, den0, o);
        den1 += __shfl_xor_sync(0xffffffffu, den1, o);
        ac00 += __shfl_xor_sync(0xffffffffu, ac00, o);
        ac01 += __shfl_xor_sync(0xffffffffu, ac01, o);
    }
    float id0 = 1.f / den0, id1 = 1.f / den1;
    float mu00 = ac00 * id0, mu01 = ac01 * id1;

    float in0 = 0.f, in1 = 0.f;
    #pragma unroll
    for (int f = 0; f < 16; f++) {
        muc[f][0] *= id0; muc[f][1] *= id0;
        muc[f][2] *= id1; muc[f][3] *= id1;
        in0 += muc[f][0]*muc[f][0] + muc[f][1]*muc[f][1];
        in1 += muc[f][2]*muc[f][2] + muc[f][3]*muc[f][3];
    }
    #pragma unroll
    for (int o = 1; o < 4; o <<= 1) {
        in0 += __shfl_xor_sync(0xffffffffu, in0, o);
        in1 += __shfl_xor_sync(0xffffffffu, in1, o);
    }
    float s20 = 1.f / (SCc * sqrtf(fmaxf(mu00*mu00 - in0, EPSc)));
    float s21 = 1.f / (SCc * sqrtf(fmaxf(mu01*mu01 - in1, EPSc)));

    float* mo0 = g_mu + ((size_t)b*Nd + i0 + r0) * DX;
    float* mo1 = mo0 + (size_t)8 * DX;
    if ((lane & 3) == 0) { mo0[0] = mu00 * s20; mo1[0] = mu01 * s21; }
    #pragma unroll
    for (int f = 0; f < 16; f++) {
        int d = f*8 + cq;
        mo0[1 + d]     = muc[f][0] * s20;
        mo0[1 + d + 1] = muc[f][1] * s20;
        mo1[1 + d]     = muc[f][2] * s21;
        mo1[1 + d + 1] = muc[f][3] * s21;
    }
}

// ---------------- kernel 3: output projection + Poincare expmap0 -----------
#define SW 132
__global__ __launch_bounds__(256, 2)
void k_proj(const float* __restrict__ Wo, const float* __restrict__ bo)
{
    extern __shared__ float sm[];
    float* wo  = sm;               // 128*132
    float* mus = wo  + 128*SW;     // 64*132
    float* np  = mus + 64*SW;      // 64*16
    float* fv  = np  + 64*16;      // 64
    float* bos = fv  + 64;         // 128

    const int tid = threadIdx.x;
    const size_t row0 = (size_t)blockIdx.x * 64;

    for (int idx = tid; idx < 128*SW; idx += 256) {
        int o = idx / SW, k = idx - o*SW;
        wo[idx] = (k < DX) ? Wo[o*DX + k] : 0.f;
    }
    const float* mb = g_mu + row0 * DX;
    for (int idx = tid; idx < 64*SW; idx += 256) {
        int i = idx / SW, k = idx - i*SW;
        mus[idx] = (k < DX) ? mb[(size_t)i*DX + k] : 0.f;
    }
    if (tid < 128) bos[tid] = bo[tid];
    __syncthreads();

    const int tx = tid & 15, ty = tid >> 4;
    unsigned long long acc2[4][8];
    #pragma unroll
    for (int r = 0; r < 4; r++)
        #pragma unroll
        for (int q = 0; q < 8; q++) acc2[r][q] = 0ull;

    for (int k = 0; k < 132; k += 4) {
        ulonglong2 m2[4];
        #pragma unroll
        for (int r = 0; r < 4; r++)
            m2[r] = *(const ulonglong2*)&mus[(ty*4+r)*SW + k];
        #pragma unroll
        for (int q = 0; q < 8; q++) {
            ulonglong2 w2 = *(const ulonglong2*)&wo[(tx+16*q)*SW + k];
            #pragma unroll
            for (int r = 0; r < 4; r++) {
                fma2(acc2[r][q], m2[r].x, w2.x);
                fma2(acc2[r][q], m2[r].y, w2.y);
            }
        }
    }

    float acc[4][8];
    #pragma unroll
    for (int r = 0; r < 4; r++) {
        float pp = 0.f;
        #pragma unroll
        for (int q = 0; q < 8; q++) {
            float lo, hi;
            upk2(acc2[r][q], lo, hi);
            float a = lo + hi + bos[tx + 16*q];
            acc[r][q] = a;
            pp += a * a;
        }
        np[(ty*4+r)*16 + tx] = pp;
    }
    __syncthreads();

    if (tid < 64) {
        float s = 0.f;
        #pragma unroll
        for (int t = 0; t < 16; t++) s += np[tid*16 + t];
        float nu = fmaxf(sqrtf(s), EPSc);
        fv[tid] = tanhf(SCc*nu) / (SCc*nu);
    }
    __syncthreads();

    float* yb = g_y + row0 * Dd;
    #pragma unroll
    for (int r = 0; r < 4; r++) {
        float f = fv[ty*4 + r];
        float pp = 0.f;
        #pragma unroll
        for (int q = 0; q < 8; q++) {
            float yv = acc[r][q] * f;
            yb[(size_t)(ty*4+r)*Dd + tx + 16*q] = yv;
            pp += yv * yv;
        }
        np[(ty*4+r)*16 + tx] = pp;
    }
    __syncthreads();
    if (tid < 64) {
        float s = 0.f;
        #pragma unroll
        for (int t = 0; t < 16; t++) s += np[tid*16 + t];
        g_y2[row0 + tid] = s;
    }
}

// ---------------- kernel 4: sequential Mobius pooling + MLR head -----------
__global__ void k_pool(const float* __restrict__ Wf,
                       const float* __restrict__ bf,
                       float* __restrict__ out)
{
    const int b    = blockIdx.x;
    const int lane = threadIdx.x;
    const float* yb  = g_y  + (size_t)b*Nd*Dd;
    const float* y2b = g_y2 + (size_t)b*Nd;
    const unsigned char* mb = g_mask + (size_t)b*Nd;

    float a0=0.f, a1=0.f, a2=0.f, a3=0.f;
    int cnt = 0;

    float4 nyv = *(const float4*)(yb + lane*4);
    float  ny2 = y2b[0];

    for (int i = 0; i < Nd; i++) {
        float4 yv = nyv; float yy2 = ny2;
        int m = mb[i];
        if (i + 1 < Nd) {
            nyv = *(const float4*)(yb + (size_t)(i+1)*Dd + lane*4);
            ny2 = y2b[i+1];
        }
        if (!m) continue;
        float xy = a0*yv.x + a1*yv.y + a2*yv.z + a3*yv.w;
        float x2 = a0*a0 + a1*a1 + a2*a2 + a3*a3;
        #pragma unroll
        for (int o = 16; o; o >>= 1) {
            xy += __shfl_xor_sync(0xffffffffu, xy, o);
            x2 += __shfl_xor_sync(0xffffffffu, x2, o);
        }
        float aa  = 1.f + 2.f*CC*xy + CC*yy2;
        float bb  = 1.f - CC*x2;
        float den = fmaxf(1.f + 2.f*CC*xy + CC*CC*x2*yy2, 1e-12f);
        a0 = (aa*a0 + bb*yv.x) / den;
        a1 = (aa*a1 + bb*yv.y) / den;
        a2 = (aa*a2 + bb*yv.z) / den;
        a3 = (aa*a3 + bb*yv.w) / den;
        cnt++;
    }

    float n2 = a0*a0 + a1*a1 + a2*a2 + a3*a3;
    #pragma unroll
    for (int o = 16; o; o >>= 1) n2 += __shfl_xor_sync(0xffffffffu, n2, o);
    float nrm = sqrtf(n2);
    float t   = fminf(fmaxf(SCc*nrm, EPSc), 1.f - 1e-6f);
    float r   = 1.f / fmaxf((float)cnt, 1.f);
    float fac = tanhf(r * atanhf(t)) / fmaxf(SCc*nrm, EPSc);
    float p0 = fac*a0, p1 = fac*a1, p2 = fac*a2, p3 = fac*a3;
    if (cnt == 0) {
        float4 y0 = *(const float4*)(yb + lane*4);
        p0 = y0.x; p1 = y0.y; p2 = y0.z; p3 = y0.w;
    }

    float pn2 = p0*p0 + p1*p1 + p2*p2 + p3*p3;
    #pragma unroll
    for (int o = 16; o; o >>= 1) pn2 += __shfl_xor_sync(0xffffffffu, pn2, o);
    float npn = fmaxf(sqrtf(pn2), EPSc);
    float t2  = fminf(fmaxf(SCc*npn, EPSc), 1.f - 1e-6f);
    float cf  = atanhf(t2) / (SCc*npn);
    float v0 = cf*p0, v1 = cf*p1, v2 = cf*p2, v3 = cf*p3;

    for (int k = 0; k < NCd; k++) {
        float4 w = *(const float4*)(Wf + (size_t)k*Dd + lane*4);
        float pr = v0*w.x + v1*w.y + v2*w.z + v3*w.w;
        #pragma unroll
        for (int o = 16; o; o >>= 1) pr += __shfl_xor_sync(0xffffffffu, pr, o);
        if (lane == 0) out[b*NCd + k] = pr + bf[k];
    }
}

// ---------------------------- launcher -------------------------------------
extern "C" void kernel_launch(void* const* d_in, const int* in_sizes, int n_in,
                              void* d_out, int out_size)
{
    (void)in_sizes; (void)n_in; (void)out_size;
    const int*   tok  = (const int*)d_in[0];
    const void*  mask = d_in[1];
    const float* emb  = (const float*)d_in[2];
    const float* Wo   = (const float*)d_in[3];
    const float* bo   = (const float*)d_in[4];
    const float* Wf   = (const float*)d_in[5];
    const float* bf   = (const float*)d_in[6];
    float*       out  = (float*)d_out;

    const int smem_proj = (128*SW + 64*SW + 64*16 + 64 + 128) * 4;
    cudaFuncSetAttribute(k_attn_mma, cudaFuncAttributeMaxDynamicSharedMemorySize, ATT_SMEM);
    cudaFuncSetAttribute(k_proj,     cudaFuncAttributeMaxDynamicSharedMemorySize, smem_proj);

    k_detect   <<<1, 1024>>>((const unsigned char*)mask);
    k_masknorm <<<(Bd*Nd + 255)/256, 256>>>(mask);
    k_embed    <<<(Bd*Nd)/8, 256>>>(tok, emb);
    k_attn_mma <<<dim3(8, Bd), 256, ATT_SMEM>>>();
    k_proj     <<<(Bd*Nd)/64, 256, smem_proj>>>(Wo, bo);
    k_pool     <<<Bd, 32>>>(Wf, bf, out);
}

// round 9
// speedup vs baseline: 2.3343x; 1.3869x over previous
#include <cuda_runtime.h>
#include <cuda_fp16.h>
#include <cstdint>
#include <cstddef>

#define CC   0.1f
#define SCc  0.31622776601683794f   /* sqrt(0.1) */
#define EPSc 1e-7f

#define Bd  64
#define Nd  1024
#define Dd  128
#define DX  129
#define NCd 10

// ---------------- packed fp32x2 helpers (FFMA2, used in k_proj) ------------
__device__ __forceinline__ void upk2(unsigned long long v, float& lo, float& hi)
{
    asm("mov.b64 {%0, %1}, %2;" : "=f"(lo), "=f"(hi) : "l"(v));
}
__device__ __forceinline__ void fma2(unsigned long long& d,
                                     unsigned long long a, unsigned long long b)
{
    asm("fma.rn.f32x2 %0, %1, %2, %0;" : "+l"(d) : "l"(a), "l"(b));
}

// ---------------- warp-MMA / cp.async helpers (baseline PTX) ---------------
__device__ __forceinline__ uint32_t smem_u32(const void* p)
{
    uint32_t a;
    asm("{ .reg .u64 t; cvta.to.shared.u64 t, %1; cvt.u32.u64 %0, t; }"
        : "=r"(a) : "l"(p));
    return a;
}
__device__ __forceinline__ void ldsm4(uint32_t& r0, uint32_t& r1,
                                      uint32_t& r2, uint32_t& r3, uint32_t addr)
{
    asm volatile("ldmatrix.sync.aligned.m8n8.x4.shared.b16 {%0,%1,%2,%3}, [%4];"
                 : "=r"(r0), "=r"(r1), "=r"(r2), "=r"(r3) : "r"(addr));
}
__device__ __forceinline__ void ldsm4t(uint32_t& r0, uint32_t& r1,
                                       uint32_t& r2, uint32_t& r3, uint32_t addr)
{
    asm volatile("ldmatrix.sync.aligned.m8n8.x4.trans.shared.b16 {%0,%1,%2,%3}, [%4];"
                 : "=r"(r0), "=r"(r1), "=r"(r2), "=r"(r3) : "r"(addr));
}
__device__ __forceinline__ void mma16816(float* c, uint32_t a0, uint32_t a1,
                                         uint32_t a2, uint32_t a3,
                                         uint32_t b0, uint32_t b1)
{
    asm volatile("mma.sync.aligned.m16n8k16.row.col.f32.f16.f16.f32 "
                 "{%0,%1,%2,%3}, {%4,%5,%6,%7}, {%8,%9}, {%0,%1,%2,%3};"
                 : "+f"(c[0]), "+f"(c[1]), "+f"(c[2]), "+f"(c[3])
                 : "r"(a0), "r"(a1), "r"(a2), "r"(a3), "r"(b0), "r"(b1));
}
__device__ __forceinline__ void cpasync16(uint32_t dst, const void* src)
{
    asm volatile("cp.async.cg.shared.global [%0], [%1], 16;"
                 :: "r"(dst), "l"(src) : "memory");
}
__device__ __forceinline__ void cp_commit()
{
    asm volatile("cp.async.commit_group;" ::: "memory");
}
__device__ __forceinline__ void cp_wait_all()
{
    asm volatile("cp.async.wait_group 0;" ::: "memory");
}
__device__ __forceinline__ uint32_t packh(float a, float b)
{
    __half ha = __float2half_rn(a), hb = __float2half_rn(b);
    return (uint32_t)__half_as_ushort(ha) | ((uint32_t)__half_as_ushort(hb) << 16);
}

// ---------------- scratch (device globals; no runtime allocation) ----------
__device__ __align__(16) __half g_xh[(size_t)Bd*Nd*Dd];  // spatial hi (fp16)
__device__ __align__(16) __half g_xl[(size_t)Bd*Nd*Dd];  // spatial lo (fp16)
__device__ __align__(16) float  g_x0[(size_t)Bd*Nd];     // time component
__device__ float g_mu[(size_t)Bd*Nd*DX];   // normalized centroids (B,N,129)
__device__ float g_y [(size_t)Bd*Nd*Dd];   // Poincare tokens (B,N,128)
__device__ float g_y2[(size_t)Bd*Nd];      // |y|^2 per token
__device__ __align__(16) unsigned char g_mask[(size_t)Bd*Nd];
__device__ int g_is32;

// ---------------- kernel 0a/0b: mask dtype detect + normalize --------------
__global__ void k_detect(const unsigned char* __restrict__ m)
{
    __shared__ int found;
    if (threadIdx.x == 0) found = 0;
    __syncthreads();
    int acc = 0;
    for (int i = threadIdx.x; i < Bd*Nd; i += blockDim.x)
        if ((i & 3) && m[i]) acc = 1;
    if (acc) atomicOr(&found, 1);
    __syncthreads();
    if (threadIdx.x == 0) g_is32 = found ? 0 : 1;
}
__global__ void k_masknorm(const void* __restrict__ m)
{
    int i = blockIdx.x * blockDim.x + threadIdx.x;
    if (i >= Bd*Nd) return;
    unsigned char v;
    if (g_is32) v = (((const int*)m)[i] != 0);
    else        v = (((const unsigned char*)m)[i] != 0);
    g_mask[i] = v;
}

// ---------------- kernel 1: embedding + Lorentz expmap0 (fp16 split out) ---
__global__ void k_embed(const int* __restrict__ tok, const float* __restrict__ emb)
{
    int gw   = (blockIdx.x * blockDim.x + threadIdx.x) >> 5;
    int lane = threadIdx.x & 31;
    if (gw >= Bd*Nd) return;
    int t = tok[gw];
    float4 v = *(const float4*)(emb + (size_t)t*Dd + lane*4);
    float ss = v.x*v.x + v.y*v.y + v.z*v.z + v.w*v.w;
    #pragma unroll
    for (int o = 16; o; o >>= 1) ss += __shfl_xor_sync(0xffffffffu, ss, o);
    float nv   = fmaxf(sqrtf(ss), EPSc);
    float tt   = SCc * nv;
    float coef = sinhf(tt) / (SCc * nv);
    if (lane == 0) g_x0[gw] = coshf(tt) / SCc;

    float vv[4] = {coef*v.x, coef*v.y, coef*v.z, coef*v.w};
    uint32_t h01, h23, l01, l23;
    {
        __half h0 = __float2half_rn(vv[0]), h1 = __float2half_rn(vv[1]);
        __half h2 = __float2half_rn(vv[2]), h3 = __float2half_rn(vv[3]);
        h01 = (uint32_t)__half_as_ushort(h0) | ((uint32_t)__half_as_ushort(h1) << 16);
        h23 = (uint32_t)__half_as_ushort(h2) | ((uint32_t)__half_as_ushort(h3) << 16);
        l01 = packh(vv[0] - __half2float(h0), vv[1] - __half2float(h1));
        l23 = packh(vv[2] - __half2float(h2), vv[3] - __half2float(h3));
    }
    uint2* ph = (uint2*)(g_xh + (size_t)gw*Dd + lane*4);
    uint2* pl = (uint2*)(g_xl + (size_t)gw*Dd + lane*4);
    *ph = make_uint2(h01, h23);
    *pl = make_uint2(l01, l23);
}

// ---------------- kernel 2: attention via mma.sync, cp.async, E-in-regs ----
// grid (8, 64); 8 warps x 16 query rows. Double-buffered Xj tiles.
#define STX 136   // half stride of Xi/Xj tiles
#define OXIH 0
#define OXIL 34816
#define OXJH0 69632
#define OXJL0 87040
#define OXJH1 104448
#define OXJL1 121856
#define OX0I 139264
#define OX0J0 139776
#define OX0J1 140032
#define OMS0 140288
#define OMS1 140352
#define ATT_SMEM 140544

__device__ __forceinline__ void prefetch_xj(uint32_t sb, int b, int jt, int buf, int tid)
{
    size_t rowbase = (size_t)b*Nd + (size_t)jt*64;
    uint32_t dH = sb + (buf ? OXJH1 : OXJH0);
    uint32_t dL = sb + (buf ? OXJL1 : OXJL0);
    #pragma unroll
    for (int c = 0; c < 4; c++) {
        int idx = tid + c*256;
        int row = idx >> 4, ch = idx & 15;
        cpasync16(dH + row*272 + ch*16, g_xh + (rowbase + row)*Dd + ch*8);
    }
    #pragma unroll
    for (int c = 0; c < 4; c++) {
        int idx = tid + c*256;
        int row = idx >> 4, ch = idx & 15;
        cpasync16(dL + row*272 + ch*16, g_xl + (rowbase + row)*Dd + ch*8);
    }
    if (tid < 16) cpasync16(sb + (buf ? OX0J1 : OX0J0) + tid*16, g_x0 + rowbase + tid*4);
    if (tid < 4)  cpasync16(sb + (buf ? OMS1 : OMS0) + tid*16, g_mask + rowbase + tid*16);
    cp_commit();
}

__global__ void __launch_bounds__(256, 1) k_attn_mma()
{
    extern __shared__ float4 smem_f4[];
    char* smb = (char*)smem_f4;
    const uint32_t sb = smem_u32(smb);

    const int tid  = threadIdx.x;
    const int wid  = tid >> 5;
    const int lane = tid & 31;
    const int b    = blockIdx.y;
    const int i0   = blockIdx.x * 128;
    const float invsq = 1.0f / sqrtf(129.0f);

    // ---- Xi tile + x0i via cp.async (one group with tile-0 prefetch) ----
    {
        size_t rowbase = (size_t)b*Nd + i0;
        #pragma unroll
        for (int c = 0; c < 8; c++) {
            int idx = tid + c*256;
            int row = idx >> 4, ch = idx & 15;
            cpasync16(sb + OXIH + row*272 + ch*16, g_xh + (rowbase + row)*Dd + ch*8);
        }
        #pragma unroll
        for (int c = 0; c < 8; c++) {
            int idx = tid + c*256;
            int row = idx >> 4, ch = idx & 15;
            cpasync16(sb + OXIL + row*272 + ch*16, g_xl + (rowbase + row)*Dd + ch*8);
        }
        if (tid < 32) cpasync16(sb + OX0I + tid*16, g_x0 + rowbase + tid*4);
    }
    prefetch_xj(sb, b, 0, 0, tid);

    const int r0 = wid*16 + (lane >> 2);
    const int cq = (lane & 3) * 2;

    // ldmatrix address patterns
    const int la_row = lane & 15;
    const int la_kof = (lane >> 4) << 3;
    const int lb_n   = (lane & 7) + ((lane >> 4) << 3);
    const int lb_kof = ((lane >> 3) & 1) << 3;
    const int tr_row = (lane & 7) + (((lane >> 3) & 1) << 3);  // j within block
    const int tr_col = (lane >> 4) << 3;                       // d offset

    const uint32_t aXiH = sb + OXIH + ((wid*16 + la_row)*STX + la_kof)*2;
    const uint32_t aXiL = sb + OXIL + ((wid*16 + la_row)*STX + la_kof)*2;

    float muc[16][4];
    #pragma unroll
    for (int f = 0; f < 16; f++)
        muc[f][0] = muc[f][1] = muc[f][2] = muc[f][3] = 0.f;
    float den0 = 0.f, den1 = 0.f, ac00 = 0.f, ac01 = 0.f;
    float xi0 = 0.f, xi1 = 0.f;

    int buf = 0;
    for (int jt = 0; jt < 16; jt++) {
        cp_wait_all();
        __syncthreads();
        if (jt == 0) {
            xi0 = ((float*)(smb + OX0I))[r0];
            xi1 = ((float*)(smb + OX0I))[r0 + 8];
        }
        if (jt + 1 < 16) prefetch_xj(sb, b, jt + 1, buf ^ 1, tid);

        const uint32_t oXjH = sb + (buf ? OXJH1 : OXJH0);
        const uint32_t oXjL = sb + (buf ? OXJL1 : OXJL0);
        const float*   x0j  = (const float*)(smb + (buf ? OX0J1 : OX0J0));
        const unsigned char* msb = (const unsigned char*)(smb + (buf ? OMS1 : OMS0));

        const uint32_t bXjH = oXjH + (lb_n*STX + lb_kof)*2;
        const uint32_t bXjL = oXjL + (lb_n*STX + lb_kof)*2;
        const uint32_t tXjH = oXjH + (tr_row*STX + tr_col)*2;
        const uint32_t tXjL = oXjL + (tr_row*STX + tr_col)*2;

        // ---- score MMAs: S[16 x 64], 3 split products, B loaded once ----
        float c[8][4];
        #pragma unroll
        for (int q = 0; q < 8; q++)
            c[q][0] = c[q][1] = c[q][2] = c[q][3] = 0.f;

        #pragma unroll
        for (int kk = 0; kk < 8; kk++) {
            uint32_t aH0, aH1, aH2, aH3, aL0, aL1, aL2, aL3;
            ldsm4(aH0, aH1, aH2, aH3, aXiH + kk*32);
            ldsm4(aL0, aL1, aL2, aL3, aXiL + kk*32);
            #pragma unroll
            for (int nb = 0; nb < 4; nb++) {
                uint32_t bH0, bH1, bH2, bH3, bL0, bL1, bL2, bL3;
                ldsm4(bH0, bH1, bH2, bH3, bXjH + nb*(16*STX*2) + kk*32);
                ldsm4(bL0, bL1, bL2, bL3, bXjL + nb*(16*STX*2) + kk*32);
                mma16816(c[nb*2],   aH0, aH1, aH2, aH3, bH0, bH1);
                mma16816(c[nb*2+1], aH0, aH1, aH2, aH3, bH2, bH3);
                mma16816(c[nb*2],   aH0, aH1, aH2, aH3, bL0, bL1);
                mma16816(c[nb*2+1], aH0, aH1, aH2, aH3, bL2, bL3);
                mma16816(c[nb*2],   aL0, aL1, aL2, aL3, bH0, bH1);
                mma16816(c[nb*2+1], aL0, aL1, aL2, aL3, bH2, bH3);
            }
        }

        // ---- epilogue in registers: e values -> mu A-fragments ----
        uint32_t eaH[4][4], eaL[4][4];
        #pragma unroll
        for (int q = 0; q < 8; q++) {
            int j0 = q*8 + cq;
            float xjx = x0j[j0], xjy = x0j[j0+1];
            float m0 = (float)msb[j0], m1 = (float)msb[j0+1];
            float e00 = m0 * __expf((xi0*xjx - c[q][0]) * invsq);
            float e01 = m1 * __expf((xi0*xjy - c[q][1]) * invsq);
            float e10 = m0 * __expf((xi1*xjx - c[q][2]) * invsq);
            float e11 = m1 * __expf((xi1*xjy - c[q][3]) * invsq);
            den0 += e00 + e01;  den1 += e10 + e11;
            ac00 += e00*xjx + e01*xjy;
            ac01 += e10*xjx + e11*xjy;
            __half h00 = __float2half_rn(e00), h01 = __float2half_rn(e01);
            __half h10 = __float2half_rn(e10), h11 = __float2half_rn(e11);
            uint32_t hp0 = (uint32_t)__half_as_ushort(h00) | ((uint32_t)__half_as_ushort(h01) << 16);
            uint32_t hp1 = (uint32_t)__half_as_ushort(h10) | ((uint32_t)__half_as_ushort(h11) << 16);
            uint32_t lp0 = packh(e00 - __half2float(h00), e01 - __half2float(h01));
            uint32_t lp1 = packh(e10 - __half2float(h10), e11 - __half2float(h11));
            int kk = q >> 1;
            if ((q & 1) == 0) {
                eaH[kk][0] = hp0; eaH[kk][1] = hp1;
                eaL[kk][0] = lp0; eaL[kk][1] = lp1;
            } else {
                eaH[kk][2] = hp0; eaH[kk][3] = hp1;
                eaL[kk][2] = lp0; eaL[kk][3] = lp1;
            }
        }

        // ---- mu MMAs: mu[16 x 128] += E[16x64] . Xj[64x128]; B via trans --
        #pragma unroll
        for (int kk = 0; kk < 4; kk++) {
            #pragma unroll
            for (int nb = 0; nb < 8; nb++) {
                uint32_t bH0, bH1, bH2, bH3, bL0, bL1, bL2, bL3;
                ldsm4t(bH0, bH1, bH2, bH3, tXjH + (kk*16*STX + nb*16)*2);
                ldsm4t(bL0, bL1, bL2, bL3, tXjL + (kk*16*STX + nb*16)*2);
                mma16816(muc[nb*2],   eaH[kk][0], eaH[kk][1], eaH[kk][2], eaH[kk][3], bH0, bH1);
                mma16816(muc[nb*2+1], eaH[kk][0], eaH[kk][1], eaH[kk][2], eaH[kk][3], bH2, bH3);
                mma16816(muc[nb*2],   eaH[kk][0], eaH[kk][1], eaH[kk][2], eaH[kk][3], bL0, bL1);
                mma16816(muc[nb*2+1], eaH[kk][0], eaH[kk][1], eaH[kk][2], eaH[kk][3], bL2, bL3);
                mma16816(muc[nb*2],   eaL[kk][0], eaL[kk][1], eaL[kk][2], eaL[kk][3], bH0, bH1);
                mma16816(muc[nb*2+1], eaL[kk][0], eaL[kk][1], eaL[kk][2], eaL[kk][3], bH2, bH3);
            }
        }
        buf ^= 1;
    }

    // ---- finalize: quad-reduce den/acc0, Lorentz renorm, store g_mu ----
    #pragma unroll
    for (int o = 1; o < 4; o <<= 1) {
        den0 += __shfl_xor_sync(0xffffffffu, den0, o);
        den1 += __shfl_xor_sync(0xffffffffu, den1, o);
        ac00 += __shfl_xor_sync(0xffffffffu, ac00, o);
        ac01 += __shfl_xor_sync(0xffffffffu, ac01, o);
    }
    float id0 = 1.f / den0, id1 = 1.f / den1;
    float mu00 = ac00 * id0, mu01 = ac01 * id1;

    float in0 = 0.f, in1 = 0.f;
    #pragma unroll
    for (int f = 0; f < 16; f++) {
        muc[f][0] *= id0; muc[f][1] *= id0;
        muc[f][2] *= id1; muc[f][3] *= id1;
        in0 += muc[f][0]*muc[f][0] + muc[f][1]*muc[f][1];
        in1 += muc[f][2]*muc[f][2] + muc[f][3]*muc[f][3];
    }
    #pragma unroll
    for (int o = 1; o < 4; o <<= 1) {
        in0 += __shfl_xor_sync(0xffffffffu, in0, o);
        in1 += __shfl_xor_sync(0xffffffffu, in1, o);
    }
    float s20 = 1.f / (SCc * sqrtf(fmaxf(mu00*mu00 - in0, EPSc)));
    float s21 = 1.f / (SCc * sqrtf(fmaxf(mu01*mu01 - in1, EPSc)));

    float* mo0 = g_mu + ((size_t)b*Nd + i0 + r0) * DX;
    float* mo1 = mo0 + (size_t)8 * DX;
    if ((lane & 3) == 0) { mo0[0] = mu00 * s20; mo1[0] = mu01 * s21; }
    #pragma unroll
    for (int f = 0; f < 16; f++) {
        int d = f*8 + cq;
        mo0[1 + d]     = muc[f][0] * s20;
        mo0[1 + d + 1] = muc[f][1] * s20;
        mo1[1 + d]     = muc[f][2] * s21;
        mo1[1 + d + 1] = muc[f][3] * s21;
    }
}

// ---------------- kernel 3: output projection + Poincare expmap0 -----------
#define SW 132
__global__ __launch_bounds__(256, 2)
void k_proj(const float* __restrict__ Wo, const float* __restrict__ bo)
{
    extern __shared__ float sm[];
    float* wo  = sm;               // 128*132
    float* mus = wo  + 128*SW;     // 64*132
    float* np  = mus + 64*SW;      // 64*16
    float* fv  = np  + 64*16;      // 64
    float* bos = fv  + 64;         // 128

    const int tid = threadIdx.x;
    const size_t row0 = (size_t)blockIdx.x * 64;

    for (int idx = tid; idx < 128*SW; idx += 256) {
        int o = idx / SW, k = idx - o*SW;
        wo[idx] = (k < DX) ? Wo[o*DX + k] : 0.f;
    }
    const float* mb = g_mu + row0 * DX;
    for (int idx = tid; idx < 64*SW; idx += 256) {
        int i = idx / SW, k = idx - i*SW;
        mus[idx] = (k < DX) ? mb[(size_t)i*DX + k] : 0.f;
    }
    if (tid < 128) bos[tid] = bo[tid];
    __syncthreads();

    const int tx = tid & 15, ty = tid >> 4;
    unsigned long long acc2[4][8];
    #pragma unroll
    for (int r = 0; r < 4; r++)
        #pragma unroll
        for (int q = 0; q < 8; q++) acc2[r][q] = 0ull;

    for (int k = 0; k < 132; k += 4) {
        ulonglong2 m2[4];
        #pragma unroll
        for (int r = 0; r < 4; r++)
            m2[r] = *(const ulonglong2*)&mus[(ty*4+r)*SW + k];
        #pragma unroll
        for (int q = 0; q < 8; q++) {
            ulonglong2 w2 = *(const ulonglong2*)&wo[(tx+16*q)*SW + k];
            #pragma unroll
            for (int r = 0; r < 4; r++) {
                fma2(acc2[r][q], m2[r].x, w2.x);
                fma2(acc2[r][q], m2[r].y, w2.y);
            }
        }
    }

    float acc[4][8];
    #pragma unroll
    for (int r = 0; r < 4; r++) {
        float pp = 0.f;
        #pragma unroll
        for (int q = 0; q < 8; q++) {
            float lo, hi;
            upk2(acc2[r][q], lo, hi);
            float a = lo + hi + bos[tx + 16*q];
            acc[r][q] = a;
            pp += a * a;
        }
        np[(ty*4+r)*16 + tx] = pp;
    }
    __syncthreads();

    if (tid < 64) {
        float s = 0.f;
        #pragma unroll
        for (int t = 0; t < 16; t++) s += np[tid*16 + t];
        float nu = fmaxf(sqrtf(s), EPSc);
        fv[tid] = tanhf(SCc*nu) / (SCc*nu);
    }
    __syncthreads();

    float* yb = g_y + row0 * Dd;
    #pragma unroll
    for (int r = 0; r < 4; r++) {
        float f = fv[ty*4 + r];
        float pp = 0.f;
        #pragma unroll
        for (int q = 0; q < 8; q++) {
            float yv = acc[r][q] * f;
            yb[(size_t)(ty*4+r)*Dd + tx + 16*q] = yv;
            pp += yv * yv;
        }
        np[(ty*4+r)*16 + tx] = pp;
    }
    __syncthreads();
    if (tid < 64) {
        float s = 0.f;
        #pragma unroll
        for (int t = 0; t < 16; t++) s += np[tid*16 + t];
        g_y2[row0 + tid] = s;
    }
}

// ---------------- kernel 4: sequential Mobius pooling + MLR head -----------
__global__ void k_pool(const float* __restrict__ Wf,
                       const float* __restrict__ bf,
                       float* __restrict__ out)
{
    const int b    = blockIdx.x;
    const int lane = threadIdx.x;
    const float* yb  = g_y  + (size_t)b*Nd*Dd;
    const float* y2b = g_y2 + (size_t)b*Nd;
    const unsigned char* mb = g_mask + (size_t)b*Nd;

    float a0=0.f, a1=0.f, a2=0.f, a3=0.f;
    int cnt = 0;

    float4 nyv = *(const float4*)(yb + lane*4);
    float  ny2 = y2b[0];

    for (int i = 0; i < Nd; i++) {
        float4 yv = nyv; float yy2 = ny2;
        int m = mb[i];
        if (i + 1 < Nd) {
            nyv = *(const float4*)(yb + (size_t)(i+1)*Dd + lane*4);
            ny2 = y2b[i+1];
        }
        if (!m) continue;
        float xy = a0*yv.x + a1*yv.y + a2*yv.z + a3*yv.w;
        float x2 = a0*a0 + a1*a1 + a2*a2 + a3*a3;
        #pragma unroll
        for (int o = 16; o; o >>= 1) {
            xy += __shfl_xor_sync(0xffffffffu, xy, o);
            x2 += __shfl_xor_sync(0xffffffffu, x2, o);
        }
        float aa  = 1.f + 2.f*CC*xy + CC*yy2;
        float bb  = 1.f - CC*x2;
        float den = fmaxf(1.f + 2.f*CC*xy + CC*CC*x2*yy2, 1e-12f);
        a0 = (aa*a0 + bb*yv.x) / den;
        a1 = (aa*a1 + bb*yv.y) / den;
        a2 = (aa*a2 + bb*yv.z) / den;
        a3 = (aa*a3 + bb*yv.w) / den;
        cnt++;
    }

    float n2 = a0*a0 + a1*a1 + a2*a2 + a3*a3;
    #pragma unroll
    for (int o = 16; o; o >>= 1) n2 += __shfl_xor_sync(0xffffffffu, n2, o);
    float nrm = sqrtf(n2);
    float t   = fminf(fmaxf(SCc*nrm, EPSc), 1.f - 1e-6f);
    float r   = 1.f / fmaxf((float)cnt, 1.f);
    float fac = tanhf(r * atanhf(t)) / fmaxf(SCc*nrm, EPSc);
    float p0 = fac*a0, p1 = fac*a1, p2 = fac*a2, p3 = fac*a3;
    if (cnt == 0) {
        float4 y0 = *(const float4*)(yb + lane*4);
        p0 = y0.x; p1 = y0.y; p2 = y0.z; p3 = y0.w;
    }

    float pn2 = p0*p0 + p1*p1 + p2*p2 + p3*p3;
    #pragma unroll
    for (int o = 16; o; o >>= 1) pn2 += __shfl_xor_sync(0xffffffffu, pn2, o);
    float npn = fmaxf(sqrtf(pn2), EPSc);
    float t2  = fminf(fmaxf(SCc*npn, EPSc), 1.f - 1e-6f);
    float cf  = atanhf(t2) / (SCc*npn);
    float v0 = cf*p0, v1 = cf*p1, v2 = cf*p2, v3 = cf*p3;

    for (int k = 0; k < NCd; k++) {
        float4 w = *(const float4*)(Wf + (size_t)k*Dd + lane*4);
        float pr = v0*w.x + v1*w.y + v2*w.z + v3*w.w;
        #pragma unroll
        for (int o = 16; o; o >>= 1) pr += __shfl_xor_sync(0xffffffffu, pr, o);
        if (lane == 0) out[b*NCd + k] = pr + bf[k];
    }
}

// ---------------------------- launcher -------------------------------------
extern "C" void kernel_launch(void* const* d_in, const int* in_sizes, int n_in,
                              void* d_out, int out_size)
{
    (void)in_sizes; (void)n_in; (void)out_size;
    const int*   tok  = (const int*)d_in[0];
    const void*  mask = d_in[1];
    const float* emb  = (const float*)d_in[2];
    const float* Wo   = (const float*)d_in[3];
    const float* bo   = (const float*)d_in[4];
    const float* Wf   = (const float*)d_in[5];
    const float* bf   = (const float*)d_in[6];
    float*       out  = (float*)d_out;

    const int smem_proj = (128*SW + 64*SW + 64*16 + 64 + 128) * 4;
    cudaFuncSetAttribute(k_attn_mma, cudaFuncAttributeMaxDynamicSharedMemorySize, ATT_SMEM);
    cudaFuncSetAttribute(k_proj,     cudaFuncAttributeMaxDynamicSharedMemorySize, smem_proj);

    k_detect   <<<1, 1024>>>((const unsigned char*)mask);
    k_masknorm <<<(Bd*Nd + 255)/256, 256>>>(mask);
    k_embed    <<<(Bd*Nd)/8, 256>>>(tok, emb);
    k_attn_mma <<<dim3(8, Bd), 256, ATT_SMEM>>>();
    k_proj     <<<(Bd*Nd)/64, 256, smem_proj>>>(Wo, bo);
    k_pool     <<<Bd, 32>>>(Wf, bf, out);
}

// round 10
// speedup vs baseline: 2.7366x; 1.1724x over previous
#include <cuda_runtime.h>
#include <cuda_fp16.h>
#include <cstdint>
#include <cstddef>

#define CC   0.1f
#define SCc  0.31622776601683794f   /* sqrt(0.1) */
#define EPSc 1e-7f

#define Bd  64
#define Nd  1024
#define Dd  128
#define DX  129
#define NCd 10

// ---------------- warp-MMA / cp.async helpers (baseline PTX) ---------------
__device__ __forceinline__ uint32_t smem_u32(const void* p)
{
    uint32_t a;
    asm("{ .reg .u64 t; cvta.to.shared.u64 t, %1; cvt.u32.u64 %0, t; }"
        : "=r"(a) : "l"(p));
    return a;
}
__device__ __forceinline__ void ldsm4(uint32_t& r0, uint32_t& r1,
                                      uint32_t& r2, uint32_t& r3, uint32_t addr)
{
    asm volatile("ldmatrix.sync.aligned.m8n8.x4.shared.b16 {%0,%1,%2,%3}, [%4];"
                 : "=r"(r0), "=r"(r1), "=r"(r2), "=r"(r3) : "r"(addr));
}
__device__ __forceinline__ void ldsm4t(uint32_t& r0, uint32_t& r1,
                                       uint32_t& r2, uint32_t& r3, uint32_t addr)
{
    asm volatile("ldmatrix.sync.aligned.m8n8.x4.trans.shared.b16 {%0,%1,%2,%3}, [%4];"
                 : "=r"(r0), "=r"(r1), "=r"(r2), "=r"(r3) : "r"(addr));
}
__device__ __forceinline__ void mma16816(float* c, uint32_t a0, uint32_t a1,
                                         uint32_t a2, uint32_t a3,
                                         uint32_t b0, uint32_t b1)
{
    asm volatile("mma.sync.aligned.m16n8k16.row.col.f32.f16.f16.f32 "
                 "{%0,%1,%2,%3}, {%4,%5,%6,%7}, {%8,%9}, {%0,%1,%2,%3};"
                 : "+f"(c[0]), "+f"(c[1]), "+f"(c[2]), "+f"(c[3])
                 : "r"(a0), "r"(a1), "r"(a2), "r"(a3), "r"(b0), "r"(b1));
}
__device__ __forceinline__ void cpasync16(uint32_t dst, const void* src)
{
    asm volatile("cp.async.cg.shared.global [%0], [%1], 16;"
                 :: "r"(dst), "l"(src) : "memory");
}
__device__ __forceinline__ void cp_commit()
{
    asm volatile("cp.async.commit_group;" ::: "memory");
}
__device__ __forceinline__ void cp_wait_all()
{
    asm volatile("cp.async.wait_group 0;" ::: "memory");
}
__device__ __forceinline__ uint32_t packh(float a, float b)
{
    __half ha = __float2half_rn(a), hb = __float2half_rn(b);
    return (uint32_t)__half_as_ushort(ha) | ((uint32_t)__half_as_ushort(hb) << 16);
}

// ---------------- scratch (device globals; no runtime allocation) ----------
__device__ __align__(16) __half g_xh[(size_t)Bd*Nd*Dd];  // x spatial hi
__device__ __align__(16) __half g_xl[(size_t)Bd*Nd*Dd];  // x spatial lo
__device__ __align__(16) float  g_x0[(size_t)Bd*Nd];     // x time component
__device__ __align__(16) __half g_muh[(size_t)Bd*Nd*Dd]; // mu spatial hi
__device__ __align__(16) __half g_mul[(size_t)Bd*Nd*Dd]; // mu spatial lo
__device__ __align__(16) float  g_mu0[(size_t)Bd*Nd];    // mu time component
__device__ __align__(16) __half g_wh[(size_t)Dd*Dd];     // Wo spatial hi
__device__ __align__(16) __half g_wl[(size_t)Dd*Dd];     // Wo spatial lo
__device__ __align__(16) float  g_wo0[Dd];               // Wo[:,0]
__device__ float g_y [(size_t)Bd*Nd*Dd];   // Poincare tokens (B,N,128)
__device__ float g_y2[(size_t)Bd*Nd];      // |y|^2 per token
__device__ __align__(16) unsigned char g_mask[(size_t)Bd*Nd];
__device__ int g_is32;

// ---------------- kernel 0a/0b: mask dtype detect + normalize --------------
__global__ void k_detect(const unsigned char* __restrict__ m)
{
    __shared__ int found;
    if (threadIdx.x == 0) found = 0;
    __syncthreads();
    int acc = 0;
    for (int i = threadIdx.x; i < Bd*Nd; i += blockDim.x)
        if ((i & 3) && m[i]) acc = 1;
    if (acc) atomicOr(&found, 1);
    __syncthreads();
    if (threadIdx.x == 0) g_is32 = found ? 0 : 1;
}
__global__ void k_masknorm(const void* __restrict__ m)
{
    int i = blockIdx.x * blockDim.x + threadIdx.x;
    if (i >= Bd*Nd) return;
    unsigned char v;
    if (g_is32) v = (((const int*)m)[i] != 0);
    else        v = (((const unsigned char*)m)[i] != 0);
    g_mask[i] = v;
}

// ---------------- kernel 0c: split Wo into fp16 hi/lo ----------------------
__global__ void k_wprep(const float* __restrict__ Wo)
{
    int idx = blockIdx.x * blockDim.x + threadIdx.x;
    if (idx >= Dd*Dd) return;
    int o = idx >> 7, k = idx & 127;
    float v = Wo[o*DX + (k+1)];
    __half h = __float2half_rn(v);
    g_wh[idx] = h;
    g_wl[idx] = __float2half_rn(v - __half2float(h));
    if (k == 0) g_wo0[o] = Wo[o*DX];
}

// ---------------- kernel 1: embedding + Lorentz expmap0 (fp16 split out) ---
__global__ void k_embed(const int* __restrict__ tok, const float* __restrict__ emb)
{
    int gw   = (blockIdx.x * blockDim.x + threadIdx.x) >> 5;
    int lane = threadIdx.x & 31;
    if (gw >= Bd*Nd) return;
    int t = tok[gw];
    float4 v = *(const float4*)(emb + (size_t)t*Dd + lane*4);
    float ss = v.x*v.x + v.y*v.y + v.z*v.z + v.w*v.w;
    #pragma unroll
    for (int o = 16; o; o >>= 1) ss += __shfl_xor_sync(0xffffffffu, ss, o);
    float nv   = fmaxf(sqrtf(ss), EPSc);
    float tt   = SCc * nv;
    float coef = sinhf(tt) / (SCc * nv);
    if (lane == 0) g_x0[gw] = coshf(tt) / SCc;

    float vv[4] = {coef*v.x, coef*v.y, coef*v.z, coef*v.w};
    uint32_t h01, h23, l01, l23;
    {
        __half h0 = __float2half_rn(vv[0]), h1 = __float2half_rn(vv[1]);
        __half h2 = __float2half_rn(vv[2]), h3 = __float2half_rn(vv[3]);
        h01 = (uint32_t)__half_as_ushort(h0) | ((uint32_t)__half_as_ushort(h1) << 16);
        h23 = (uint32_t)__half_as_ushort(h2) | ((uint32_t)__half_as_ushort(h3) << 16);
        l01 = packh(vv[0] - __half2float(h0), vv[1] - __half2float(h1));
        l23 = packh(vv[2] - __half2float(h2), vv[3] - __half2float(h3));
    }
    uint2* ph = (uint2*)(g_xh + (size_t)gw*Dd + lane*4);
    uint2* pl = (uint2*)(g_xl + (size_t)gw*Dd + lane*4);
    *ph = make_uint2(h01, h23);
    *pl = make_uint2(l01, l23);
}

// ---------------- kernel 2: attention via mma.sync, 64-query tiles ---------
// grid (16, 64); 128 threads = 4 warps x 16 query rows; 2 CTAs/SM.
#define STX 136
#define OXIH 0
#define OXIL 17408
#define OXJH0 34816
#define OXJL0 52224
#define OXJH1 69632
#define OXJL1 87040
#define OX0I 104448
#define OX0J0 104704
#define OX0J1 104960
#define OMS0 105216
#define OMS1 105280
#define ATT_SMEM 105344

__device__ __forceinline__ void prefetch_xj(uint32_t sb, int b, int jt, int buf, int tid)
{
    size_t rowbase = (size_t)b*Nd + (size_t)jt*64;
    uint32_t dH = sb + (buf ? OXJH1 : OXJH0);
    uint32_t dL = sb + (buf ? OXJL1 : OXJL0);
    #pragma unroll
    for (int c = 0; c < 8; c++) {
        int idx = tid + c*128;
        int row = idx >> 4, ch = idx & 15;
        cpasync16(dH + row*272 + ch*16, g_xh + (rowbase + row)*Dd + ch*8);
    }
    #pragma unroll
    for (int c = 0; c < 8; c++) {
        int idx = tid + c*128;
        int row = idx >> 4, ch = idx & 15;
        cpasync16(dL + row*272 + ch*16, g_xl + (rowbase + row)*Dd + ch*8);
    }
    if (tid < 16) cpasync16(sb + (buf ? OX0J1 : OX0J0) + tid*16, g_x0 + rowbase + tid*4);
    if (tid < 4)  cpasync16(sb + (buf ? OMS1 : OMS0) + tid*16, g_mask + rowbase + tid*16);
    cp_commit();
}

__global__ void __launch_bounds__(128, 2) k_attn_mma()
{
    extern __shared__ float4 smem_f4[];
    char* smb = (char*)smem_f4;
    const uint32_t sb = smem_u32(smb);

    const int tid  = threadIdx.x;
    const int wid  = tid >> 5;
    const int lane = tid & 31;
    const int b    = blockIdx.y;
    const int i0   = blockIdx.x * 64;
    const float invsq = 1.0f / sqrtf(129.0f);

    // ---- Xi tile (64 rows) + x0i via cp.async ----
    {
        size_t rowbase = (size_t)b*Nd + i0;
        #pragma unroll
        for (int c = 0; c < 8; c++) {
            int idx = tid + c*128;
            int row = idx >> 4, ch = idx & 15;
            cpasync16(sb + OXIH + row*272 + ch*16, g_xh + (rowbase + row)*Dd + ch*8);
        }
        #pragma unroll
        for (int c = 0; c < 8; c++) {
            int idx = tid + c*128;
            int row = idx >> 4, ch = idx & 15;
            cpasync16(sb + OXIL + row*272 + ch*16, g_xl + (rowbase + row)*Dd + ch*8);
        }
        if (tid < 16) cpasync16(sb + OX0I + tid*16, g_x0 + rowbase + tid*4);
    }
    prefetch_xj(sb, b, 0, 0, tid);

    const int r0 = wid*16 + (lane >> 2);
    const int cq = (lane & 3) * 2;

    const int la_row = lane & 15;
    const int la_kof = (lane >> 4) << 3;
    const int lb_n   = (lane & 7) + ((lane >> 4) << 3);
    const int lb_kof = ((lane >> 3) & 1) << 3;
    const int tr_row = (lane & 7) + (((lane >> 3) & 1) << 3);
    const int tr_col = (lane >> 4) << 3;

    const uint32_t aXiH = sb + OXIH + ((wid*16 + la_row)*STX + la_kof)*2;
    const uint32_t aXiL = sb + OXIL + ((wid*16 + la_row)*STX + la_kof)*2;

    float muc[16][4];
    #pragma unroll
    for (int f = 0; f < 16; f++)
        muc[f][0] = muc[f][1] = muc[f][2] = muc[f][3] = 0.f;
    float den0 = 0.f, den1 = 0.f, ac00 = 0.f, ac01 = 0.f;
    float xi0 = 0.f, xi1 = 0.f;

    int buf = 0;
    for (int jt = 0; jt < 16; jt++) {
        cp_wait_all();
        __syncthreads();
        if (jt == 0) {
            xi0 = ((float*)(smb + OX0I))[r0];
            xi1 = ((float*)(smb + OX0I))[r0 + 8];
        }
        if (jt + 1 < 16) prefetch_xj(sb, b, jt + 1, buf ^ 1, tid);

        const uint32_t oXjH = sb + (buf ? OXJH1 : OXJH0);
        const uint32_t oXjL = sb + (buf ? OXJL1 : OXJL0);
        const float*   x0j  = (const float*)(smb + (buf ? OX0J1 : OX0J0));
        const unsigned char* msb = (const unsigned char*)(smb + (buf ? OMS1 : OMS0));

        const uint32_t bXjH = oXjH + (lb_n*STX + lb_kof)*2;
        const uint32_t bXjL = oXjL + (lb_n*STX + lb_kof)*2;
        const uint32_t tXjH = oXjH + (tr_row*STX + tr_col)*2;
        const uint32_t tXjL = oXjL + (tr_row*STX + tr_col)*2;

        // ---- score MMAs: S[16 x 64], 3 split products ----
        float c[8][4];
        #pragma unroll
        for (int q = 0; q < 8; q++)
            c[q][0] = c[q][1] = c[q][2] = c[q][3] = 0.f;

        #pragma unroll
        for (int kk = 0; kk < 8; kk++) {
            uint32_t aH0, aH1, aH2, aH3, aL0, aL1, aL2, aL3;
            ldsm4(aH0, aH1, aH2, aH3, aXiH + kk*32);
            ldsm4(aL0, aL1, aL2, aL3, aXiL + kk*32);
            #pragma unroll
            for (int nb = 0; nb < 4; nb++) {
                uint32_t bH0, bH1, bH2, bH3, bL0, bL1, bL2, bL3;
                ldsm4(bH0, bH1, bH2, bH3, bXjH + nb*(16*STX*2) + kk*32);
                ldsm4(bL0, bL1, bL2, bL3, bXjL + nb*(16*STX*2) + kk*32);
                mma16816(c[nb*2],   aH0, aH1, aH2, aH3, bH0, bH1);
                mma16816(c[nb*2+1], aH0, aH1, aH2, aH3, bH2, bH3);
                mma16816(c[nb*2],   aH0, aH1, aH2, aH3, bL0, bL1);
                mma16816(c[nb*2+1], aH0, aH1, aH2, aH3, bL2, bL3);
                mma16816(c[nb*2],   aL0, aL1, aL2, aL3, bH0, bH1);
                mma16816(c[nb*2+1], aL0, aL1, aL2, aL3, bH2, bH3);
            }
        }

        // ---- epilogue in registers: e values -> mu A-fragments ----
        uint32_t eaH[4][4], eaL[4][4];
        #pragma unroll
        for (int q = 0; q < 8; q++) {
            int j0 = q*8 + cq;
            float xjx = x0j[j0], xjy = x0j[j0+1];
            float m0 = (float)msb[j0], m1 = (float)msb[j0+1];
            float e00 = m0 * __expf((xi0*xjx - c[q][0]) * invsq);
            float e01 = m1 * __expf((xi0*xjy - c[q][1]) * invsq);
            float e10 = m0 * __expf((xi1*xjx - c[q][2]) * invsq);
            float e11 = m1 * __expf((xi1*xjy - c[q][3]) * invsq);
            den0 += e00 + e01;  den1 += e10 + e11;
            ac00 += e00*xjx + e01*xjy;
            ac01 += e10*xjx + e11*xjy;
            __half h00 = __float2half_rn(e00), h01 = __float2half_rn(e01);
            __half h10 = __float2half_rn(e10), h11 = __float2half_rn(e11);
            uint32_t hp0 = (uint32_t)__half_as_ushort(h00) | ((uint32_t)__half_as_ushort(h01) << 16);
            uint32_t hp1 = (uint32_t)__half_as_ushort(h10) | ((uint32_t)__half_as_ushort(h11) << 16);
            uint32_t lp0 = packh(e00 - __half2float(h00), e01 - __half2float(h01));
            uint32_t lp1 = packh(e10 - __half2float(h10), e11 - __half2float(h11));
            int kk = q >> 1;
            if ((q & 1) == 0) {
                eaH[kk][0] = hp0; eaH[kk][1] = hp1;
                eaL[kk][0] = lp0; eaL[kk][1] = lp1;
            } else {
                eaH[kk][2] = hp0; eaH[kk][3] = hp1;
                eaL[kk][2] = lp0; eaL[kk][3] = lp1;
            }
        }

        // ---- mu MMAs: mu[16 x 128] += E[16x64] . Xj[64x128]; B via trans --
        #pragma unroll
        for (int kk = 0; kk < 4; kk++) {
            #pragma unroll
            for (int nb = 0; nb < 8; nb++) {
                uint32_t bH0, bH1, bH2, bH3, bL0, bL1, bL2, bL3;
                ldsm4t(bH0, bH1, bH2, bH3, tXjH + (kk*16*STX + nb*16)*2);
                ldsm4t(bL0, bL1, bL2, bL3, tXjL + (kk*16*STX + nb*16)*2);
                mma16816(muc[nb*2],   eaH[kk][0], eaH[kk][1], eaH[kk][2], eaH[kk][3], bH0, bH1);
                mma16816(muc[nb*2+1], eaH[kk][0], eaH[kk][1], eaH[kk][2], eaH[kk][3], bH2, bH3);
                mma16816(muc[nb*2],   eaH[kk][0], eaH[kk][1], eaH[kk][2], eaH[kk][3], bL0, bL1);
                mma16816(muc[nb*2+1], eaH[kk][0], eaH[kk][1], eaH[kk][2], eaH[kk][3], bL2, bL3);
                mma16816(muc[nb*2],   eaL[kk][0], eaL[kk][1], eaL[kk][2], eaL[kk][3], bH0, bH1);
                mma16816(muc[nb*2+1], eaL[kk][0], eaL[kk][1], eaL[kk][2], eaL[kk][3], bH2, bH3);
            }
        }
        buf ^= 1;
    }

    // ---- finalize: quad-reduce, Lorentz renorm, store mu as fp16 hi/lo ----
    #pragma unroll
    for (int o = 1; o < 4; o <<= 1) {
        den0 += __shfl_xor_sync(0xffffffffu, den0, o);
        den1 += __shfl_xor_sync(0xffffffffu, den1, o);
        ac00 += __shfl_xor_sync(0xffffffffu, ac00, o);
        ac01 += __shfl_xor_sync(0xffffffffu, ac01, o);
    }
    float id0 = 1.f / den0, id1 = 1.f / den1;
    float mu00 = ac00 * id0, mu01 = ac01 * id1;

    float in0 = 0.f, in1 = 0.f;
    #pragma unroll
    for (int f = 0; f < 16; f++) {
        muc[f][0] *= id0; muc[f][1] *= id0;
        muc[f][2] *= id1; muc[f][3] *= id1;
        in0 += muc[f][0]*muc[f][0] + muc[f][1]*muc[f][1];
        in1 += muc[f][2]*muc[f][2] + muc[f][3]*muc[f][3];
    }
    #pragma unroll
    for (int o = 1; o < 4; o <<= 1) {
        in0 += __shfl_xor_sync(0xffffffffu, in0, o);
        in1 += __shfl_xor_sync(0xffffffffu, in1, o);
    }
    float s20 = 1.f / (SCc * sqrtf(fmaxf(mu00*mu00 - in0, EPSc)));
    float s21 = 1.f / (SCc * sqrtf(fmaxf(mu01*mu01 - in1, EPSc)));

    size_t rg0 = (size_t)b*Nd + i0 + r0;
    size_t rg1 = rg0 + 8;
    if ((lane & 3) == 0) { g_mu0[rg0] = mu00 * s20; g_mu0[rg1] = mu01 * s21; }
    #pragma unroll
    for (int f = 0; f < 16; f++) {
        int d = f*8 + cq;
        float v00 = muc[f][0] * s20, v01 = muc[f][1] * s20;
        float v10 = muc[f][2] * s21, v11 = muc[f][3] * s21;
        __half h00 = __float2half_rn(v00), h01 = __float2half_rn(v01);
        __half h10 = __float2half_rn(v10), h11 = __float2half_rn(v11);
        *(uint32_t*)(g_muh + rg0*Dd + d) =
            (uint32_t)__half_as_ushort(h00) | ((uint32_t)__half_as_ushort(h01) << 16);
        *(uint32_t*)(g_muh + rg1*Dd + d) =
            (uint32_t)__half_as_ushort(h10) | ((uint32_t)__half_as_ushort(h11) << 16);
        *(uint32_t*)(g_mul + rg0*Dd + d) = packh(v00 - __half2float(h00), v01 - __half2float(h01));
        *(uint32_t*)(g_mul + rg1*Dd + d) = packh(v10 - __half2float(h10), v11 - __half2float(h11));
    }
}

// ---------------- kernel 3: projection via mma.sync + Poincare expmap0 -----
// grid 1024 (64 rows each); 128 threads = 4 warps x 16 rows.
#define PAH 0
#define PAL 17408
#define PBH 34816
#define PBL 69632
#define PW0 104448
#define PBO 104960
#define PROJ_SMEM 105472

__global__ void __launch_bounds__(128, 2) k_proj(const float* __restrict__ bo)
{
    extern __shared__ float4 smem_f4[];
    char* smb = (char*)smem_f4;
    const uint32_t sb = smem_u32(smb);

    const int tid  = threadIdx.x;
    const int wid  = tid >> 5;
    const int lane = tid & 31;
    const size_t row0 = (size_t)blockIdx.x * 64;

    // ---- cp.async loads: A (mu hi/lo), B (Wo hi/lo), wo0, bo ----
    #pragma unroll
    for (int c = 0; c < 8; c++) {
        int idx = tid + c*128;
        int row = idx >> 4, ch = idx & 15;
        cpasync16(sb + PAH + row*272 + ch*16, g_muh + (row0 + row)*Dd + ch*8);
        cpasync16(sb + PAL + row*272 + ch*16, g_mul + (row0 + row)*Dd + ch*8);
    }
    #pragma unroll
    for (int c = 0; c < 16; c++) {
        int idx = tid + c*128;
        int row = idx >> 4, ch = idx & 15;
        cpasync16(sb + PBH + row*272 + ch*16, g_wh + (size_t)row*Dd + ch*8);
        cpasync16(sb + PBL + row*272 + ch*16, g_wl + (size_t)row*Dd + ch*8);
    }
    if (tid < 32) cpasync16(sb + PW0 + tid*16, g_wo0 + tid*4);
    else if (tid < 64) cpasync16(sb + PBO + (tid-32)*16, bo + (tid-32)*4);
    cp_commit();

    const int r0 = wid*16 + (lane >> 2);
    const int cq = (lane & 3) * 2;
    const int la_row = lane & 15;
    const int la_kof = (lane >> 4) << 3;
    const int lb_n   = (lane & 7) + ((lane >> 4) << 3);
    const int lb_kof = ((lane >> 3) & 1) << 3;

    const uint32_t aAH = sb + PAH + ((wid*16 + la_row)*STX + la_kof)*2;
    const uint32_t aAL = sb + PAL + ((wid*16 + la_row)*STX + la_kof)*2;
    const uint32_t bBH = sb + PBH + (lb_n*STX + lb_kof)*2;
    const uint32_t bBL = sb + PBL + (lb_n*STX + lb_kof)*2;

    cp_wait_all();
    __syncthreads();

    float c[16][4];
    #pragma unroll
    for (int q = 0; q < 16; q++)
        c[q][0] = c[q][1] = c[q][2] = c[q][3] = 0.f;

    #pragma unroll
    for (int kk = 0; kk < 8; kk++) {
        uint32_t aH0, aH1, aH2, aH3, aL0, aL1, aL2, aL3;
        ldsm4(aH0, aH1, aH2, aH3, aAH + kk*32);
        ldsm4(aL0, aL1, aL2, aL3, aAL + kk*32);
        #pragma unroll
        for (int nb = 0; nb < 8; nb++) {
            uint32_t bH0, bH1, bH2, bH3, bL0, bL1, bL2, bL3;
            ldsm4(bH0, bH1, bH2, bH3, bBH + nb*(16*STX*2) + kk*32);
            ldsm4(bL0, bL1, bL2, bL3, bBL + nb*(16*STX*2) + kk*32);
            mma16816(c[nb*2],   aH0, aH1, aH2, aH3, bH0, bH1);
            mma16816(c[nb*2+1], aH0, aH1, aH2, aH3, bH2, bH3);
            mma16816(c[nb*2],   aH0, aH1, aH2, aH3, bL0, bL1);
            mma16816(c[nb*2+1], aH0, aH1, aH2, aH3, bL2, bL3);
            mma16816(c[nb*2],   aL0, aL1, aL2, aL3, bH0, bH1);
            mma16816(c[nb*2+1], aL0, aL1, aL2, aL3, bH2, bH3);
        }
    }

    // ---- epilogue: +mu0*Wo0 + bo, norm, tanh scale, write y/y2 ----
    const float* wo0s = (const float*)(smb + PW0);
    const float* bos  = (const float*)(smb + PBO);
    float mu0a = g_mu0[row0 + r0];
    float mu0b = g_mu0[row0 + r0 + 8];

    float u[16][4];
    float pp0 = 0.f, pp1 = 0.f;
    #pragma unroll
    for (int q = 0; q < 16; q++) {
        int col = q*8 + cq;
        float w0 = wo0s[col], w1 = wo0s[col+1];
        float b0 = bos[col],  b1 = bos[col+1];
        u[q][0] = c[q][0] + mu0a*w0 + b0;
        u[q][1] = c[q][1] + mu0a*w1 + b1;
        u[q][2] = c[q][2] + mu0b*w0 + b0;
        u[q][3] = c[q][3] + mu0b*w1 + b1;
        pp0 += u[q][0]*u[q][0] + u[q][1]*u[q][1];
        pp1 += u[q][2]*u[q][2] + u[q][3]*u[q][3];
    }
    #pragma unroll
    for (int o = 1; o < 4; o <<= 1) {
        pp0 += __shfl_xor_sync(0xffffffffu, pp0, o);
        pp1 += __shfl_xor_sync(0xffffffffu, pp1, o);
    }
    float nu0 = fmaxf(sqrtf(pp0), EPSc);
    float nu1 = fmaxf(sqrtf(pp1), EPSc);
    float f0 = tanhf(SCc*nu0) / (SCc*nu0);
    float f1 = tanhf(SCc*nu1) / (SCc*nu1);

    float* y0 = g_y + (row0 + r0) * Dd;
    float* y1 = g_y + (row0 + r0 + 8) * Dd;
    float qq0 = 0.f, qq1 = 0.f;
    #pragma unroll
    for (int q = 0; q < 16; q++) {
        int col = q*8 + cq;
        float v00 = u[q][0]*f0, v01 = u[q][1]*f0;
        float v10 = u[q][2]*f1, v11 = u[q][3]*f1;
        *(float2*)(y0 + col) = make_float2(v00, v01);
        *(float2*)(y1 + col) = make_float2(v10, v11);
        qq0 += v00*v00 + v01*v01;
        qq1 += v10*v10 + v11*v11;
    }
    #pragma unroll
    for (int o = 1; o < 4; o <<= 1) {
        qq0 += __shfl_xor_sync(0xffffffffu, qq0, o);
        qq1 += __shfl_xor_sync(0xffffffffu, qq1, o);
    }
    if ((lane & 3) == 0) {
        g_y2[row0 + r0]     = qq0;
        g_y2[row0 + r0 + 8] = qq1;
    }
}

// ---------------- kernel 4: sequential Mobius pooling + MLR head -----------
__global__ void k_pool(const float* __restrict__ Wf,
                       const float* __restrict__ bf,
                       float* __restrict__ out)
{
    const int b    = blockIdx.x;
    const int lane = threadIdx.x;
    const float* yb  = g_y  + (size_t)b*Nd*Dd;
    const float* y2b = g_y2 + (size_t)b*Nd;
    const unsigned char* mb = g_mask + (size_t)b*Nd;

    float a0=0.f, a1=0.f, a2=0.f, a3=0.f;
    int cnt = 0;

    float4 nyv = *(const float4*)(yb + lane*4);
    float  ny2 = y2b[0];

    for (int i = 0; i < Nd; i++) {
        float4 yv = nyv; float yy2 = ny2;
        int m = mb[i];
        if (i + 1 < Nd) {
            nyv = *(const float4*)(yb + (size_t)(i+1)*Dd + lane*4);
            ny2 = y2b[i+1];
        }
        if (!m) continue;
        float xy = a0*yv.x + a1*yv.y + a2*yv.z + a3*yv.w;
        float x2 = a0*a0 + a1*a1 + a2*a2 + a3*a3;
        #pragma unroll
        for (int o = 16; o; o >>= 1) {
            xy += __shfl_xor_sync(0xffffffffu, xy, o);
            x2 += __shfl_xor_sync(0xffffffffu, x2, o);
        }
        float aa  = 1.f + 2.f*CC*xy + CC*yy2;
        float bb  = 1.f - CC*x2;
        float den = fmaxf(1.f + 2.f*CC*xy + CC*CC*x2*yy2, 1e-12f);
        a0 = (aa*a0 + bb*yv.x) / den;
        a1 = (aa*a1 + bb*yv.y) / den;
        a2 = (aa*a2 + bb*yv.z) / den;
        a3 = (aa*a3 + bb*yv.w) / den;
        cnt++;
    }

    float n2 = a0*a0 + a1*a1 + a2*a2 + a3*a3;
    #pragma unroll
    for (int o = 16; o; o >>= 1) n2 += __shfl_xor_sync(0xffffffffu, n2, o);
    float nrm = sqrtf(n2);
    float t   = fminf(fmaxf(SCc*nrm, EPSc), 1.f - 1e-6f);
    float r   = 1.f / fmaxf((float)cnt, 1.f);
    float fac = tanhf(r * atanhf(t)) / fmaxf(SCc*nrm, EPSc);
    float p0 = fac*a0, p1 = fac*a1, p2 = fac*a2, p3 = fac*a3;
    if (cnt == 0) {
        float4 y0 = *(const float4*)(yb + lane*4);
        p0 = y0.x; p1 = y0.y; p2 = y0.z; p3 = y0.w;
    }

    float pn2 = p0*p0 + p1*p1 + p2*p2 + p3*p3;
    #pragma unroll
    for (int o = 16; o; o >>= 1) pn2 += __shfl_xor_sync(0xffffffffu, pn2, o);
    float npn = fmaxf(sqrtf(pn2), EPSc);
    float t2  = fminf(fmaxf(SCc*npn, EPSc), 1.f - 1e-6f);
    float cf  = atanhf(t2) / (SCc*npn);
    float v0 = cf*p0, v1 = cf*p1, v2 = cf*p2, v3 = cf*p3;

    for (int k = 0; k < NCd; k++) {
        float4 w = *(const float4*)(Wf + (size_t)k*Dd + lane*4);
        float pr = v0*w.x + v1*w.y + v2*w.z + v3*w.w;
        #pragma unroll
        for (int o = 16; o; o >>= 1) pr += __shfl_xor_sync(0xffffffffu, pr, o);
        if (lane == 0) out[b*NCd + k] = pr + bf[k];
    }
}

// ---------------------------- launcher -------------------------------------
extern "C" void kernel_launch(void* const* d_in, const int* in_sizes, int n_in,
                              void* d_out, int out_size)
{
    (void)in_sizes; (void)n_in; (void)out_size;
    const int*   tok  = (const int*)d_in[0];
    const void*  mask = d_in[1];
    const float* emb  = (const float*)d_in[2];
    const float* Wo   = (const float*)d_in[3];
    const float* bo   = (const float*)d_in[4];
    const float* Wf   = (const float*)d_in[5];
    const float* bf   = (const float*)d_in[6];
    float*       out  = (float*)d_out;

    cudaFuncSetAttribute(k_attn_mma, cudaFuncAttributeMaxDynamicSharedMemorySize, ATT_SMEM);
    cudaFuncSetAttribute(k_proj,     cudaFuncAttributeMaxDynamicSharedMemorySize, PROJ_SMEM);

    k_detect   <<<1, 1024>>>((const unsigned char*)mask);
    k_masknorm <<<(Bd*Nd + 255)/256, 256>>>(mask);
    k_wprep    <<<(Dd*Dd + 255)/256, 256>>>(Wo);
    k_embed    <<<(Bd*Nd)/8, 256>>>(tok, emb);
    k_attn_mma <<<dim3(16, Bd), 128, ATT_SMEM>>>();
    k_proj     <<<(Bd*Nd)/64, 128, PROJ_SMEM>>>(bo);
    k_pool     <<<Bd, 32>>>(Wf, bf, out);
}

// round 11
// speedup vs baseline: 3.1974x; 1.1684x over previous
#include <cuda_runtime.h>
#include <cuda_fp16.h>
#include <cstdint>
#include <cstddef>

#define CC   0.1f
#define SCc  0.31622776601683794f   /* sqrt(0.1) */
#define EPSc 1e-7f

#define Bd  64
#define Nd  1024
#define Dd  128
#define DX  129
#define NCd 10

// ---------------- warp-MMA / cp.async helpers (baseline PTX) ---------------
__device__ __forceinline__ uint32_t smem_u32(const void* p)
{
    uint32_t a;
    asm("{ .reg .u64 t; cvta.to.shared.u64 t, %1; cvt.u32.u64 %0, t; }"
        : "=r"(a) : "l"(p));
    return a;
}
__device__ __forceinline__ void ldsm4(uint32_t& r0, uint32_t& r1,
                                      uint32_t& r2, uint32_t& r3, uint32_t addr)
{
    asm volatile("ldmatrix.sync.aligned.m8n8.x4.shared.b16 {%0,%1,%2,%3}, [%4];"
                 : "=r"(r0), "=r"(r1), "=r"(r2), "=r"(r3) : "r"(addr));
}
__device__ __forceinline__ void ldsm4t(uint32_t& r0, uint32_t& r1,
                                       uint32_t& r2, uint32_t& r3, uint32_t addr)
{
    asm volatile("ldmatrix.sync.aligned.m8n8.x4.trans.shared.b16 {%0,%1,%2,%3}, [%4];"
                 : "=r"(r0), "=r"(r1), "=r"(r2), "=r"(r3) : "r"(addr));
}
__device__ __forceinline__ void mma16816(float* c, uint32_t a0, uint32_t a1,
                                         uint32_t a2, uint32_t a3,
                                         uint32_t b0, uint32_t b1)
{
    asm volatile("mma.sync.aligned.m16n8k16.row.col.f32.f16.f16.f32 "
                 "{%0,%1,%2,%3}, {%4,%5,%6,%7}, {%8,%9}, {%0,%1,%2,%3};"
                 : "+f"(c[0]), "+f"(c[1]), "+f"(c[2]), "+f"(c[3])
                 : "r"(a0), "r"(a1), "r"(a2), "r"(a3), "r"(b0), "r"(b1));
}
__device__ __forceinline__ void cpasync16(uint32_t dst, const void* src)
{
    asm volatile("cp.async.cg.shared.global [%0], [%1], 16;"
                 :: "r"(dst), "l"(src) : "memory");
}
__device__ __forceinline__ void cp_commit()
{
    asm volatile("cp.async.commit_group;" ::: "memory");
}
__device__ __forceinline__ void cp_wait_all()
{
    asm volatile("cp.async.wait_group 0;" ::: "memory");
}
__device__ __forceinline__ uint32_t packh(float a, float b)
{
    __half ha = __float2half_rn(a), hb = __float2half_rn(b);
    return (uint32_t)__half_as_ushort(ha) | ((uint32_t)__half_as_ushort(hb) << 16);
}

// ---------------- scratch (device globals; no runtime allocation) ----------
__device__ __align__(16) __half g_xh[(size_t)Bd*Nd*Dd];  // x spatial hi
__device__ __align__(16) __half g_xl[(size_t)Bd*Nd*Dd];  // x spatial lo
__device__ __align__(16) float  g_x0[(size_t)Bd*Nd];     // x time component
__device__ __align__(16) __half g_muh[(size_t)Bd*Nd*Dd]; // mu spatial hi
__device__ __align__(16) __half g_mul[(size_t)Bd*Nd*Dd]; // mu spatial lo
__device__ __align__(16) float  g_mu0[(size_t)Bd*Nd];    // mu time component
__device__ __align__(16) __half g_wh[(size_t)Dd*Dd];     // Wo spatial hi
__device__ __align__(16) __half g_wl[(size_t)Dd*Dd];     // Wo spatial lo
__device__ __align__(16) float  g_wo0[Dd];               // Wo[:,0]
__device__ __align__(16) float g_y [(size_t)Bd*Nd*Dd];   // Poincare tokens
__device__ __align__(16) float g_y2[(size_t)Bd*Nd];      // |y|^2 per token
__device__ __align__(16) unsigned char g_mask[(size_t)Bd*Nd];
__device__ int g_is32;

// ---------------- kernel 0a/0b: mask dtype detect + normalize --------------
__global__ void k_detect(const uint4* __restrict__ m)
{
    __shared__ int found;
    if (threadIdx.x == 0) found = 0;
    __syncthreads();
    unsigned int acc = 0;
    for (int i = threadIdx.x; i < Bd*Nd/16; i += blockDim.x) {
        uint4 v = m[i];
        acc |= (v.x | v.y | v.z | v.w) & 0xFFFFFF00u;
    }
    if (acc) atomicOr(&found, 1);
    __syncthreads();
    if (threadIdx.x == 0) g_is32 = found ? 0 : 1;
}
__global__ void k_masknorm(const void* __restrict__ m)
{
    int i = blockIdx.x * blockDim.x + threadIdx.x;
    if (i >= Bd*Nd) return;
    unsigned char v;
    if (g_is32) v = (((const int*)m)[i] != 0);
    else        v = (((const unsigned char*)m)[i] != 0);
    g_mask[i] = v;
}

// ---------------- kernel 0c: split Wo into fp16 hi/lo ----------------------
__global__ void k_wprep(const float* __restrict__ Wo)
{
    int idx = blockIdx.x * blockDim.x + threadIdx.x;
    if (idx >= Dd*Dd) return;
    int o = idx >> 7, k = idx & 127;
    float v = Wo[o*DX + (k+1)];
    __half h = __float2half_rn(v);
    g_wh[idx] = h;
    g_wl[idx] = __float2half_rn(v - __half2float(h));
    if (k == 0) g_wo0[o] = Wo[o*DX];
}

// ---------------- kernel 1: embedding + Lorentz expmap0 (fp16 split out) ---
__global__ void k_embed(const int* __restrict__ tok, const float* __restrict__ emb)
{
    int gw   = (blockIdx.x * blockDim.x + threadIdx.x) >> 5;
    int lane = threadIdx.x & 31;
    if (gw >= Bd*Nd) return;
    int t = tok[gw];
    float4 v = *(const float4*)(emb + (size_t)t*Dd + lane*4);
    float ss = v.x*v.x + v.y*v.y + v.z*v.z + v.w*v.w;
    #pragma unroll
    for (int o = 16; o; o >>= 1) ss += __shfl_xor_sync(0xffffffffu, ss, o);
    float nv   = fmaxf(sqrtf(ss), EPSc);
    float tt   = SCc * nv;
    float coef = sinhf(tt) / (SCc * nv);
    if (lane == 0) g_x0[gw] = coshf(tt) / SCc;

    float vv[4] = {coef*v.x, coef*v.y, coef*v.z, coef*v.w};
    uint32_t h01, h23, l01, l23;
    {
        __half h0 = __float2half_rn(vv[0]), h1 = __float2half_rn(vv[1]);
        __half h2 = __float2half_rn(vv[2]), h3 = __float2half_rn(vv[3]);
        h01 = (uint32_t)__half_as_ushort(h0) | ((uint32_t)__half_as_ushort(h1) << 16);
        h23 = (uint32_t)__half_as_ushort(h2) | ((uint32_t)__half_as_ushort(h3) << 16);
        l01 = packh(vv[0] - __half2float(h0), vv[1] - __half2float(h1));
        l23 = packh(vv[2] - __half2float(h2), vv[3] - __half2float(h3));
    }
    uint2* ph = (uint2*)(g_xh + (size_t)gw*Dd + lane*4);
    uint2* pl = (uint2*)(g_xl + (size_t)gw*Dd + lane*4);
    *ph = make_uint2(h01, h23);
    *pl = make_uint2(l01, l23);
}

// ---------------- kernel 2: attention via mma.sync, 64-query tiles ---------
// grid (16, 64); 128 threads = 4 warps x 16 query rows; 2 CTAs/SM.
#define STX 136
#define OXIH 0
#define OXIL 17408
#define OXJH0 34816
#define OXJL0 52224
#define OXJH1 69632
#define OXJL1 87040
#define OX0I 104448
#define OX0J0 104704
#define OX0J1 104960
#define OMS0 105216
#define OMS1 105280
#define ATT_SMEM 105344

__device__ __forceinline__ void prefetch_xj(uint32_t sb, int b, int jt, int buf, int tid)
{
    size_t rowbase = (size_t)b*Nd + (size_t)jt*64;
    uint32_t dH = sb + (buf ? OXJH1 : OXJH0);
    uint32_t dL = sb + (buf ? OXJL1 : OXJL0);
    #pragma unroll
    for (int c = 0; c < 8; c++) {
        int idx = tid + c*128;
        int row = idx >> 4, ch = idx & 15;
        cpasync16(dH + row*272 + ch*16, g_xh + (rowbase + row)*Dd + ch*8);
    }
    #pragma unroll
    for (int c = 0; c < 8; c++) {
        int idx = tid + c*128;
        int row = idx >> 4, ch = idx & 15;
        cpasync16(dL + row*272 + ch*16, g_xl + (rowbase + row)*Dd + ch*8);
    }
    if (tid < 16) cpasync16(sb + (buf ? OX0J1 : OX0J0) + tid*16, g_x0 + rowbase + tid*4);
    if (tid < 4)  cpasync16(sb + (buf ? OMS1 : OMS0) + tid*16, g_mask + rowbase + tid*16);
    cp_commit();
}

__global__ void __launch_bounds__(128, 2) k_attn_mma()
{
    extern __shared__ float4 smem_f4[];
    char* smb = (char*)smem_f4;
    const uint32_t sb = smem_u32(smb);

    const int tid  = threadIdx.x;
    const int wid  = tid >> 5;
    const int lane = tid & 31;
    const int b    = blockIdx.y;
    const int i0   = blockIdx.x * 64;
    const float invsq = 1.0f / sqrtf(129.0f);

    // ---- Xi tile (64 rows) + x0i via cp.async ----
    {
        size_t rowbase = (size_t)b*Nd + i0;
        #pragma unroll
        for (int c = 0; c < 8; c++) {
            int idx = tid + c*128;
            int row = idx >> 4, ch = idx & 15;
            cpasync16(sb + OXIH + row*272 + ch*16, g_xh + (rowbase + row)*Dd + ch*8);
        }
        #pragma unroll
        for (int c = 0; c < 8; c++) {
            int idx = tid + c*128;
            int row = idx >> 4, ch = idx & 15;
            cpasync16(sb + OXIL + row*272 + ch*16, g_xl + (rowbase + row)*Dd + ch*8);
        }
        if (tid < 16) cpasync16(sb + OX0I + tid*16, g_x0 + rowbase + tid*4);
    }
    prefetch_xj(sb, b, 0, 0, tid);

    const int r0 = wid*16 + (lane >> 2);
    const int cq = (lane & 3) * 2;

    const int la_row = lane & 15;
    const int la_kof = (lane >> 4) << 3;
    const int lb_n   = (lane & 7) + ((lane >> 4) << 3);
    const int lb_kof = ((lane >> 3) & 1) << 3;
    const int tr_row = (lane & 7) + (((lane >> 3) & 1) << 3);
    const int tr_col = (lane >> 4) << 3;

    const uint32_t aXiH = sb + OXIH + ((wid*16 + la_row)*STX + la_kof)*2;
    const uint32_t aXiL = sb + OXIL + ((wid*16 + la_row)*STX + la_kof)*2;

    float muc[16][4];
    #pragma unroll
    for (int f = 0; f < 16; f++)
        muc[f][0] = muc[f][1] = muc[f][2] = muc[f][3] = 0.f;
    float den0 = 0.f, den1 = 0.f, ac00 = 0.f, ac01 = 0.f;
    float xi0 = 0.f, xi1 = 0.f;

    int buf = 0;
    for (int jt = 0; jt < 16; jt++) {
        cp_wait_all();
        __syncthreads();
        if (jt == 0) {
            xi0 = ((float*)(smb + OX0I))[r0];
            xi1 = ((float*)(smb + OX0I))[r0 + 8];
        }
        if (jt + 1 < 16) prefetch_xj(sb, b, jt + 1, buf ^ 1, tid);

        const uint32_t oXjH = sb + (buf ? OXJH1 : OXJH0);
        const uint32_t oXjL = sb + (buf ? OXJL1 : OXJL0);
        const float*   x0j  = (const float*)(smb + (buf ? OX0J1 : OX0J0));
        const unsigned char* msb = (const unsigned char*)(smb + (buf ? OMS1 : OMS0));

        const uint32_t bXjH = oXjH + (lb_n*STX + lb_kof)*2;
        const uint32_t bXjL = oXjL + (lb_n*STX + lb_kof)*2;
        const uint32_t tXjH = oXjH + (tr_row*STX + tr_col)*2;
        const uint32_t tXjL = oXjL + (tr_row*STX + tr_col)*2;

        // ---- score MMAs: S[16 x 64], 3 split products ----
        float c[8][4];
        #pragma unroll
        for (int q = 0; q < 8; q++)
            c[q][0] = c[q][1] = c[q][2] = c[q][3] = 0.f;

        #pragma unroll
        for (int kk = 0; kk < 8; kk++) {
            uint32_t aH0, aH1, aH2, aH3, aL0, aL1, aL2, aL3;
            ldsm4(aH0, aH1, aH2, aH3, aXiH + kk*32);
            ldsm4(aL0, aL1, aL2, aL3, aXiL + kk*32);
            #pragma unroll
            for (int nb = 0; nb < 4; nb++) {
                uint32_t bH0, bH1, bH2, bH3, bL0, bL1, bL2, bL3;
                ldsm4(bH0, bH1, bH2, bH3, bXjH + nb*(16*STX*2) + kk*32);
                ldsm4(bL0, bL1, bL2, bL3, bXjL + nb*(16*STX*2) + kk*32);
                mma16816(c[nb*2],   aH0, aH1, aH2, aH3, bH0, bH1);
                mma16816(c[nb*2+1], aH0, aH1, aH2, aH3, bH2, bH3);
                mma16816(c[nb*2],   aH0, aH1, aH2, aH3, bL0, bL1);
                mma16816(c[nb*2+1], aH0, aH1, aH2, aH3, bL2, bL3);
                mma16816(c[nb*2],   aL0, aL1, aL2, aL3, bH0, bH1);
                mma16816(c[nb*2+1], aL0, aL1, aL2, aL3, bH2, bH3);
            }
        }

        // ---- epilogue in registers: e values -> mu A-fragments ----
        uint32_t eaH[4][4], eaL[4][4];
        #pragma unroll
        for (int q = 0; q < 8; q++) {
            int j0 = q*8 + cq;
            float xjx = x0j[j0], xjy = x0j[j0+1];
            float m0 = (float)msb[j0], m1 = (float)msb[j0+1];
            float e00 = m0 * __expf((xi0*xjx - c[q][0]) * invsq);
            float e01 = m1 * __expf((xi0*xjy - c[q][1]) * invsq);
            float e10 = m0 * __expf((xi1*xjx - c[q][2]) * invsq);
            float e11 = m1 * __expf((xi1*xjy - c[q][3]) * invsq);
            den0 += e00 + e01;  den1 += e10 + e11;
            ac00 += e00*xjx + e01*xjy;
            ac01 += e10*xjx + e11*xjy;
            __half h00 = __float2half_rn(e00), h01 = __float2half_rn(e01);
            __half h10 = __float2half_rn(e10), h11 = __float2half_rn(e11);
            uint32_t hp0 = (uint32_t)__half_as_ushort(h00) | ((uint32_t)__half_as_ushort(h01) << 16);
            uint32_t hp1 = (uint32_t)__half_as_ushort(h10) | ((uint32_t)__half_as_ushort(h11) << 16);
            uint32_t lp0 = packh(e00 - __half2float(h00), e01 - __half2float(h01));
            uint32_t lp1 = packh(e10 - __half2float(h10), e11 - __half2float(h11));
            int kk = q >> 1;
            if ((q & 1) == 0) {
                eaH[kk][0] = hp0; eaH[kk][1] = hp1;
                eaL[kk][0] = lp0; eaL[kk][1] = lp1;
            } else {
                eaH[kk][2] = hp0; eaH[kk][3] = hp1;
                eaL[kk][2] = lp0; eaL[kk][3] = lp1;
            }
        }

        // ---- mu MMAs: mu[16 x 128] += E[16x64] . Xj[64x128]; B via trans --
        #pragma unroll
        for (int kk = 0; kk < 4; kk++) {
            #pragma unroll
            for (int nb = 0; nb < 8; nb++) {
                uint32_t bH0, bH1, bH2, bH3, bL0, bL1, bL2, bL3;
                ldsm4t(bH0, bH1, bH2, bH3, tXjH + (kk*16*STX + nb*16)*2);
                ldsm4t(bL0, bL1, bL2, bL3, tXjL + (kk*16*STX + nb*16)*2);
                mma16816(muc[nb*2],   eaH[kk][0], eaH[kk][1], eaH[kk][2], eaH[kk][3], bH0, bH1);
                mma16816(muc[nb*2+1], eaH[kk][0], eaH[kk][1], eaH[kk][2], eaH[kk][3], bH2, bH3);
                mma16816(muc[nb*2],   eaH[kk][0], eaH[kk][1], eaH[kk][2], eaH[kk][3], bL0, bL1);
                mma16816(muc[nb*2+1], eaH[kk][0], eaH[kk][1], eaH[kk][2], eaH[kk][3], bL2, bL3);
                mma16816(muc[nb*2],   eaL[kk][0], eaL[kk][1], eaL[kk][2], eaL[kk][3], bH0, bH1);
                mma16816(muc[nb*2+1], eaL[kk][0], eaL[kk][1], eaL[kk][2], eaL[kk][3], bH2, bH3);
            }
        }
        buf ^= 1;
    }

    // ---- finalize: quad-reduce, Lorentz renorm, store mu as fp16 hi/lo ----
    #pragma unroll
    for (int o = 1; o < 4; o <<= 1) {
        den0 += __shfl_xor_sync(0xffffffffu, den0, o);
        den1 += __shfl_xor_sync(0xffffffffu, den1, o);
        ac00 += __shfl_xor_sync(0xffffffffu, ac00, o);
        ac01 += __shfl_xor_sync(0xffffffffu, ac01, o);
    }
    float id0 = 1.f / den0, id1 = 1.f / den1;
    float mu00 = ac00 * id0, mu01 = ac01 * id1;

    float in0 = 0.f, in1 = 0.f;
    #pragma unroll
    for (int f = 0; f < 16; f++) {
        muc[f][0] *= id0; muc[f][1] *= id0;
        muc[f][2] *= id1; muc[f][3] *= id1;
        in0 += muc[f][0]*muc[f][0] + muc[f][1]*muc[f][1];
        in1 += muc[f][2]*muc[f][2] + muc[f][3]*muc[f][3];
    }
    #pragma unroll
    for (int o = 1; o < 4; o <<= 1) {
        in0 += __shfl_xor_sync(0xffffffffu, in0, o);
        in1 += __shfl_xor_sync(0xffffffffu, in1, o);
    }
    float s20 = 1.f / (SCc * sqrtf(fmaxf(mu00*mu00 - in0, EPSc)));
    float s21 = 1.f / (SCc * sqrtf(fmaxf(mu01*mu01 - in1, EPSc)));

    size_t rg0 = (size_t)b*Nd + i0 + r0;
    size_t rg1 = rg0 + 8;
    if ((lane & 3) == 0) { g_mu0[rg0] = mu00 * s20; g_mu0[rg1] = mu01 * s21; }
    #pragma unroll
    for (int f = 0; f < 16; f++) {
        int d = f*8 + cq;
        float v00 = muc[f][0] * s20, v01 = muc[f][1] * s20;
        float v10 = muc[f][2] * s21, v11 = muc[f][3] * s21;
        __half h00 = __float2half_rn(v00), h01 = __float2half_rn(v01);
        __half h10 = __float2half_rn(v10), h11 = __float2half_rn(v11);
        *(uint32_t*)(g_muh + rg0*Dd + d) =
            (uint32_t)__half_as_ushort(h00) | ((uint32_t)__half_as_ushort(h01) << 16);
        *(uint32_t*)(g_muh + rg1*Dd + d) =
            (uint32_t)__half_as_ushort(h10) | ((uint32_t)__half_as_ushort(h11) << 16);
        *(uint32_t*)(g_mul + rg0*Dd + d) = packh(v00 - __half2float(h00), v01 - __half2float(h01));
        *(uint32_t*)(g_mul + rg1*Dd + d) = packh(v10 - __half2float(h10), v11 - __half2float(h11));
    }
}

// ---------------- kernel 3: projection via mma.sync + Poincare expmap0 -----
#define PAH 0
#define PAL 17408
#define PBH 34816
#define PBL 69632
#define PW0 104448
#define PBO 104960
#define PROJ_SMEM 105472

__global__ void __launch_bounds__(128, 2) k_proj(const float* __restrict__ bo)
{
    extern __shared__ float4 smem_f4[];
    char* smb = (char*)smem_f4;
    const uint32_t sb = smem_u32(smb);

    const int tid  = threadIdx.x;
    const int wid  = tid >> 5;
    const int lane = tid & 31;
    const size_t row0 = (size_t)blockIdx.x * 64;

    #pragma unroll
    for (int c = 0; c < 8; c++) {
        int idx = tid + c*128;
        int row = idx >> 4, ch = idx & 15;
        cpasync16(sb + PAH + row*272 + ch*16, g_muh + (row0 + row)*Dd + ch*8);
        cpasync16(sb + PAL + row*272 + ch*16, g_mul + (row0 + row)*Dd + ch*8);
    }
    #pragma unroll
    for (int c = 0; c < 16; c++) {
        int idx = tid + c*128;
        int row = idx >> 4, ch = idx & 15;
        cpasync16(sb + PBH + row*272 + ch*16, g_wh + (size_t)row*Dd + ch*8);
        cpasync16(sb + PBL + row*272 + ch*16, g_wl + (size_t)row*Dd + ch*8);
    }
    if (tid < 32) cpasync16(sb + PW0 + tid*16, g_wo0 + tid*4);
    else if (tid < 64) cpasync16(sb + PBO + (tid-32)*16, bo + (tid-32)*4);
    cp_commit();

    const int r0 = wid*16 + (lane >> 2);
    const int cq = (lane & 3) * 2;
    const int la_row = lane & 15;
    const int la_kof = (lane >> 4) << 3;
    const int lb_n   = (lane & 7) + ((lane >> 4) << 3);
    const int lb_kof = ((lane >> 3) & 1) << 3;

    const uint32_t aAH = sb + PAH + ((wid*16 + la_row)*STX + la_kof)*2;
    const uint32_t aAL = sb + PAL + ((wid*16 + la_row)*STX + la_kof)*2;
    const uint32_t bBH = sb + PBH + (lb_n*STX + lb_kof)*2;
    const uint32_t bBL = sb + PBL + (lb_n*STX + lb_kof)*2;

    cp_wait_all();
    __syncthreads();

    float c[16][4];
    #pragma unroll
    for (int q = 0; q < 16; q++)
        c[q][0] = c[q][1] = c[q][2] = c[q][3] = 0.f;

    #pragma unroll
    for (int kk = 0; kk < 8; kk++) {
        uint32_t aH0, aH1, aH2, aH3, aL0, aL1, aL2, aL3;
        ldsm4(aH0, aH1, aH2, aH3, aAH + kk*32);
        ldsm4(aL0, aL1, aL2, aL3, aAL + kk*32);
        #pragma unroll
        for (int nb = 0; nb < 8; nb++) {
            uint32_t bH0, bH1, bH2, bH3, bL0, bL1, bL2, bL3;
            ldsm4(bH0, bH1, bH2, bH3, bBH + nb*(16*STX*2) + kk*32);
            ldsm4(bL0, bL1, bL2, bL3, bBL + nb*(16*STX*2) + kk*32);
            mma16816(c[nb*2],   aH0, aH1, aH2, aH3, bH0, bH1);
            mma16816(c[nb*2+1], aH0, aH1, aH2, aH3, bH2, bH3);
            mma16816(c[nb*2],   aH0, aH1, aH2, aH3, bL0, bL1);
            mma16816(c[nb*2+1], aH0, aH1, aH2, aH3, bL2, bL3);
            mma16816(c[nb*2],   aL0, aL1, aL2, aL3, bH0, bH1);
            mma16816(c[nb*2+1], aL0, aL1, aL2, aL3, bH2, bH3);
        }
    }

    const float* wo0s = (const float*)(smb + PW0);
    const float* bos  = (const float*)(smb + PBO);
    float mu0a = g_mu0[row0 + r0];
    float mu0b = g_mu0[row0 + r0 + 8];

    float u[16][4];
    float pp0 = 0.f, pp1 = 0.f;
    #pragma unroll
    for (int q = 0; q < 16; q++) {
        int col = q*8 + cq;
        float w0 = wo0s[col], w1 = wo0s[col+1];
        float b0 = bos[col],  b1 = bos[col+1];
        u[q][0] = c[q][0] + mu0a*w0 + b0;
        u[q][1] = c[q][1] + mu0a*w1 + b1;
        u[q][2] = c[q][2] + mu0b*w0 + b0;
        u[q][3] = c[q][3] + mu0b*w1 + b1;
        pp0 += u[q][0]*u[q][0] + u[q][1]*u[q][1];
        pp1 += u[q][2]*u[q][2] + u[q][3]*u[q][3];
    }
    #pragma unroll
    for (int o = 1; o < 4; o <<= 1) {
        pp0 += __shfl_xor_sync(0xffffffffu, pp0, o);
        pp1 += __shfl_xor_sync(0xffffffffu, pp1, o);
    }
    float nu0 = fmaxf(sqrtf(pp0), EPSc);
    float nu1 = fmaxf(sqrtf(pp1), EPSc);
    float f0 = tanhf(SCc*nu0) / (SCc*nu0);
    float f1 = tanhf(SCc*nu1) / (SCc*nu1);

    float* y0 = g_y + (row0 + r0) * Dd;
    float* y1 = g_y + (row0 + r0 + 8) * Dd;
    float qq0 = 0.f, qq1 = 0.f;
    #pragma unroll
    for (int q = 0; q < 16; q++) {
        int col = q*8 + cq;
        float v00 = u[q][0]*f0, v01 = u[q][1]*f0;
        float v10 = u[q][2]*f1, v11 = u[q][3]*f1;
        *(float2*)(y0 + col) = make_float2(v00, v01);
        *(float2*)(y1 + col) = make_float2(v10, v11);
        qq0 += v00*v00 + v01*v01;
        qq1 += v10*v10 + v11*v11;
    }
    #pragma unroll
    for (int o = 1; o < 4; o <<= 1) {
        qq0 += __shfl_xor_sync(0xffffffffu, qq0, o);
        qq1 += __shfl_xor_sync(0xffffffffu, qq1, o);
    }
    if ((lane & 3) == 0) {
        g_y2[row0 + r0]     = qq0;
        g_y2[row0 + r0 + 8] = qq1;
    }
}

// ---------------- kernel 4: Mobius pooling + MLR head (deep prefetch) ------
// one warp per batch; chunks of 8 tokens, double-buffered register prefetch.
__global__ void k_pool(const float* __restrict__ Wf,
                       const float* __restrict__ bf,
                       float* __restrict__ out)
{
    const int b    = blockIdx.x;
    const int lane = threadIdx.x;
    const float* yb  = g_y  + (size_t)b*Nd*Dd;
    const float* y2b = g_y2 + (size_t)b*Nd;
    const unsigned char* mb = g_mask + (size_t)b*Nd;

    float a0=0.f, a1=0.f, a2=0.f, a3=0.f;
    int cnt = 0;

    float4 yB[2][8];
    float  y2B[2][8];
    unsigned long long mB[2];

    // load chunk 0 into buffer 0
    #pragma unroll
    for (int t = 0; t < 8; t++)
        yB[0][t] = *(const float4*)(yb + (size_t)t*Dd + lane*4);
    {
        float4 q0 = *(const float4*)(y2b + 0);
        float4 q1 = *(const float4*)(y2b + 4);
        y2B[0][0]=q0.x; y2B[0][1]=q0.y; y2B[0][2]=q0.z; y2B[0][3]=q0.w;
        y2B[0][4]=q1.x; y2B[0][5]=q1.y; y2B[0][6]=q1.z; y2B[0][7]=q1.w;
        mB[0] = *(const unsigned long long*)(mb);
    }

    int cur = 0;
    for (int ch = 0; ch < Nd/8; ch++) {
        int nxt = cur ^ 1;
        if (ch + 1 < Nd/8) {
            const float* ybn = yb + (size_t)(ch+1)*8*Dd;
            #pragma unroll
            for (int t = 0; t < 8; t++)
                yB[nxt][t] = *(const float4*)(ybn + (size_t)t*Dd + lane*4);
            float4 q0 = *(const float4*)(y2b + (ch+1)*8);
            float4 q1 = *(const float4*)(y2b + (ch+1)*8 + 4);
            y2B[nxt][0]=q0.x; y2B[nxt][1]=q0.y; y2B[nxt][2]=q0.z; y2B[nxt][3]=q0.w;
            y2B[nxt][4]=q1.x; y2B[nxt][5]=q1.y; y2B[nxt][6]=q1.z; y2B[nxt][7]=q1.w;
            mB[nxt] = *(const unsigned long long*)(mb + (ch+1)*8);
        }
        unsigned long long m8 = mB[cur];
        #pragma unroll
        for (int t = 0; t < 8; t++) {
            if ((m8 >> (t*8)) & 0xFFull) {
                float4 yv = yB[cur][t];
                float yy2 = y2B[cur][t];
                float xy = a0*yv.x + a1*yv.y + a2*yv.z + a3*yv.w;
                float x2 = a0*a0 + a1*a1 + a2*a2 + a3*a3;
                #pragma unroll
                for (int o = 16; o; o >>= 1) {
                    xy += __shfl_xor_sync(0xffffffffu, xy, o);
                    x2 += __shfl_xor_sync(0xffffffffu, x2, o);
                }
                float aa  = 1.f + 2.f*CC*xy + CC*yy2;
                float bb  = 1.f - CC*x2;
                float den = fmaxf(1.f + 2.f*CC*xy + CC*CC*x2*yy2, 1e-12f);
                a0 = (aa*a0 + bb*yv.x) / den;
                a1 = (aa*a1 + bb*yv.y) / den;
                a2 = (aa*a2 + bb*yv.z) / den;
                a3 = (aa*a3 + bb*yv.w) / den;
                cnt++;
            }
        }
        cur = nxt;
    }

    // mobius scalar-mul by 1/cnt
    float n2 = a0*a0 + a1*a1 + a2*a2 + a3*a3;
    #pragma unroll
    for (int o = 16; o; o >>= 1) n2 += __shfl_xor_sync(0xffffffffu, n2, o);
    float nrm = sqrtf(n2);
    float t   = fminf(fmaxf(SCc*nrm, EPSc), 1.f - 1e-6f);
    float r   = 1.f / fmaxf((float)cnt, 1.f);
    float fac = tanhf(r * atanhf(t)) / fmaxf(SCc*nrm, EPSc);
    float p0 = fac*a0, p1 = fac*a1, p2 = fac*a2, p3 = fac*a3;
    if (cnt == 0) {
        float4 y0 = *(const float4*)(yb + lane*4);
        p0 = y0.x; p1 = y0.y; p2 = y0.z; p3 = y0.w;
    }

    // logmap0
    float pn2 = p0*p0 + p1*p1 + p2*p2 + p3*p3;
    #pragma unroll
    for (int o = 16; o; o >>= 1) pn2 += __shfl_xor_sync(0xffffffffu, pn2, o);
    float npn = fmaxf(sqrtf(pn2), EPSc);
    float t2  = fminf(fmaxf(SCc*npn, EPSc), 1.f - 1e-6f);
    float cf  = atanhf(t2) / (SCc*npn);
    float v0 = cf*p0, v1 = cf*p1, v2 = cf*p2, v3 = cf*p3;

    // logits
    for (int k = 0; k < NCd; k++) {
        float4 w = *(const float4*)(Wf + (size_t)k*Dd + lane*4);
        float pr = v0*w.x + v1*w.y + v2*w.z + v3*w.w;
        #pragma unroll
        for (int o = 16; o; o >>= 1) pr += __shfl_xor_sync(0xffffffffu, pr, o);
        if (lane == 0) out[b*NCd + k] = pr + bf[k];
    }
}

// ---------------------------- launcher -------------------------------------
extern "C" void kernel_launch(void* const* d_in, const int* in_sizes, int n_in,
                              void* d_out, int out_size)
{
    (void)in_sizes; (void)n_in; (void)out_size;
    const int*   tok  = (const int*)d_in[0];
    const void*  mask = d_in[1];
    const float* emb  = (const float*)d_in[2];
    const float* Wo   = (const float*)d_in[3];
    const float* bo   = (const float*)d_in[4];
    const float* Wf   = (const float*)d_in[5];
    const float* bf   = (const float*)d_in[6];
    float*       out  = (float*)d_out;

    cudaFuncSetAttribute(k_attn_mma, cudaFuncAttributeMaxDynamicSharedMemorySize, ATT_SMEM);
    cudaFuncSetAttribute(k_proj,     cudaFuncAttributeMaxDynamicSharedMemorySize, PROJ_SMEM);

    k_detect   <<<1, 1024>>>((const uint4*)mask);
    k_masknorm <<<(Bd*Nd + 255)/256, 256>>>(mask);
    k_wprep    <<<(Dd*Dd + 255)/256, 256>>>(Wo);
    k_embed    <<<(Bd*Nd)/8, 256>>>(tok, emb);
    k_attn_mma <<<dim3(16, Bd), 128, ATT_SMEM>>>();
    k_proj     <<<(Bd*Nd)/64, 128, PROJ_SMEM>>>(bo);
    k_pool     <<<Bd, 32>>>(Wf, bf, out);
}

// round 12
// speedup vs baseline: 3.2908x; 1.0292x over previous
#include <cuda_runtime.h>
#include <cuda_fp16.h>
#include <cstdint>
#include <cstddef>

#define CC   0.1f
#define SCc  0.31622776601683794f   /* sqrt(0.1) */
#define EPSc 1e-7f

#define Bd  64
#define Nd  1024
#define Dd  128
#define DX  129
#define NCd 10

// ---------------- warp-MMA / cp.async helpers (baseline PTX) ---------------
__device__ __forceinline__ uint32_t smem_u32(const void* p)
{
    uint32_t a;
    asm("{ .reg .u64 t; cvta.to.shared.u64 t, %1; cvt.u32.u64 %0, t; }"
        : "=r"(a) : "l"(p));
    return a;
}
__device__ __forceinline__ void ldsm4(uint32_t& r0, uint32_t& r1,
                                      uint32_t& r2, uint32_t& r3, uint32_t addr)
{
    asm volatile("ldmatrix.sync.aligned.m8n8.x4.shared.b16 {%0,%1,%2,%3}, [%4];"
                 : "=r"(r0), "=r"(r1), "=r"(r2), "=r"(r3) : "r"(addr));
}
__device__ __forceinline__ void ldsm4t(uint32_t& r0, uint32_t& r1,
                                       uint32_t& r2, uint32_t& r3, uint32_t addr)
{
    asm volatile("ldmatrix.sync.aligned.m8n8.x4.trans.shared.b16 {%0,%1,%2,%3}, [%4];"
                 : "=r"(r0), "=r"(r1), "=r"(r2), "=r"(r3) : "r"(addr));
}
__device__ __forceinline__ void mma16816(float* c, uint32_t a0, uint32_t a1,
                                         uint32_t a2, uint32_t a3,
                                         uint32_t b0, uint32_t b1)
{
    asm volatile("mma.sync.aligned.m16n8k16.row.col.f32.f16.f16.f32 "
                 "{%0,%1,%2,%3}, {%4,%5,%6,%7}, {%8,%9}, {%0,%1,%2,%3};"
                 : "+f"(c[0]), "+f"(c[1]), "+f"(c[2]), "+f"(c[3])
                 : "r"(a0), "r"(a1), "r"(a2), "r"(a3), "r"(b0), "r"(b1));
}
__device__ __forceinline__ void cpasync16(uint32_t dst, const void* src)
{
    asm volatile("cp.async.cg.shared.global [%0], [%1], 16;"
                 :: "r"(dst), "l"(src) : "memory");
}
__device__ __forceinline__ void cp_commit()
{
    asm volatile("cp.async.commit_group;" ::: "memory");
}
__device__ __forceinline__ void cp_wait_all()
{
    asm volatile("cp.async.wait_group 0;" ::: "memory");
}
__device__ __forceinline__ uint32_t packh(float a, float b)
{
    __half ha = __float2half_rn(a), hb = __float2half_rn(b);
    return (uint32_t)__half_as_ushort(ha) | ((uint32_t)__half_as_ushort(hb) << 16);
}

// ---------------- scratch (device globals; no runtime allocation) ----------
__device__ __align__(16) __half g_xh[(size_t)Bd*Nd*Dd];  // x spatial hi
__device__ __align__(16) __half g_xl[(size_t)Bd*Nd*Dd];  // x spatial lo
__device__ __align__(16) float  g_x0[(size_t)Bd*Nd];     // x time component
__device__ __align__(16) __half g_wh[(size_t)Dd*Dd];     // Wo spatial hi
__device__ __align__(16) __half g_wl[(size_t)Dd*Dd];     // Wo spatial lo
__device__ __align__(16) float  g_wo0[Dd];               // Wo[:,0]
__device__ __align__(16) float g_y [(size_t)Bd*Nd*Dd];   // Poincare tokens
__device__ __align__(16) float g_y2[(size_t)Bd*Nd];      // |y|^2 per token
__device__ __align__(16) unsigned char g_mask[(size_t)Bd*Nd];
__device__ int g_is32;

// ---------------- kernel 0a/0b: mask dtype detect + normalize --------------
__global__ void k_detect(const uint4* __restrict__ m)
{
    __shared__ int found;
    if (threadIdx.x == 0) found = 0;
    __syncthreads();
    unsigned int acc = 0;
    for (int i = threadIdx.x; i < Bd*Nd/16; i += blockDim.x) {
        uint4 v = m[i];
        acc |= (v.x | v.y | v.z | v.w) & 0xFFFFFF00u;
    }
    if (acc) atomicOr(&found, 1);
    __syncthreads();
    if (threadIdx.x == 0) g_is32 = found ? 0 : 1;
}
__global__ void k_masknorm(const void* __restrict__ m)
{
    int i = blockIdx.x * blockDim.x + threadIdx.x;
    if (i >= Bd*Nd) return;
    unsigned char v;
    if (g_is32) v = (((const int*)m)[i] != 0);
    else        v = (((const unsigned char*)m)[i] != 0);
    g_mask[i] = v;
}

// ---------------- kernel 0c: split Wo into fp16 hi/lo ----------------------
__global__ void k_wprep(const float* __restrict__ Wo)
{
    int idx = blockIdx.x * blockDim.x + threadIdx.x;
    if (idx >= Dd*Dd) return;
    int o = idx >> 7, k = idx & 127;
    float v = Wo[o*DX + (k+1)];
    __half h = __float2half_rn(v);
    g_wh[idx] = h;
    g_wl[idx] = __float2half_rn(v - __half2float(h));
    if (k == 0) g_wo0[o] = Wo[o*DX];
}

// ---------------- kernel 1: embedding + Lorentz expmap0 (fp16 split out) ---
__global__ void k_embed(const int* __restrict__ tok, const float* __restrict__ emb)
{
    int gw   = (blockIdx.x * blockDim.x + threadIdx.x) >> 5;
    int lane = threadIdx.x & 31;
    if (gw >= Bd*Nd) return;
    int t = tok[gw];
    float4 v = *(const float4*)(emb + (size_t)t*Dd + lane*4);
    float ss = v.x*v.x + v.y*v.y + v.z*v.z + v.w*v.w;
    #pragma unroll
    for (int o = 16; o; o >>= 1) ss += __shfl_xor_sync(0xffffffffu, ss, o);
    float nv   = fmaxf(sqrtf(ss), EPSc);
    float tt   = SCc * nv;
    float coef = sinhf(tt) / (SCc * nv);
    if (lane == 0) g_x0[gw] = coshf(tt) / SCc;

    float vv[4] = {coef*v.x, coef*v.y, coef*v.z, coef*v.w};
    uint32_t h01, h23, l01, l23;
    {
        __half h0 = __float2half_rn(vv[0]), h1 = __float2half_rn(vv[1]);
        __half h2 = __float2half_rn(vv[2]), h3 = __float2half_rn(vv[3]);
        h01 = (uint32_t)__half_as_ushort(h0) | ((uint32_t)__half_as_ushort(h1) << 16);
        h23 = (uint32_t)__half_as_ushort(h2) | ((uint32_t)__half_as_ushort(h3) << 16);
        l01 = packh(vv[0] - __half2float(h0), vv[1] - __half2float(h1));
        l23 = packh(vv[2] - __half2float(h2), vv[3] - __half2float(h3));
    }
    uint2* ph = (uint2*)(g_xh + (size_t)gw*Dd + lane*4);
    uint2* pl = (uint2*)(g_xl + (size_t)gw*Dd + lane*4);
    *ph = make_uint2(h01, h23);
    *pl = make_uint2(l01, l23);
}

// ---------------- kernel 2: attention + FUSED projection via mma.sync ------
// grid (16, 64); 128 threads = 4 warps x 16 query rows; 2 CTAs/SM.
// After the j-loop, Wo hi/lo stream into the dead Xj buffers and the
// normalized mu C-fragments become A-fragments for the projection GEMM.
#define STX 136
#define OXIH 0
#define OXIL 17408
#define OXJH0 34816
#define OXJL0 52224
#define OXJH1 69632
#define OXJL1 87040
#define OX0I 104448
#define OX0J0 104704
#define OX0J1 104960
#define OMS0 105216
#define OMS1 105280
#define OWO0 105344
#define OBO  105856
#define ATT_SMEM 106368

__device__ __forceinline__ void prefetch_xj(uint32_t sb, int b, int jt, int buf, int tid)
{
    size_t rowbase = (size_t)b*Nd + (size_t)jt*64;
    uint32_t dH = sb + (buf ? OXJH1 : OXJH0);
    uint32_t dL = sb + (buf ? OXJL1 : OXJL0);
    #pragma unroll
    for (int c = 0; c < 8; c++) {
        int idx = tid + c*128;
        int row = idx >> 4, ch = idx & 15;
        cpasync16(dH + row*272 + ch*16, g_xh + (rowbase + row)*Dd + ch*8);
    }
    #pragma unroll
    for (int c = 0; c < 8; c++) {
        int idx = tid + c*128;
        int row = idx >> 4, ch = idx & 15;
        cpasync16(dL + row*272 + ch*16, g_xl + (rowbase + row)*Dd + ch*8);
    }
    if (tid < 16) cpasync16(sb + (buf ? OX0J1 : OX0J0) + tid*16, g_x0 + rowbase + tid*4);
    if (tid < 4)  cpasync16(sb + (buf ? OMS1 : OMS0) + tid*16, g_mask + rowbase + tid*16);
    cp_commit();
}

__global__ void __launch_bounds__(128, 2) k_attn_mma(const float* __restrict__ bo)
{
    extern __shared__ float4 smem_f4[];
    char* smb = (char*)smem_f4;
    const uint32_t sb = smem_u32(smb);

    const int tid  = threadIdx.x;
    const int wid  = tid >> 5;
    const int lane = tid & 31;
    const int b    = blockIdx.y;
    const int i0   = blockIdx.x * 64;
    const float invsq = 1.0f / sqrtf(129.0f);

    // ---- Xi tile (64 rows) + x0i + wo0 + bo via cp.async ----
    {
        size_t rowbase = (size_t)b*Nd + i0;
        #pragma unroll
        for (int c = 0; c < 8; c++) {
            int idx = tid + c*128;
            int row = idx >> 4, ch = idx & 15;
            cpasync16(sb + OXIH + row*272 + ch*16, g_xh + (rowbase + row)*Dd + ch*8);
        }
        #pragma unroll
        for (int c = 0; c < 8; c++) {
            int idx = tid + c*128;
            int row = idx >> 4, ch = idx & 15;
            cpasync16(sb + OXIL + row*272 + ch*16, g_xl + (rowbase + row)*Dd + ch*8);
        }
        if (tid < 16)      cpasync16(sb + OX0I + tid*16, g_x0 + rowbase + tid*4);
        else if (tid < 48) cpasync16(sb + OWO0 + (tid-16)*16, g_wo0 + (tid-16)*4);
        else if (tid < 80) cpasync16(sb + OBO + (tid-48)*16, bo + (tid-48)*4);
    }
    prefetch_xj(sb, b, 0, 0, tid);

    const int r0 = wid*16 + (lane >> 2);
    const int cq = (lane & 3) * 2;

    const int la_row = lane & 15;
    const int la_kof = (lane >> 4) << 3;
    const int lb_n   = (lane & 7) + ((lane >> 4) << 3);
    const int lb_kof = ((lane >> 3) & 1) << 3;
    const int tr_row = (lane & 7) + (((lane >> 3) & 1) << 3);
    const int tr_col = (lane >> 4) << 3;

    const uint32_t aXiH = sb + OXIH + ((wid*16 + la_row)*STX + la_kof)*2;
    const uint32_t aXiL = sb + OXIL + ((wid*16 + la_row)*STX + la_kof)*2;

    float muc[16][4];
    #pragma unroll
    for (int f = 0; f < 16; f++)
        muc[f][0] = muc[f][1] = muc[f][2] = muc[f][3] = 0.f;
    float den0 = 0.f, den1 = 0.f, ac00 = 0.f, ac01 = 0.f;
    float xi0 = 0.f, xi1 = 0.f;

    int buf = 0;
    for (int jt = 0; jt < 16; jt++) {
        cp_wait_all();
        __syncthreads();
        if (jt == 0) {
            xi0 = ((float*)(smb + OX0I))[r0];
            xi1 = ((float*)(smb + OX0I))[r0 + 8];
        }
        if (jt + 1 < 16) prefetch_xj(sb, b, jt + 1, buf ^ 1, tid);

        const uint32_t oXjH = sb + (buf ? OXJH1 : OXJH0);
        const uint32_t oXjL = sb + (buf ? OXJL1 : OXJL0);
        const float*   x0j  = (const float*)(smb + (buf ? OX0J1 : OX0J0));
        const unsigned char* msb = (const unsigned char*)(smb + (buf ? OMS1 : OMS0));

        const uint32_t bXjH = oXjH + (lb_n*STX + lb_kof)*2;
        const uint32_t bXjL = oXjL + (lb_n*STX + lb_kof)*2;
        const uint32_t tXjH = oXjH + (tr_row*STX + tr_col)*2;
        const uint32_t tXjL = oXjL + (tr_row*STX + tr_col)*2;

        // ---- score MMAs: S[16 x 64], 3 split products ----
        float c[8][4];
        #pragma unroll
        for (int q = 0; q < 8; q++)
            c[q][0] = c[q][1] = c[q][2] = c[q][3] = 0.f;

        #pragma unroll
        for (int kk = 0; kk < 8; kk++) {
            uint32_t aH0, aH1, aH2, aH3, aL0, aL1, aL2, aL3;
            ldsm4(aH0, aH1, aH2, aH3, aXiH + kk*32);
            ldsm4(aL0, aL1, aL2, aL3, aXiL + kk*32);
            #pragma unroll
            for (int nb = 0; nb < 4; nb++) {
                uint32_t bH0, bH1, bH2, bH3, bL0, bL1, bL2, bL3;
                ldsm4(bH0, bH1, bH2, bH3, bXjH + nb*(16*STX*2) + kk*32);
                ldsm4(bL0, bL1, bL2, bL3, bXjL + nb*(16*STX*2) + kk*32);
                mma16816(c[nb*2],   aH0, aH1, aH2, aH3, bH0, bH1);
                mma16816(c[nb*2+1], aH0, aH1, aH2, aH3, bH2, bH3);
                mma16816(c[nb*2],   aH0, aH1, aH2, aH3, bL0, bL1);
                mma16816(c[nb*2+1], aH0, aH1, aH2, aH3, bL2, bL3);
                mma16816(c[nb*2],   aL0, aL1, aL2, aL3, bH0, bH1);
                mma16816(c[nb*2+1], aL0, aL1, aL2, aL3, bH2, bH3);
            }
        }

        // ---- epilogue in registers: e values -> mu A-fragments ----
        uint32_t eaH[4][4], eaL[4][4];
        #pragma unroll
        for (int q = 0; q < 8; q++) {
            int j0 = q*8 + cq;
            float xjx = x0j[j0], xjy = x0j[j0+1];
            float m0 = (float)msb[j0], m1 = (float)msb[j0+1];
            float e00 = m0 * __expf((xi0*xjx - c[q][0]) * invsq);
            float e01 = m1 * __expf((xi0*xjy - c[q][1]) * invsq);
            float e10 = m0 * __expf((xi1*xjx - c[q][2]) * invsq);
            float e11 = m1 * __expf((xi1*xjy - c[q][3]) * invsq);
            den0 += e00 + e01;  den1 += e10 + e11;
            ac00 += e00*xjx + e01*xjy;
            ac01 += e10*xjx + e11*xjy;
            __half h00 = __float2half_rn(e00), h01 = __float2half_rn(e01);
            __half h10 = __float2half_rn(e10), h11 = __float2half_rn(e11);
            uint32_t hp0 = (uint32_t)__half_as_ushort(h00) | ((uint32_t)__half_as_ushort(h01) << 16);
            uint32_t hp1 = (uint32_t)__half_as_ushort(h10) | ((uint32_t)__half_as_ushort(h11) << 16);
            uint32_t lp0 = packh(e00 - __half2float(h00), e01 - __half2float(h01));
            uint32_t lp1 = packh(e10 - __half2float(h10), e11 - __half2float(h11));
            int kk = q >> 1;
            if ((q & 1) == 0) {
                eaH[kk][0] = hp0; eaH[kk][1] = hp1;
                eaL[kk][0] = lp0; eaL[kk][1] = lp1;
            } else {
                eaH[kk][2] = hp0; eaH[kk][3] = hp1;
                eaL[kk][2] = lp0; eaL[kk][3] = lp1;
            }
        }

        // ---- mu MMAs: mu[16 x 128] += E[16x64] . Xj[64x128]; B via trans --
        #pragma unroll
        for (int kk = 0; kk < 4; kk++) {
            #pragma unroll
            for (int nb = 0; nb < 8; nb++) {
                uint32_t bH0, bH1, bH2, bH3, bL0, bL1, bL2, bL3;
                ldsm4t(bH0, bH1, bH2, bH3, tXjH + (kk*16*STX + nb*16)*2);
                ldsm4t(bL0, bL1, bL2, bL3, tXjL + (kk*16*STX + nb*16)*2);
                mma16816(muc[nb*2],   eaH[kk][0], eaH[kk][1], eaH[kk][2], eaH[kk][3], bH0, bH1);
                mma16816(muc[nb*2+1], eaH[kk][0], eaH[kk][1], eaH[kk][2], eaH[kk][3], bH2, bH3);
                mma16816(muc[nb*2],   eaH[kk][0], eaH[kk][1], eaH[kk][2], eaH[kk][3], bL0, bL1);
                mma16816(muc[nb*2+1], eaH[kk][0], eaH[kk][1], eaH[kk][2], eaH[kk][3], bL2, bL3);
                mma16816(muc[nb*2],   eaL[kk][0], eaL[kk][1], eaL[kk][2], eaL[kk][3], bH0, bH1);
                mma16816(muc[nb*2+1], eaL[kk][0], eaL[kk][1], eaL[kk][2], eaL[kk][3], bH2, bH3);
            }
        }
        buf ^= 1;
    }

    // ---- finalize: quad-reduce, Lorentz renorm (registers only) ----
    #pragma unroll
    for (int o = 1; o < 4; o <<= 1) {
        den0 += __shfl_xor_sync(0xffffffffu, den0, o);
        den1 += __shfl_xor_sync(0xffffffffu, den1, o);
        ac00 += __shfl_xor_sync(0xffffffffu, ac00, o);
        ac01 += __shfl_xor_sync(0xffffffffu, ac01, o);
    }
    float id0 = 1.f / den0, id1 = 1.f / den1;
    float mu00 = ac00 * id0, mu01 = ac01 * id1;

    float in0 = 0.f, in1 = 0.f;
    #pragma unroll
    for (int f = 0; f < 16; f++) {
        muc[f][0] *= id0; muc[f][1] *= id0;
        muc[f][2] *= id1; muc[f][3] *= id1;
        in0 += muc[f][0]*muc[f][0] + muc[f][1]*muc[f][1];
        in1 += muc[f][2]*muc[f][2] + muc[f][3]*muc[f][3];
    }
    #pragma unroll
    for (int o = 1; o < 4; o <<= 1) {
        in0 += __shfl_xor_sync(0xffffffffu, in0, o);
        in1 += __shfl_xor_sync(0xffffffffu, in1, o);
    }
    float s20 = 1.f / (SCc * sqrtf(fmaxf(mu00*mu00 - in0, EPSc)));
    float s21 = 1.f / (SCc * sqrtf(fmaxf(mu01*mu01 - in1, EPSc)));
    float mu0a = mu00 * s20, mu0b = mu01 * s21;

    // ---- all warps done with Xj smem; stream Wo hi/lo into dead buffers ----
    __syncthreads();
    #pragma unroll
    for (int c = 0; c < 16; c++) {
        int idx = tid + c*128;
        int row = idx >> 4, ch = idx & 15;
        cpasync16(sb + OXJH0 + row*272 + ch*16, g_wh + (size_t)row*Dd + ch*8);
    }
    #pragma unroll
    for (int c = 0; c < 16; c++) {
        int idx = tid + c*128;
        int row = idx >> 4, ch = idx & 15;
        cpasync16(sb + OXJH1 + row*272 + ch*16, g_wl + (size_t)row*Dd + ch*8);
    }
    cp_commit();

    // ---- scale mu and split to fp16 hi/lo A-fragments (overlaps loads) ----
    #pragma unroll
    for (int f = 0; f < 16; f++) {
        muc[f][0] *= s20; muc[f][1] *= s20;
        muc[f][2] *= s21; muc[f][3] *= s21;
    }
    uint32_t mAH[8][4], mAL[8][4];
    #pragma unroll
    for (int kk = 0; kk < 8; kk++) {
        #pragma unroll
        for (int g = 0; g < 2; g++) {
            int f = 2*kk + g;
            __half h0 = __float2half_rn(muc[f][0]), h1 = __float2half_rn(muc[f][1]);
            __half h2 = __float2half_rn(muc[f][2]), h3 = __float2half_rn(muc[f][3]);
            mAH[kk][2*g+0] = (uint32_t)__half_as_ushort(h0) | ((uint32_t)__half_as_ushort(h1) << 16);
            mAH[kk][2*g+1] = (uint32_t)__half_as_ushort(h2) | ((uint32_t)__half_as_ushort(h3) << 16);
            mAL[kk][2*g+0] = packh(muc[f][0] - __half2float(h0), muc[f][1] - __half2float(h1));
            mAL[kk][2*g+1] = packh(muc[f][2] - __half2float(h2), muc[f][3] - __half2float(h3));
        }
    }

    cp_wait_all();
    __syncthreads();

    // ---- projection MMAs: u[16 x 128] = mu_spatial . Wo_spatial^T ----
    const uint32_t bWH = sb + OXJH0 + (lb_n*STX + lb_kof)*2;
    const uint32_t bWL = sb + OXJH1 + (lb_n*STX + lb_kof)*2;

    float c2[16][4];
    #pragma unroll
    for (int q = 0; q < 16; q++)
        c2[q][0] = c2[q][1] = c2[q][2] = c2[q][3] = 0.f;

    #pragma unroll
    for (int kk = 0; kk < 8; kk++) {
        #pragma unroll
        for (int nb = 0; nb < 8; nb++) {
            uint32_t bH0, bH1, bH2, bH3, bL0, bL1, bL2, bL3;
            ldsm4(bH0, bH1, bH2, bH3, bWH + nb*(16*STX*2) + kk*32);
            ldsm4(bL0, bL1, bL2, bL3, bWL + nb*(16*STX*2) + kk*32);
            mma16816(c2[nb*2],   mAH[kk][0], mAH[kk][1], mAH[kk][2], mAH[kk][3], bH0, bH1);
            mma16816(c2[nb*2+1], mAH[kk][0], mAH[kk][1], mAH[kk][2], mAH[kk][3], bH2, bH3);
            mma16816(c2[nb*2],   mAH[kk][0], mAH[kk][1], mAH[kk][2], mAH[kk][3], bL0, bL1);
            mma16816(c2[nb*2+1], mAH[kk][0], mAH[kk][1], mAH[kk][2], mAH[kk][3], bL2, bL3);
            mma16816(c2[nb*2],   mAL[kk][0], mAL[kk][1], mAL[kk][2], mAL[kk][3], bH0, bH1);
            mma16816(c2[nb*2+1], mAL[kk][0], mAL[kk][1], mAL[kk][2], mAL[kk][3], bH2, bH3);
        }
    }

    // ---- epilogue: +mu0*Wo0 + bo, norm, tanh scale, write y/y2 ----
    const float* wo0s = (const float*)(smb + OWO0);
    const float* bos  = (const float*)(smb + OBO);

    float u[16][4];
    float pp0 = 0.f, pp1 = 0.f;
    #pragma unroll
    for (int q = 0; q < 16; q++) {
        int col = q*8 + cq;
        float w0 = wo0s[col], w1 = wo0s[col+1];
        float b0 = bos[col],  b1 = bos[col+1];
        u[q][0] = c2[q][0] + mu0a*w0 + b0;
        u[q][1] = c2[q][1] + mu0a*w1 + b1;
        u[q][2] = c2[q][2] + mu0b*w0 + b0;
        u[q][3] = c2[q][3] + mu0b*w1 + b1;
        pp0 += u[q][0]*u[q][0] + u[q][1]*u[q][1];
        pp1 += u[q][2]*u[q][2] + u[q][3]*u[q][3];
    }
    #pragma unroll
    for (int o = 1; o < 4; o <<= 1) {
        pp0 += __shfl_xor_sync(0xffffffffu, pp0, o);
        pp1 += __shfl_xor_sync(0xffffffffu, pp1, o);
    }
    float nu0 = fmaxf(sqrtf(pp0), EPSc);
    float nu1 = fmaxf(sqrtf(pp1), EPSc);
    float f0 = tanhf(SCc*nu0) / (SCc*nu0);
    float f1 = tanhf(SCc*nu1) / (SCc*nu1);

    float* y0 = g_y + ((size_t)b*Nd + i0 + r0) * Dd;
    float* y1 = y0 + (size_t)8 * Dd;
    float qq0 = 0.f, qq1 = 0.f;
    #pragma unroll
    for (int q = 0; q < 16; q++) {
        int col = q*8 + cq;
        float v00 = u[q][0]*f0, v01 = u[q][1]*f0;
        float v10 = u[q][2]*f1, v11 = u[q][3]*f1;
        *(float2*)(y0 + col) = make_float2(v00, v01);
        *(float2*)(y1 + col) = make_float2(v10, v11);
        qq0 += v00*v00 + v01*v01;
        qq1 += v10*v10 + v11*v11;
    }
    #pragma unroll
    for (int o = 1; o < 4; o <<= 1) {
        qq0 += __shfl_xor_sync(0xffffffffu, qq0, o);
        qq1 += __shfl_xor_sync(0xffffffffu, qq1, o);
    }
    if ((lane & 3) == 0) {
        g_y2[(size_t)b*Nd + i0 + r0]     = qq0;
        g_y2[(size_t)b*Nd + i0 + r0 + 8] = qq1;
    }
}

// ---------------- kernel 4: Mobius pooling + MLR head (deep prefetch) ------
__global__ void k_pool(const float* __restrict__ Wf,
                       const float* __restrict__ bf,
                       float* __restrict__ out)
{
    const int b    = blockIdx.x;
    const int lane = threadIdx.x;
    const float* yb  = g_y  + (size_t)b*Nd*Dd;
    const float* y2b = g_y2 + (size_t)b*Nd;
    const unsigned char* mb = g_mask + (size_t)b*Nd;

    float a0=0.f, a1=0.f, a2=0.f, a3=0.f;
    int cnt = 0;

    float4 yB[2][8];
    float  y2B[2][8];
    unsigned long long mB[2];

    #pragma unroll
    for (int t = 0; t < 8; t++)
        yB[0][t] = *(const float4*)(yb + (size_t)t*Dd + lane*4);
    {
        float4 q0 = *(const float4*)(y2b + 0);
        float4 q1 = *(const float4*)(y2b + 4);
        y2B[0][0]=q0.x; y2B[0][1]=q0.y; y2B[0][2]=q0.z; y2B[0][3]=q0.w;
        y2B[0][4]=q1.x; y2B[0][5]=q1.y; y2B[0][6]=q1.z; y2B[0][7]=q1.w;
        mB[0] = *(const unsigned long long*)(mb);
    }

    int cur = 0;
    for (int ch = 0; ch < Nd/8; ch++) {
        int nxt = cur ^ 1;
        if (ch + 1 < Nd/8) {
            const float* ybn = yb + (size_t)(ch+1)*8*Dd;
            #pragma unroll
            for (int t = 0; t < 8; t++)
                yB[nxt][t] = *(const float4*)(ybn + (size_t)t*Dd + lane*4);
            float4 q0 = *(const float4*)(y2b + (ch+1)*8);
            float4 q1 = *(const float4*)(y2b + (ch+1)*8 + 4);
            y2B[nxt][0]=q0.x; y2B[nxt][1]=q0.y; y2B[nxt][2]=q0.z; y2B[nxt][3]=q0.w;
            y2B[nxt][4]=q1.x; y2B[nxt][5]=q1.y; y2B[nxt][6]=q1.z; y2B[nxt][7]=q1.w;
            mB[nxt] = *(const unsigned long long*)(mb + (ch+1)*8);
        }
        unsigned long long m8 = mB[cur];
        #pragma unroll
        for (int t = 0; t < 8; t++) {
            if ((m8 >> (t*8)) & 0xFFull) {
                float4 yv = yB[cur][t];
                float yy2 = y2B[cur][t];
                float xy = a0*yv.x + a1*yv.y + a2*yv.z + a3*yv.w;
                float x2 = a0*a0 + a1*a1 + a2*a2 + a3*a3;
                #pragma unroll
                for (int o = 16; o; o >>= 1) {
                    xy += __shfl_xor_sync(0xffffffffu, xy, o);
                    x2 += __shfl_xor_sync(0xffffffffu, x2, o);
                }
                float aa  = 1.f + 2.f*CC*xy + CC*yy2;
                float bb  = 1.f - CC*x2;
                float den = fmaxf(1.f + 2.f*CC*xy + CC*CC*x2*yy2, 1e-12f);
                a0 = (aa*a0 + bb*yv.x) / den;
                a1 = (aa*a1 + bb*yv.y) / den;
                a2 = (aa*a2 + bb*yv.z) / den;
                a3 = (aa*a3 + bb*yv.w) / den;
                cnt++;
            }
        }
        cur = nxt;
    }

    float n2 = a0*a0 + a1*a1 + a2*a2 + a3*a3;
    #pragma unroll
    for (int o = 16; o; o >>= 1) n2 += __shfl_xor_sync(0xffffffffu, n2, o);
    float nrm = sqrtf(n2);
    float t   = fminf(fmaxf(SCc*nrm, EPSc), 1.f - 1e-6f);
    float r   = 1.f / fmaxf((float)cnt, 1.f);
    float fac = tanhf(r * atanhf(t)) / fmaxf(SCc*nrm, EPSc);
    float p0 = fac*a0, p1 = fac*a1, p2 = fac*a2, p3 = fac*a3;
    if (cnt == 0) {
        float4 y0 = *(const float4*)(yb + lane*4);
        p0 = y0.x; p1 = y0.y; p2 = y0.z; p3 = y0.w;
    }

    float pn2 = p0*p0 + p1*p1 + p2*p2 + p3*p3;
    #pragma unroll
    for (int o = 16; o; o >>= 1) pn2 += __shfl_xor_sync(0xffffffffu, pn2, o);
    float npn = fmaxf(sqrtf(pn2), EPSc);
    float t2  = fminf(fmaxf(SCc*npn, EPSc), 1.f - 1e-6f);
    float cf  = atanhf(t2) / (SCc*npn);
    float v0 = cf*p0, v1 = cf*p1, v2 = cf*p2, v3 = cf*p3;

    for (int k = 0; k < NCd; k++) {
        float4 w = *(const float4*)(Wf + (size_t)k*Dd + lane*4);
        float pr = v0*w.x + v1*w.y + v2*w.z + v3*w.w;
        #pragma unroll
        for (int o = 16; o; o >>= 1) pr += __shfl_xor_sync(0xffffffffu, pr, o);
        if (lane == 0) out[b*NCd + k] = pr + bf[k];
    }
}

// ---------------------------- launcher -------------------------------------
extern "C" void kernel_launch(void* const* d_in, const int* in_sizes, int n_in,
                              void* d_out, int out_size)
{
    (void)in_sizes; (void)n_in; (void)out_size;
    const int*   tok  = (const int*)d_in[0];
    const void*  mask = d_in[1];
    const float* emb  = (const float*)d_in[2];
    const float* Wo   = (const float*)d_in[3];
    const float* bo   = (const float*)d_in[4];
    const float* Wf   = (const float*)d_in[5];
    const float* bf   = (const float*)d_in[6];
    float*       out  = (float*)d_out;

    cudaFuncSetAttribute(k_attn_mma, cudaFuncAttributeMaxDynamicSharedMemorySize, ATT_SMEM);

    k_detect   <<<1, 1024>>>((const uint4*)mask);
    k_masknorm <<<(Bd*Nd + 255)/256, 256>>>(mask);
    k_wprep    <<<(Dd*Dd + 255)/256, 256>>>(Wo);
    k_embed    <<<(Bd*Nd)/8, 256>>>(tok, emb);
    k_attn_mma <<<dim3(16, Bd), 128, ATT_SMEM>>>(bo);
    k_pool     <<<Bd, 32>>>(Wf, bf, out);
}

// round 13
// speedup vs baseline: 3.5951x; 1.0925x over previous
#include <cuda_runtime.h>
#include <cuda_fp16.h>
#include <cstdint>
#include <cstddef>

#define CC   0.1f
#define SCc  0.31622776601683794f   /* sqrt(0.1) */
#define EPSc 1e-7f

#define Bd  64
#define Nd  1024
#define Dd  128
#define DX  129
#define NCd 10

// ---------------- warp-MMA / cp.async helpers (baseline PTX) ---------------
__device__ __forceinline__ uint32_t smem_u32(const void* p)
{
    uint32_t a;
    asm("{ .reg .u64 t; cvta.to.shared.u64 t, %1; cvt.u32.u64 %0, t; }"
        : "=r"(a) : "l"(p));
    return a;
}
__device__ __forceinline__ void ldsm4(uint32_t& r0, uint32_t& r1,
                                      uint32_t& r2, uint32_t& r3, uint32_t addr)
{
    asm volatile("ldmatrix.sync.aligned.m8n8.x4.shared.b16 {%0,%1,%2,%3}, [%4];"
                 : "=r"(r0), "=r"(r1), "=r"(r2), "=r"(r3) : "r"(addr));
}
__device__ __forceinline__ void ldsm4t(uint32_t& r0, uint32_t& r1,
                                       uint32_t& r2, uint32_t& r3, uint32_t addr)
{
    asm volatile("ldmatrix.sync.aligned.m8n8.x4.trans.shared.b16 {%0,%1,%2,%3}, [%4];"
                 : "=r"(r0), "=r"(r1), "=r"(r2), "=r"(r3) : "r"(addr));
}
__device__ __forceinline__ void mma16816(float* c, uint32_t a0, uint32_t a1,
                                         uint32_t a2, uint32_t a3,
                                         uint32_t b0, uint32_t b1)
{
    asm volatile("mma.sync.aligned.m16n8k16.row.col.f32.f16.f16.f32 "
                 "{%0,%1,%2,%3}, {%4,%5,%6,%7}, {%8,%9}, {%0,%1,%2,%3};"
                 : "+f"(c[0]), "+f"(c[1]), "+f"(c[2]), "+f"(c[3])
                 : "r"(a0), "r"(a1), "r"(a2), "r"(a3), "r"(b0), "r"(b1));
}
__device__ __forceinline__ void cpasync16(uint32_t dst, const void* src)
{
    asm volatile("cp.async.cg.shared.global [%0], [%1], 16;"
                 :: "r"(dst), "l"(src) : "memory");
}
__device__ __forceinline__ void cp_commit()
{
    asm volatile("cp.async.commit_group;" ::: "memory");
}
__device__ __forceinline__ void cp_wait_all()
{
    asm volatile("cp.async.wait_group 0;" ::: "memory");
}
__device__ __forceinline__ uint32_t packh(float a, float b)
{
    __half ha = __float2half_rn(a), hb = __float2half_rn(b);
    return (uint32_t)__half_as_ushort(ha) | ((uint32_t)__half_as_ushort(hb) << 16);
}

// ---------------- scratch (device globals; no runtime allocation) ----------
__device__ __align__(16) __half g_xh[(size_t)Bd*Nd*Dd];  // x spatial hi
__device__ __align__(16) __half g_xl[(size_t)Bd*Nd*Dd];  // x spatial lo (Xj/mu only)
__device__ __align__(16) float  g_x0[(size_t)Bd*Nd];     // x time component
__device__ __align__(16) __half g_wh[(size_t)Dd*Dd];     // Wo spatial hi
__device__ __align__(16) __half g_wl[(size_t)Dd*Dd];     // Wo spatial lo
__device__ __align__(16) float  g_wo0[Dd];               // Wo[:,0]
__device__ __align__(16) float g_y [(size_t)Bd*Nd*Dd];   // Poincare tokens
__device__ __align__(16) float g_y2[(size_t)Bd*Nd];      // |y|^2 per token
__device__ __align__(16) unsigned char g_mask[(size_t)Bd*Nd];
__device__ int g_is32;

// ---------------- kernel 0a/0b: mask dtype detect + normalize --------------
__global__ void k_detect(const uint4* __restrict__ m)
{
    __shared__ int found;
    if (threadIdx.x == 0) found = 0;
    __syncthreads();
    unsigned int acc = 0;
    for (int i = threadIdx.x; i < Bd*Nd/16; i += blockDim.x) {
        uint4 v = m[i];
        acc |= (v.x | v.y | v.z | v.w) & 0xFFFFFF00u;
    }
    if (acc) atomicOr(&found, 1);
    __syncthreads();
    if (threadIdx.x == 0) g_is32 = found ? 0 : 1;
}
__global__ void k_masknorm(const void* __restrict__ m)
{
    int i = blockIdx.x * blockDim.x + threadIdx.x;
    if (i >= Bd*Nd) return;
    unsigned char v;
    if (g_is32) v = (((const int*)m)[i] != 0);
    else        v = (((const unsigned char*)m)[i] != 0);
    g_mask[i] = v;
}

// ---------------- kernel 0c: split Wo into fp16 hi/lo ----------------------
__global__ void k_wprep(const float* __restrict__ Wo)
{
    int idx = blockIdx.x * blockDim.x + threadIdx.x;
    if (idx >= Dd*Dd) return;
    int o = idx >> 7, k = idx & 127;
    float v = Wo[o*DX + (k+1)];
    __half h = __float2half_rn(v);
    g_wh[idx] = h;
    g_wl[idx] = __float2half_rn(v - __half2float(h));
    if (k == 0) g_wo0[o] = Wo[o*DX];
}

// ---------------- kernel 1: embedding + Lorentz expmap0 (fp16 split out) ---
__global__ void k_embed(const int* __restrict__ tok, const float* __restrict__ emb)
{
    int gw   = (blockIdx.x * blockDim.x + threadIdx.x) >> 5;
    int lane = threadIdx.x & 31;
    if (gw >= Bd*Nd) return;
    int t = tok[gw];
    float4 v = *(const float4*)(emb + (size_t)t*Dd + lane*4);
    float ss = v.x*v.x + v.y*v.y + v.z*v.z + v.w*v.w;
    #pragma unroll
    for (int o = 16; o; o >>= 1) ss += __shfl_xor_sync(0xffffffffu, ss, o);
    float nv   = fmaxf(sqrtf(ss), EPSc);
    float tt   = SCc * nv;
    float coef = sinhf(tt) / (SCc * nv);
    if (lane == 0) g_x0[gw] = coshf(tt) / SCc;

    float vv[4] = {coef*v.x, coef*v.y, coef*v.z, coef*v.w};
    uint32_t h01, h23, l01, l23;
    {
        __half h0 = __float2half_rn(vv[0]), h1 = __float2half_rn(vv[1]);
        __half h2 = __float2half_rn(vv[2]), h3 = __float2half_rn(vv[3]);
        h01 = (uint32_t)__half_as_ushort(h0) | ((uint32_t)__half_as_ushort(h1) << 16);
        h23 = (uint32_t)__half_as_ushort(h2) | ((uint32_t)__half_as_ushort(h3) << 16);
        l01 = packh(vv[0] - __half2float(h0), vv[1] - __half2float(h1));
        l23 = packh(vv[2] - __half2float(h2), vv[3] - __half2float(h3));
    }
    uint2* ph = (uint2*)(g_xh + (size_t)gw*Dd + lane*4);
    uint2* pl = (uint2*)(g_xl + (size_t)gw*Dd + lane*4);
    *ph = make_uint2(h01, h23);
    *pl = make_uint2(l01, l23);
}

// ---------------- kernel 2: attention + FUSED projection via mma.sync ------
// grid (16, 64); 128 threads = 4 warps x 16 query rows; 2 CTAs/SM.
// Score GEMM: single fp16 product (error analysis: <1e-6 at output).
// mu GEMM + projection GEMM: full 3-product fp16 hi/lo split.
// Xi A-fragments hoisted into registers across all 16 j-tiles.
#define STX 136
#define OXIH 0
#define OXJH0 17408
#define OXJL0 34816
#define OXJH1 52224
#define OXJL1 69632
#define OX0I  87040
#define OX0J0 87296
#define OX0J1 87552
#define OMS0  87808
#define OMS1  87872
#define OWO0  87936
#define OBO   88448
#define ATT_SMEM 88960

__device__ __forceinline__ void prefetch_xj(uint32_t sb, int b, int jt, int buf, int tid)
{
    size_t rowbase = (size_t)b*Nd + (size_t)jt*64;
    uint32_t dH = sb + (buf ? OXJH1 : OXJH0);
    uint32_t dL = sb + (buf ? OXJL1 : OXJL0);
    #pragma unroll
    for (int c = 0; c < 8; c++) {
        int idx = tid + c*128;
        int row = idx >> 4, ch = idx & 15;
        cpasync16(dH + row*272 + ch*16, g_xh + (rowbase + row)*Dd + ch*8);
    }
    #pragma unroll
    for (int c = 0; c < 8; c++) {
        int idx = tid + c*128;
        int row = idx >> 4, ch = idx & 15;
        cpasync16(dL + row*272 + ch*16, g_xl + (rowbase + row)*Dd + ch*8);
    }
    if (tid < 16) cpasync16(sb + (buf ? OX0J1 : OX0J0) + tid*16, g_x0 + rowbase + tid*4);
    if (tid < 4)  cpasync16(sb + (buf ? OMS1 : OMS0) + tid*16, g_mask + rowbase + tid*16);
    cp_commit();
}

__global__ void __launch_bounds__(128, 2) k_attn_mma(const float* __restrict__ bo)
{
    extern __shared__ float4 smem_f4[];
    char* smb = (char*)smem_f4;
    const uint32_t sb = smem_u32(smb);

    const int tid  = threadIdx.x;
    const int wid  = tid >> 5;
    const int lane = tid & 31;
    const int b    = blockIdx.y;
    const int i0   = blockIdx.x * 64;
    const float invsq = 1.0f / sqrtf(129.0f);

    // ---- Xi hi tile (64 rows) + x0i + wo0 + bo via cp.async ----
    {
        size_t rowbase = (size_t)b*Nd + i0;
        #pragma unroll
        for (int c = 0; c < 8; c++) {
            int idx = tid + c*128;
            int row = idx >> 4, ch = idx & 15;
            cpasync16(sb + OXIH + row*272 + ch*16, g_xh + (rowbase + row)*Dd + ch*8);
        }
        if (tid < 16)      cpasync16(sb + OX0I + tid*16, g_x0 + rowbase + tid*4);
        else if (tid < 48) cpasync16(sb + OWO0 + (tid-16)*16, g_wo0 + (tid-16)*4);
        else if (tid < 80) cpasync16(sb + OBO + (tid-48)*16, bo + (tid-48)*4);
    }
    prefetch_xj(sb, b, 0, 0, tid);

    const int r0 = wid*16 + (lane >> 2);
    const int cq = (lane & 3) * 2;

    const int la_row = lane & 15;
    const int la_kof = (lane >> 4) << 3;
    const int lb_n   = (lane & 7) + ((lane >> 4) << 3);
    const int lb_kof = ((lane >> 3) & 1) << 3;
    const int tr_row = (lane & 7) + (((lane >> 3) & 1) << 3);
    const int tr_col = (lane >> 4) << 3;

    const uint32_t aXiH = sb + OXIH + ((wid*16 + la_row)*STX + la_kof)*2;

    float muc[16][4];
    #pragma unroll
    for (int f = 0; f < 16; f++)
        muc[f][0] = muc[f][1] = muc[f][2] = muc[f][3] = 0.f;
    float den0 = 0.f, den1 = 0.f, ac00 = 0.f, ac01 = 0.f;
    float xi0 = 0.f, xi1 = 0.f;
    uint32_t xiA[8][4];   // hoisted Xi A-fragments (invariant across j-tiles)

    int buf = 0;
    for (int jt = 0; jt < 16; jt++) {
        cp_wait_all();
        __syncthreads();
        if (jt == 0) {
            xi0 = ((float*)(smb + OX0I))[r0];
            xi1 = ((float*)(smb + OX0I))[r0 + 8];
            #pragma unroll
            for (int kk = 0; kk < 8; kk++)
                ldsm4(xiA[kk][0], xiA[kk][1], xiA[kk][2], xiA[kk][3], aXiH + kk*32);
        }
        if (jt + 1 < 16) prefetch_xj(sb, b, jt + 1, buf ^ 1, tid);

        const uint32_t oXjH = sb + (buf ? OXJH1 : OXJH0);
        const uint32_t oXjL = sb + (buf ? OXJL1 : OXJL0);
        const float*   x0j  = (const float*)(smb + (buf ? OX0J1 : OX0J0));
        const unsigned char* msb = (const unsigned char*)(smb + (buf ? OMS1 : OMS0));

        const uint32_t bXjH = oXjH + (lb_n*STX + lb_kof)*2;
        const uint32_t tXjH = oXjH + (tr_row*STX + tr_col)*2;
        const uint32_t tXjL = oXjL + (tr_row*STX + tr_col)*2;

        // ---- score MMAs: S[16 x 64], single fp16 product ----
        float c[8][4];
        #pragma unroll
        for (int q = 0; q < 8; q++)
            c[q][0] = c[q][1] = c[q][2] = c[q][3] = 0.f;

        #pragma unroll
        for (int kk = 0; kk < 8; kk++) {
            #pragma unroll
            for (int nb = 0; nb < 4; nb++) {
                uint32_t bH0, bH1, bH2, bH3;
                ldsm4(bH0, bH1, bH2, bH3, bXjH + nb*(16*STX*2) + kk*32);
                mma16816(c[nb*2],   xiA[kk][0], xiA[kk][1], xiA[kk][2], xiA[kk][3], bH0, bH1);
                mma16816(c[nb*2+1], xiA[kk][0], xiA[kk][1], xiA[kk][2], xiA[kk][3], bH2, bH3);
            }
        }

        // ---- epilogue in registers: e values -> mu A-fragments ----
        uint32_t eaH[4][4], eaL[4][4];
        #pragma unroll
        for (int q = 0; q < 8; q++) {
            int j0 = q*8 + cq;
            float xjx = x0j[j0], xjy = x0j[j0+1];
            float m0 = (float)msb[j0], m1 = (float)msb[j0+1];
            float e00 = m0 * __expf((xi0*xjx - c[q][0]) * invsq);
            float e01 = m1 * __expf((xi0*xjy - c[q][1]) * invsq);
            float e10 = m0 * __expf((xi1*xjx - c[q][2]) * invsq);
            float e11 = m1 * __expf((xi1*xjy - c[q][3]) * invsq);
            den0 += e00 + e01;  den1 += e10 + e11;
            ac00 += e00*xjx + e01*xjy;
            ac01 += e10*xjx + e11*xjy;
            __half h00 = __float2half_rn(e00), h01 = __float2half_rn(e01);
            __half h10 = __float2half_rn(e10), h11 = __float2half_rn(e11);
            uint32_t hp0 = (uint32_t)__half_as_ushort(h00) | ((uint32_t)__half_as_ushort(h01) << 16);
            uint32_t hp1 = (uint32_t)__half_as_ushort(h10) | ((uint32_t)__half_as_ushort(h11) << 16);
            uint32_t lp0 = packh(e00 - __half2float(h00), e01 - __half2float(h01));
            uint32_t lp1 = packh(e10 - __half2float(h10), e11 - __half2float(h11));
            int kk = q >> 1;
            if ((q & 1) == 0) {
                eaH[kk][0] = hp0; eaH[kk][1] = hp1;
                eaL[kk][0] = lp0; eaL[kk][1] = lp1;
            } else {
                eaH[kk][2] = hp0; eaH[kk][3] = hp1;
                eaL[kk][2] = lp0; eaL[kk][3] = lp1;
            }
        }

        // ---- mu MMAs: mu[16 x 128] += E[16x64] . Xj[64x128]; 3 products ---
        #pragma unroll
        for (int kk = 0; kk < 4; kk++) {
            #pragma unroll
            for (int nb = 0; nb < 8; nb++) {
                uint32_t bH0, bH1, bH2, bH3, bL0, bL1, bL2, bL3;
                ldsm4t(bH0, bH1, bH2, bH3, tXjH + (kk*16*STX + nb*16)*2);
                ldsm4t(bL0, bL1, bL2, bL3, tXjL + (kk*16*STX + nb*16)*2);
                mma16816(muc[nb*2],   eaH[kk][0], eaH[kk][1], eaH[kk][2], eaH[kk][3], bH0, bH1);
                mma16816(muc[nb*2+1], eaH[kk][0], eaH[kk][1], eaH[kk][2], eaH[kk][3], bH2, bH3);
                mma16816(muc[nb*2],   eaH[kk][0], eaH[kk][1], eaH[kk][2], eaH[kk][3], bL0, bL1);
                mma16816(muc[nb*2+1], eaH[kk][0], eaH[kk][1], eaH[kk][2], eaH[kk][3], bL2, bL3);
                mma16816(muc[nb*2],   eaL[kk][0], eaL[kk][1], eaL[kk][2], eaL[kk][3], bH0, bH1);
                mma16816(muc[nb*2+1], eaL[kk][0], eaL[kk][1], eaL[kk][2], eaL[kk][3], bH2, bH3);
            }
        }
        buf ^= 1;
    }

    // ---- finalize: quad-reduce, Lorentz renorm (registers only) ----
    #pragma unroll
    for (int o = 1; o < 4; o <<= 1) {
        den0 += __shfl_xor_sync(0xffffffffu, den0, o);
        den1 += __shfl_xor_sync(0xffffffffu, den1, o);
        ac00 += __shfl_xor_sync(0xffffffffu, ac00, o);
        ac01 += __shfl_xor_sync(0xffffffffu, ac01, o);
    }
    float id0 = 1.f / den0, id1 = 1.f / den1;
    float mu00 = ac00 * id0, mu01 = ac01 * id1;

    float in0 = 0.f, in1 = 0.f;
    #pragma unroll
    for (int f = 0; f < 16; f++) {
        muc[f][0] *= id0; muc[f][1] *= id0;
        muc[f][2] *= id1; muc[f][3] *= id1;
        in0 += muc[f][0]*muc[f][0] + muc[f][1]*muc[f][1];
        in1 += muc[f][2]*muc[f][2] + muc[f][3]*muc[f][3];
    }
    #pragma unroll
    for (int o = 1; o < 4; o <<= 1) {
        in0 += __shfl_xor_sync(0xffffffffu, in0, o);
        in1 += __shfl_xor_sync(0xffffffffu, in1, o);
    }
    float s20 = 1.f / (SCc * sqrtf(fmaxf(mu00*mu00 - in0, EPSc)));
    float s21 = 1.f / (SCc * sqrtf(fmaxf(mu01*mu01 - in1, EPSc)));
    float mu0a = mu00 * s20, mu0b = mu01 * s21;

    // ---- all warps done with Xj smem; stream Wo hi/lo into dead buffers ----
    __syncthreads();
    #pragma unroll
    for (int c = 0; c < 16; c++) {
        int idx = tid + c*128;
        int row = idx >> 4, ch = idx & 15;
        cpasync16(sb + OXJH0 + row*272 + ch*16, g_wh + (size_t)row*Dd + ch*8);
    }
    #pragma unroll
    for (int c = 0; c < 16; c++) {
        int idx = tid + c*128;
        int row = idx >> 4, ch = idx & 15;
        cpasync16(sb + OXJH1 + row*272 + ch*16, g_wl + (size_t)row*Dd + ch*8);
    }
    cp_commit();

    // ---- scale mu and split to fp16 hi/lo A-fragments (overlaps loads) ----
    #pragma unroll
    for (int f = 0; f < 16; f++) {
        muc[f][0] *= s20; muc[f][1] *= s20;
        muc[f][2] *= s21; muc[f][3] *= s21;
    }
    uint32_t mAH[8][4], mAL[8][4];
    #pragma unroll
    for (int kk = 0; kk < 8; kk++) {
        #pragma unroll
        for (int g = 0; g < 2; g++) {
            int f = 2*kk + g;
            __half h0 = __float2half_rn(muc[f][0]), h1 = __float2half_rn(muc[f][1]);
            __half h2 = __float2half_rn(muc[f][2]), h3 = __float2half_rn(muc[f][3]);
            mAH[kk][2*g+0] = (uint32_t)__half_as_ushort(h0) | ((uint32_t)__half_as_ushort(h1) << 16);
            mAH[kk][2*g+1] = (uint32_t)__half_as_ushort(h2) | ((uint32_t)__half_as_ushort(h3) << 16);
            mAL[kk][2*g+0] = packh(muc[f][0] - __half2float(h0), muc[f][1] - __half2float(h1));
            mAL[kk][2*g+1] = packh(muc[f][2] - __half2float(h2), muc[f][3] - __half2float(h3));
        }
    }

    cp_wait_all();
    __syncthreads();

    // ---- projection MMAs: u[16 x 128] = mu_spatial . Wo_spatial^T ----
    const uint32_t bWH = sb + OXJH0 + (lb_n*STX + lb_kof)*2;
    const uint32_t bWL = sb + OXJH1 + (lb_n*STX + lb_kof)*2;

    float c2[16][4];
    #pragma unroll
    for (int q = 0; q < 16; q++)
        c2[q][0] = c2[q][1] = c2[q][2] = c2[q][3] = 0.f;

    #pragma unroll
    for (int kk = 0; kk < 8; kk++) {
        #pragma unroll
        for (int nb = 0; nb < 8; nb++) {
            uint32_t bH0, bH1, bH2, bH3, bL0, bL1, bL2, bL3;
            ldsm4(bH0, bH1, bH2, bH3, bWH + nb*(16*STX*2) + kk*32);
            ldsm4(bL0, bL1, bL2, bL3, bWL + nb*(16*STX*2) + kk*32);
            mma16816(c2[nb*2],   mAH[kk][0], mAH[kk][1], mAH[kk][2], mAH[kk][3], bH0, bH1);
            mma16816(c2[nb*2+1], mAH[kk][0], mAH[kk][1], mAH[kk][2], mAH[kk][3], bH2, bH3);
            mma16816(c2[nb*2],   mAH[kk][0], mAH[kk][1], mAH[kk][2], mAH[kk][3], bL0, bL1);
            mma16816(c2[nb*2+1], mAH[kk][0], mAH[kk][1], mAH[kk][2], mAH[kk][3], bL2, bL3);
            mma16816(c2[nb*2],   mAL[kk][0], mAL[kk][1], mAL[kk][2], mAL[kk][3], bH0, bH1);
            mma16816(c2[nb*2+1], mAL[kk][0], mAL[kk][1], mAL[kk][2], mAL[kk][3], bH2, bH3);
        }
    }

    // ---- epilogue: +mu0*Wo0 + bo, norm, tanh scale, write y/y2 ----
    const float* wo0s = (const float*)(smb + OWO0);
    const float* bos  = (const float*)(smb + OBO);

    float u[16][4];
    float pp0 = 0.f, pp1 = 0.f;
    #pragma unroll
    for (int q = 0; q < 16; q++) {
        int col = q*8 + cq;
        float w0 = wo0s[col], w1 = wo0s[col+1];
        float b0 = bos[col],  b1 = bos[col+1];
        u[q][0] = c2[q][0] + mu0a*w0 + b0;
        u[q][1] = c2[q][1] + mu0a*w1 + b1;
        u[q][2] = c2[q][2] + mu0b*w0 + b0;
        u[q][3] = c2[q][3] + mu0b*w1 + b1;
        pp0 += u[q][0]*u[q][0] + u[q][1]*u[q][1];
        pp1 += u[q][2]*u[q][2] + u[q][3]*u[q][3];
    }
    #pragma unroll
    for (int o = 1; o < 4; o <<= 1) {
        pp0 += __shfl_xor_sync(0xffffffffu, pp0, o);
        pp1 += __shfl_xor_sync(0xffffffffu, pp1, o);
    }
    float nu0 = fmaxf(sqrtf(pp0), EPSc);
    float nu1 = fmaxf(sqrtf(pp1), EPSc);
    float f0 = tanhf(SCc*nu0) / (SCc*nu0);
    float f1 = tanhf(SCc*nu1) / (SCc*nu1);

    float* y0 = g_y + ((size_t)b*Nd + i0 + r0) * Dd;
    float* y1 = y0 + (size_t)8 * Dd;
    float qq0 = 0.f, qq1 = 0.f;
    #pragma unroll
    for (int q = 0; q < 16; q++) {
        int col = q*8 + cq;
        float v00 = u[q][0]*f0, v01 = u[q][1]*f0;
        float v10 = u[q][2]*f1, v11 = u[q][3]*f1;
        *(float2*)(y0 + col) = make_float2(v00, v01);
        *(float2*)(y1 + col) = make_float2(v10, v11);
        qq0 += v00*v00 + v01*v01;
        qq1 += v10*v10 + v11*v11;
    }
    #pragma unroll
    for (int o = 1; o < 4; o <<= 1) {
        qq0 += __shfl_xor_sync(0xffffffffu, qq0, o);
        qq1 += __shfl_xor_sync(0xffffffffu, qq1, o);
    }
    if ((lane & 3) == 0) {
        g_y2[(size_t)b*Nd + i0 + r0]     = qq0;
        g_y2[(size_t)b*Nd + i0 + r0 + 8] = qq1;
    }
}

// ---------------- kernel 4: Mobius pooling + MLR head (deep prefetch) ------
__global__ void k_pool(const float* __restrict__ Wf,
                       const float* __restrict__ bf,
                       float* __restrict__ out)
{
    const int b    = blockIdx.x;
    const int lane = threadIdx.x;
    const float* yb  = g_y  + (size_t)b*Nd*Dd;
    const float* y2b = g_y2 + (size_t)b*Nd;
    const unsigned char* mb = g_mask + (size_t)b*Nd;

    float a0=0.f, a1=0.f, a2=0.f, a3=0.f;
    int cnt = 0;

    float4 yB[2][8];
    float  y2B[2][8];
    unsigned long long mB[2];

    #pragma unroll
    for (int t = 0; t < 8; t++)
        yB[0][t] = *(const float4*)(yb + (size_t)t*Dd + lane*4);
    {
        float4 q0 = *(const float4*)(y2b + 0);
        float4 q1 = *(const float4*)(y2b + 4);
        y2B[0][0]=q0.x; y2B[0][1]=q0.y; y2B[0][2]=q0.z; y2B[0][3]=q0.w;
        y2B[0][4]=q1.x; y2B[0][5]=q1.y; y2B[0][6]=q1.z; y2B[0][7]=q1.w;
        mB[0] = *(const unsigned long long*)(mb);
    }

    int cur = 0;
    for (int ch = 0; ch < Nd/8; ch++) {
        int nxt = cur ^ 1;
        if (ch + 1 < Nd/8) {
            const float* ybn = yb + (size_t)(ch+1)*8*Dd;
            #pragma unroll
            for (int t = 0; t < 8; t++)
                yB[nxt][t] = *(const float4*)(ybn + (size_t)t*Dd + lane*4);
            float4 q0 = *(const float4*)(y2b + (ch+1)*8);
            float4 q1 = *(const float4*)(y2b + (ch+1)*8 + 4);
            y2B[nxt][0]=q0.x; y2B[nxt][1]=q0.y; y2B[nxt][2]=q0.z; y2B[nxt][3]=q0.w;
            y2B[nxt][4]=q1.x; y2B[nxt][5]=q1.y; y2B[nxt][6]=q1.z; y2B[nxt][7]=q1.w;
            mB[nxt] = *(const unsigned long long*)(mb + (ch+1)*8);
        }
        unsigned long long m8 = mB[cur];
        #pragma unroll
        for (int t = 0; t < 8; t++) {
            if ((m8 >> (t*8)) & 0xFFull) {
                float4 yv = yB[cur][t];
                float yy2 = y2B[cur][t];
                float xy = a0*yv.x + a1*yv.y + a2*yv.z + a3*yv.w;
                float x2 = a0*a0 + a1*a1 + a2*a2 + a3*a3;
                #pragma unroll
                for (int o = 16; o; o >>= 1) {
                    xy += __shfl_xor_sync(0xffffffffu, xy, o);
                    x2 += __shfl_xor_sync(0xffffffffu, x2, o);
                }
                float aa  = 1.f + 2.f*CC*xy + CC*yy2;
                float bb  = 1.f - CC*x2;
                float den = fmaxf(1.f + 2.f*CC*xy + CC*CC*x2*yy2, 1e-12f);
                a0 = (aa*a0 + bb*yv.x) / den;
                a1 = (aa*a1 + bb*yv.y) / den;
                a2 = (aa*a2 + bb*yv.z) / den;
                a3 = (aa*a3 + bb*yv.w) / den;
                cnt++;
            }
        }
        cur = nxt;
    }

    float n2 = a0*a0 + a1*a1 + a2*a2 + a3*a3;
    #pragma unroll
    for (int o = 16; o; o >>= 1) n2 += __shfl_xor_sync(0xffffffffu, n2, o);
    float nrm = sqrtf(n2);
    float t   = fminf(fmaxf(SCc*nrm, EPSc), 1.f - 1e-6f);
    float r   = 1.f / fmaxf((float)cnt, 1.f);
    float fac = tanhf(r * atanhf(t)) / fmaxf(SCc*nrm, EPSc);
    float p0 = fac*a0, p1 = fac*a1, p2 = fac*a2, p3 = fac*a3;
    if (cnt == 0) {
        float4 y0 = *(const float4*)(yb + lane*4);
        p0 = y0.x; p1 = y0.y; p2 = y0.z; p3 = y0.w;
    }

    float pn2 = p0*p0 + p1*p1 + p2*p2 + p3*p3;
    #pragma unroll
    for (int o = 16; o; o >>= 1) pn2 += __shfl_xor_sync(0xffffffffu, pn2, o);
    float npn = fmaxf(sqrtf(pn2), EPSc);
    float t2  = fminf(fmaxf(SCc*npn, EPSc), 1.f - 1e-6f);
    float cf  = atanhf(t2) / (SCc*npn);
    float v0 = cf*p0, v1 = cf*p1, v2 = cf*p2, v3 = cf*p3;

    for (int k = 0; k < NCd; k++) {
        float4 w = *(const float4*)(Wf + (size_t)k*Dd + lane*4);
        float pr = v0*w.x + v1*w.y + v2*w.z + v3*w.w;
        #pragma unroll
        for (int o = 16; o; o >>= 1) pr += __shfl_xor_sync(0xffffffffu, pr, o);
        if (lane == 0) out[b*NCd + k] = pr + bf[k];
    }
}

// ---------------------------- launcher -------------------------------------
extern "C" void kernel_launch(void* const* d_in, const int* in_sizes, int n_in,
                              void* d_out, int out_size)
{
    (void)in_sizes; (void)n_in; (void)out_size;
    const int*   tok  = (const int*)d_in[0];
    const void*  mask = d_in[1];
    const float* emb  = (const float*)d_in[2];
    const float* Wo   = (const float*)d_in[3];
    const float* bo   = (const float*)d_in[4];
    const float* Wf   = (const float*)d_in[5];
    const float* bf   = (const float*)d_in[6];
    float*       out  = (float*)d_out;

    cudaFuncSetAttribute(k_attn_mma, cudaFuncAttributeMaxDynamicSharedMemorySize, ATT_SMEM);

    k_detect   <<<1, 1024>>>((const uint4*)mask);
    k_masknorm <<<(Bd*Nd + 255)/256, 256>>>(mask);
    k_wprep    <<<(Dd*Dd + 255)/256, 256>>>(Wo);
    k_embed    <<<(Bd*Nd)/8, 256>>>(tok, emb);
    k_attn_mma <<<dim3(16, Bd), 128, ATT_SMEM>>>(bo);
    k_pool     <<<Bd, 32>>>(Wf, bf, out);
}

// round 14
// speedup vs baseline: 3.6956x; 1.0280x over previous
#include <cuda_runtime.h>
#include <cuda_fp16.h>
#include <cstdint>
#include <cstddef>

#define CC   0.1f
#define SCc  0.31622776601683794f   /* sqrt(0.1) */
#define EPSc 1e-7f

#define Bd  64
#define Nd  1024
#define Dd  128
#define DX  129
#define NCd 10

// ---------------- warp-MMA / cp.async helpers (baseline PTX) ---------------
__device__ __forceinline__ uint32_t smem_u32(const void* p)
{
    uint32_t a;
    asm("{ .reg .u64 t; cvta.to.shared.u64 t, %1; cvt.u32.u64 %0, t; }"
        : "=r"(a) : "l"(p));
    return a;
}
__device__ __forceinline__ void ldsm4(uint32_t& r0, uint32_t& r1,
                                      uint32_t& r2, uint32_t& r3, uint32_t addr)
{
    asm volatile("ldmatrix.sync.aligned.m8n8.x4.shared.b16 {%0,%1,%2,%3}, [%4];"
                 : "=r"(r0), "=r"(r1), "=r"(r2), "=r"(r3) : "r"(addr));
}
__device__ __forceinline__ void ldsm4t(uint32_t& r0, uint32_t& r1,
                                       uint32_t& r2, uint32_t& r3, uint32_t addr)
{
    asm volatile("ldmatrix.sync.aligned.m8n8.x4.trans.shared.b16 {%0,%1,%2,%3}, [%4];"
                 : "=r"(r0), "=r"(r1), "=r"(r2), "=r"(r3) : "r"(addr));
}
__device__ __forceinline__ void mma16816(float* c, uint32_t a0, uint32_t a1,
                                         uint32_t a2, uint32_t a3,
                                         uint32_t b0, uint32_t b1)
{
    asm volatile("mma.sync.aligned.m16n8k16.row.col.f32.f16.f16.f32 "
                 "{%0,%1,%2,%3}, {%4,%5,%6,%7}, {%8,%9}, {%0,%1,%2,%3};"
                 : "+f"(c[0]), "+f"(c[1]), "+f"(c[2]), "+f"(c[3])
                 : "r"(a0), "r"(a1), "r"(a2), "r"(a3), "r"(b0), "r"(b1));
}
__device__ __forceinline__ void cpasync16(uint32_t dst, const void* src)
{
    asm volatile("cp.async.cg.shared.global [%0], [%1], 16;"
                 :: "r"(dst), "l"(src) : "memory");
}
__device__ __forceinline__ void cp_commit()
{
    asm volatile("cp.async.commit_group;" ::: "memory");
}
__device__ __forceinline__ void cp_wait0()
{
    asm volatile("cp.async.wait_group 0;" ::: "memory");
}
__device__ __forceinline__ void cp_wait1()
{
    asm volatile("cp.async.wait_group 1;" ::: "memory");
}
__device__ __forceinline__ uint32_t packh(float a, float b)
{
    __half ha = __float2half_rn(a), hb = __float2half_rn(b);
    return (uint32_t)__half_as_ushort(ha) | ((uint32_t)__half_as_ushort(hb) << 16);
}

// ---------------- scratch (device globals; no runtime allocation) ----------
__device__ __align__(16) __half g_xh[(size_t)Bd*Nd*Dd];  // x spatial hi
__device__ __align__(16) __half g_xl[(size_t)Bd*Nd*Dd];  // x spatial lo
__device__ __align__(16) float  g_x0[(size_t)Bd*Nd];     // x time component
__device__ __align__(16) __half g_wh[(size_t)Dd*Dd];     // Wo spatial hi
__device__ __align__(16) __half g_wl[(size_t)Dd*Dd];     // Wo spatial lo
__device__ __align__(16) float  g_wo0[Dd];               // Wo[:,0]
__device__ __align__(16) float g_y [(size_t)Bd*Nd*Dd];   // Poincare tokens
__device__ __align__(16) float g_y2[(size_t)Bd*Nd];      // |y|^2 per token
__device__ __align__(16) unsigned char g_mask[(size_t)Bd*Nd];
__device__ int g_is32;

// ---------------- kernel 0a/0b: mask dtype detect + normalize --------------
__global__ void k_detect(const uint4* __restrict__ m)
{
    __shared__ int found;
    if (threadIdx.x == 0) found = 0;
    __syncthreads();
    unsigned int acc = 0;
    for (int i = threadIdx.x; i < Bd*Nd/16; i += blockDim.x) {
        uint4 v = m[i];
        acc |= (v.x | v.y | v.z | v.w) & 0xFFFFFF00u;
    }
    if (acc) atomicOr(&found, 1);
    __syncthreads();
    if (threadIdx.x == 0) g_is32 = found ? 0 : 1;
}
__global__ void k_masknorm(const void* __restrict__ m)
{
    int i = blockIdx.x * blockDim.x + threadIdx.x;
    if (i >= Bd*Nd) return;
    unsigned char v;
    if (g_is32) v = (((const int*)m)[i] != 0);
    else        v = (((const unsigned char*)m)[i] != 0);
    g_mask[i] = v;
}

// ---------------- kernel 0c: split Wo into fp16 hi/lo ----------------------
__global__ void k_wprep(const float* __restrict__ Wo)
{
    int idx = blockIdx.x * blockDim.x + threadIdx.x;
    if (idx >= Dd*Dd) return;
    int o = idx >> 7, k = idx & 127;
    float v = Wo[o*DX + (k+1)];
    __half h = __float2half_rn(v);
    g_wh[idx] = h;
    g_wl[idx] = __float2half_rn(v - __half2float(h));
    if (k == 0) g_wo0[o] = Wo[o*DX];
}

// ---------------- kernel 1: embedding + Lorentz expmap0 (fp16 split out) ---
__global__ void k_embed(const int* __restrict__ tok, const float* __restrict__ emb)
{
    int gw   = (blockIdx.x * blockDim.x + threadIdx.x) >> 5;
    int lane = threadIdx.x & 31;
    if (gw >= Bd*Nd) return;
    int t = tok[gw];
    float4 v = *(const float4*)(emb + (size_t)t*Dd + lane*4);
    float ss = v.x*v.x + v.y*v.y + v.z*v.z + v.w*v.w;
    #pragma unroll
    for (int o = 16; o; o >>= 1) ss += __shfl_xor_sync(0xffffffffu, ss, o);
    float nv   = fmaxf(sqrtf(ss), EPSc);
    float tt   = SCc * nv;
    float coef = sinhf(tt) / (SCc * nv);
    if (lane == 0) g_x0[gw] = coshf(tt) / SCc;

    float vv[4] = {coef*v.x, coef*v.y, coef*v.z, coef*v.w};
    uint32_t h01, h23, l01, l23;
    {
        __half h0 = __float2half_rn(vv[0]), h1 = __float2half_rn(vv[1]);
        __half h2 = __float2half_rn(vv[2]), h3 = __float2half_rn(vv[3]);
        h01 = (uint32_t)__half_as_ushort(h0) | ((uint32_t)__half_as_ushort(h1) << 16);
        h23 = (uint32_t)__half_as_ushort(h2) | ((uint32_t)__half_as_ushort(h3) << 16);
        l01 = packh(vv[0] - __half2float(h0), vv[1] - __half2float(h1));
        l23 = packh(vv[2] - __half2float(h2), vv[3] - __half2float(h3));
    }
    uint2* ph = (uint2*)(g_xh + (size_t)gw*Dd + lane*4);
    uint2* pl = (uint2*)(g_xl + (size_t)gw*Dd + lane*4);
    *ph = make_uint2(h01, h23);
    *pl = make_uint2(l01, l23);
}

// ---------------- kernel 2: attention + FUSED projection via mma.sync ------
// grid (16, 64); 128 threads = 4 warps x 16 query rows; 3 CTAs/SM.
// Xj-hi double-buffered (group A), Xj-lo single-buffered (group B) — the lo
// load overlaps the score GEMM, which only needs hi.
#define STX 136
#define OXIH  0
#define OXJH0 17408
#define OXJH1 34816
#define OXJL  52224
#define OX0I  69632
#define OX0J0 69888
#define OX0J1 70144
#define OMS0  70400
#define OMS1  70464
#define OWO0  70528
#define OBO   71040
#define ATT_SMEM 71552

__device__ __forceinline__ void prefetch_xjH(uint32_t sb, int b, int jt, int buf, int tid)
{
    size_t rowbase = (size_t)b*Nd + (size_t)jt*64;
    uint32_t dH = sb + (buf ? OXJH1 : OXJH0);
    #pragma unroll
    for (int c = 0; c < 8; c++) {
        int idx = tid + c*128;
        int row = idx >> 4, ch = idx & 15;
        cpasync16(dH + row*272 + ch*16, g_xh + (rowbase + row)*Dd + ch*8);
    }
    if (tid < 16) cpasync16(sb + (buf ? OX0J1 : OX0J0) + tid*16, g_x0 + rowbase + tid*4);
    if (tid < 4)  cpasync16(sb + (buf ? OMS1 : OMS0) + tid*16, g_mask + rowbase + tid*16);
    cp_commit();
}
__device__ __forceinline__ void prefetch_xjL(uint32_t sb, int b, int jt, int tid)
{
    size_t rowbase = (size_t)b*Nd + (size_t)jt*64;
    #pragma unroll
    for (int c = 0; c < 8; c++) {
        int idx = tid + c*128;
        int row = idx >> 4, ch = idx & 15;
        cpasync16(sb + OXJL + row*272 + ch*16, g_xl + (rowbase + row)*Dd + ch*8);
    }
    cp_commit();
}

__global__ void __launch_bounds__(128, 3) k_attn_mma(const float* __restrict__ bo)
{
    extern __shared__ float4 smem_f4[];
    char* smb = (char*)smem_f4;
    const uint32_t sb = smem_u32(smb);

    const int tid  = threadIdx.x;
    const int wid  = tid >> 5;
    const int lane = tid & 31;
    const int b    = blockIdx.y;
    const int i0   = blockIdx.x * 64;
    const float invsq = 1.0f / sqrtf(129.0f);

    // ---- group A0: Xi hi tile + x0i + wo0 + bo + XjH(0) ----
    {
        size_t rowbase = (size_t)b*Nd + i0;
        #pragma unroll
        for (int c = 0; c < 8; c++) {
            int idx = tid + c*128;
            int row = idx >> 4, ch = idx & 15;
            cpasync16(sb + OXIH + row*272 + ch*16, g_xh + (rowbase + row)*Dd + ch*8);
        }
        if (tid < 16)      cpasync16(sb + OX0I + tid*16, g_x0 + rowbase + tid*4);
        else if (tid < 48) cpasync16(sb + OWO0 + (tid-16)*16, g_wo0 + (tid-16)*4);
        else if (tid < 80) cpasync16(sb + OBO + (tid-48)*16, bo + (tid-48)*4);
    }
    prefetch_xjH(sb, b, 0, 0, tid);   // merged into one big group A with Xi? No: separate commit
    prefetch_xjL(sb, b, 0, tid);      // group B

    const int r0 = wid*16 + (lane >> 2);
    const int cq = (lane & 3) * 2;

    const int la_row = lane & 15;
    const int la_kof = (lane >> 4) << 3;
    const int lb_n   = (lane & 7) + ((lane >> 4) << 3);
    const int lb_kof = ((lane >> 3) & 1) << 3;
    const int tr_row = (lane & 7) + (((lane >> 3) & 1) << 3);
    const int tr_col = (lane >> 4) << 3;

    const uint32_t aXiH = sb + OXIH + ((wid*16 + la_row)*STX + la_kof)*2;

    float muc[16][4];
    #pragma unroll
    for (int f = 0; f < 16; f++)
        muc[f][0] = muc[f][1] = muc[f][2] = muc[f][3] = 0.f;
    float den0 = 0.f, den1 = 0.f, ac00 = 0.f, ac01 = 0.f;
    float xi0 = 0.f, xi1 = 0.f;

    int buf = 0;
    for (int jt = 0; jt < 16; jt++) {
        // hi tile (and everything committed before it) ready; lo may still fly
        cp_wait1();
        __syncthreads();
        if (jt == 0) {
            xi0 = ((float*)(smb + OX0I))[r0];
            xi1 = ((float*)(smb + OX0I))[r0 + 8];
        }
        if (jt + 1 < 16) prefetch_xjH(sb, b, jt + 1, buf ^ 1, tid);

        const uint32_t oXjH = sb + (buf ? OXJH1 : OXJH0);
        const float*   x0j  = (const float*)(smb + (buf ? OX0J1 : OX0J0));
        const unsigned char* msb = (const unsigned char*)(smb + (buf ? OMS1 : OMS0));

        const uint32_t bXjH = oXjH + (lb_n*STX + lb_kof)*2;
        const uint32_t tXjH = oXjH + (tr_row*STX + tr_col)*2;
        const uint32_t tXjL = sb + OXJL + (tr_row*STX + tr_col)*2;

        // ---- score MMAs: S[16 x 64], single fp16 product (hi only) ----
        float c[8][4];
        #pragma unroll
        for (int q = 0; q < 8; q++)
            c[q][0] = c[q][1] = c[q][2] = c[q][3] = 0.f;

        #pragma unroll
        for (int kk = 0; kk < 8; kk++) {
            uint32_t a0, a1, a2, a3;
            ldsm4(a0, a1, a2, a3, aXiH + kk*32);
            #pragma unroll
            for (int nb = 0; nb < 4; nb++) {
                uint32_t bH0, bH1, bH2, bH3;
                ldsm4(bH0, bH1, bH2, bH3, bXjH + nb*(16*STX*2) + kk*32);
                mma16816(c[nb*2],   a0, a1, a2, a3, bH0, bH1);
                mma16816(c[nb*2+1], a0, a1, a2, a3, bH2, bH3);
            }
        }

        // lo tile now needed (its load overlapped the score GEMM above)
        if (jt + 1 < 16) cp_wait1();
        else             cp_wait0();

        // ---- epilogue in registers: e values -> mu A-fragments ----
        uint32_t eaH[4][4], eaL[4][4];
        #pragma unroll
        for (int q = 0; q < 8; q++) {
            int j0 = q*8 + cq;
            float xjx = x0j[j0], xjy = x0j[j0+1];
            float m0 = (float)msb[j0], m1 = (float)msb[j0+1];
            float e00 = m0 * __expf((xi0*xjx - c[q][0]) * invsq);
            float e01 = m1 * __expf((xi0*xjy - c[q][1]) * invsq);
            float e10 = m0 * __expf((xi1*xjx - c[q][2]) * invsq);
            float e11 = m1 * __expf((xi1*xjy - c[q][3]) * invsq);
            den0 += e00 + e01;  den1 += e10 + e11;
            ac00 += e00*xjx + e01*xjy;
            ac01 += e10*xjx + e11*xjy;
            __half h00 = __float2half_rn(e00), h01 = __float2half_rn(e01);
            __half h10 = __float2half_rn(e10), h11 = __float2half_rn(e11);
            uint32_t hp0 = (uint32_t)__half_as_ushort(h00) | ((uint32_t)__half_as_ushort(h01) << 16);
            uint32_t hp1 = (uint32_t)__half_as_ushort(h10) | ((uint32_t)__half_as_ushort(h11) << 16);
            uint32_t lp0 = packh(e00 - __half2float(h00), e01 - __half2float(h01));
            uint32_t lp1 = packh(e10 - __half2float(h10), e11 - __half2float(h11));
            int kk = q >> 1;
            if ((q & 1) == 0) {
                eaH[kk][0] = hp0; eaH[kk][1] = hp1;
                eaL[kk][0] = lp0; eaL[kk][1] = lp1;
            } else {
                eaH[kk][2] = hp0; eaH[kk][3] = hp1;
                eaL[kk][2] = lp0; eaL[kk][3] = lp1;
            }
        }

        // ---- mu MMAs: mu[16 x 128] += E[16x64] . Xj[64x128]; 3 products ---
        #pragma unroll
        for (int kk = 0; kk < 4; kk++) {
            #pragma unroll
            for (int nb = 0; nb < 8; nb++) {
                uint32_t bH0, bH1, bH2, bH3, bL0, bL1, bL2, bL3;
                ldsm4t(bH0, bH1, bH2, bH3, tXjH + (kk*16*STX + nb*16)*2);
                ldsm4t(bL0, bL1, bL2, bL3, tXjL + (kk*16*STX + nb*16)*2);
                mma16816(muc[nb*2],   eaH[kk][0], eaH[kk][1], eaH[kk][2], eaH[kk][3], bH0, bH1);
                mma16816(muc[nb*2+1], eaH[kk][0], eaH[kk][1], eaH[kk][2], eaH[kk][3], bH2, bH3);
                mma16816(muc[nb*2],   eaH[kk][0], eaH[kk][1], eaH[kk][2], eaH[kk][3], bL0, bL1);
                mma16816(muc[nb*2+1], eaH[kk][0], eaH[kk][1], eaH[kk][2], eaH[kk][3], bL2, bL3);
                mma16816(muc[nb*2],   eaL[kk][0], eaL[kk][1], eaL[kk][2], eaL[kk][3], bH0, bH1);
                mma16816(muc[nb*2+1], eaL[kk][0], eaL[kk][1], eaL[kk][2], eaL[kk][3], bH2, bH3);
            }
        }

        // all warps done reading XjL(jt) -> safe to overwrite
        __syncthreads();
        if (jt + 1 < 16) prefetch_xjL(sb, b, jt + 1, tid);
        buf ^= 1;
    }

    // ---- finalize: quad-reduce, Lorentz renorm (registers only) ----
    #pragma unroll
    for (int o = 1; o < 4; o <<= 1) {
        den0 += __shfl_xor_sync(0xffffffffu, den0, o);
        den1 += __shfl_xor_sync(0xffffffffu, den1, o);
        ac00 += __shfl_xor_sync(0xffffffffu, ac00, o);
        ac01 += __shfl_xor_sync(0xffffffffu, ac01, o);
    }
    float id0 = 1.f / den0, id1 = 1.f / den1;
    float mu00 = ac00 * id0, mu01 = ac01 * id1;

    float in0 = 0.f, in1 = 0.f;
    #pragma unroll
    for (int f = 0; f < 16; f++) {
        muc[f][0] *= id0; muc[f][1] *= id0;
        muc[f][2] *= id1; muc[f][3] *= id1;
        in0 += muc[f][0]*muc[f][0] + muc[f][1]*muc[f][1];
        in1 += muc[f][2]*muc[f][2] + muc[f][3]*muc[f][3];
    }
    #pragma unroll
    for (int o = 1; o < 4; o <<= 1) {
        in0 += __shfl_xor_sync(0xffffffffu, in0, o);
        in1 += __shfl_xor_sync(0xffffffffu, in1, o);
    }
    float s20 = 1.f / (SCc * sqrtf(fmaxf(mu00*mu00 - in0, EPSc)));
    float s21 = 1.f / (SCc * sqrtf(fmaxf(mu01*mu01 - in1, EPSc)));
    float mu0a = mu00 * s20, mu0b = mu01 * s21;

    // ---- Xi/Xj smem all dead; stream Wo hi (at 0) and lo (at 34816) ----
    __syncthreads();
    #pragma unroll
    for (int c = 0; c < 16; c++) {
        int idx = tid + c*128;
        int row = idx >> 4, ch = idx & 15;
        cpasync16(sb + 0 + row*272 + ch*16, g_wh + (size_t)row*Dd + ch*8);
    }
    #pragma unroll
    for (int c = 0; c < 16; c++) {
        int idx = tid + c*128;
        int row = idx >> 4, ch = idx & 15;
        cpasync16(sb + 34816 + row*272 + ch*16, g_wl + (size_t)row*Dd + ch*8);
    }
    cp_commit();

    // ---- scale mu and split to fp16 hi/lo A-fragments (overlaps loads) ----
    #pragma unroll
    for (int f = 0; f < 16; f++) {
        muc[f][0] *= s20; muc[f][1] *= s20;
        muc[f][2] *= s21; muc[f][3] *= s21;
    }
    uint32_t mAH[8][4], mAL[8][4];
    #pragma unroll
    for (int kk = 0; kk < 8; kk++) {
        #pragma unroll
        for (int g = 0; g < 2; g++) {
            int f = 2*kk + g;
            __half h0 = __float2half_rn(muc[f][0]), h1 = __float2half_rn(muc[f][1]);
            __half h2 = __float2half_rn(muc[f][2]), h3 = __float2half_rn(muc[f][3]);
            mAH[kk][2*g+0] = (uint32_t)__half_as_ushort(h0) | ((uint32_t)__half_as_ushort(h1) << 16);
            mAH[kk][2*g+1] = (uint32_t)__half_as_ushort(h2) | ((uint32_t)__half_as_ushort(h3) << 16);
            mAL[kk][2*g+0] = packh(muc[f][0] - __half2float(h0), muc[f][1] - __half2float(h1));
            mAL[kk][2*g+1] = packh(muc[f][2] - __half2float(h2), muc[f][3] - __half2float(h3));
        }
    }

    cp_wait0();
    __syncthreads();

    // ---- projection MMAs: u[16 x 128] = mu_spatial . Wo_spatial^T ----
    const uint32_t bWH = sb + 0     + (lb_n*STX + lb_kof)*2;
    const uint32_t bWL = sb + 34816 + (lb_n*STX + lb_kof)*2;

    float c2[16][4];
    #pragma unroll
    for (int q = 0; q < 16; q++)
        c2[q][0] = c2[q][1] = c2[q][2] = c2[q][3] = 0.f;

    #pragma unroll
    for (int kk = 0; kk < 8; kk++) {
        #pragma unroll
        for (int nb = 0; nb < 8; nb++) {
            uint32_t bH0, bH1, bH2, bH3, bL0, bL1, bL2, bL3;
            ldsm4(bH0, bH1, bH2, bH3, bWH + nb*(16*STX*2) + kk*32);
            ldsm4(bL0, bL1, bL2, bL3, bWL + nb*(16*STX*2) + kk*32);
            mma16816(c2[nb*2],   mAH[kk][0], mAH[kk][1], mAH[kk][2], mAH[kk][3], bH0, bH1);
            mma16816(c2[nb*2+1], mAH[kk][0], mAH[kk][1], mAH[kk][2], mAH[kk][3], bH2, bH3);
            mma16816(c2[nb*2],   mAH[kk][0], mAH[kk][1], mAH[kk][2], mAH[kk][3], bL0, bL1);
            mma16816(c2[nb*2+1], mAH[kk][0], mAH[kk][1], mAH[kk][2], mAH[kk][3], bL2, bL3);
            mma16816(c2[nb*2],   mAL[kk][0], mAL[kk][1], mAL[kk][2], mAL[kk][3], bH0, bH1);
            mma16816(c2[nb*2+1], mAL[kk][0], mAL[kk][1], mAL[kk][2], mAL[kk][3], bH2, bH3);
        }
    }

    // ---- epilogue: +mu0*Wo0 + bo, norm, tanh scale, write y/y2 ----
    const float* wo0s = (const float*)(smb + OWO0);
    const float* bos  = (const float*)(smb + OBO);

    float u[16][4];
    float pp0 = 0.f, pp1 = 0.f;
    #pragma unroll
    for (int q = 0; q < 16; q++) {
        int col = q*8 + cq;
        float w0 = wo0s[col], w1 = wo0s[col+1];
        float b0 = bos[col],  b1 = bos[col+1];
        u[q][0] = c2[q][0] + mu0a*w0 + b0;
        u[q][1] = c2[q][1] + mu0a*w1 + b1;
        u[q][2] = c2[q][2] + mu0b*w0 + b0;
        u[q][3] = c2[q][3] + mu0b*w1 + b1;
        pp0 += u[q][0]*u[q][0] + u[q][1]*u[q][1];
        pp1 += u[q][2]*u[q][2] + u[q][3]*u[q][3];
    }
    #pragma unroll
    for (int o = 1; o < 4; o <<= 1) {
        pp0 += __shfl_xor_sync(0xffffffffu, pp0, o);
        pp1 += __shfl_xor_sync(0xffffffffu, pp1, o);
    }
    float nu0 = fmaxf(sqrtf(pp0), EPSc);
    float nu1 = fmaxf(sqrtf(pp1), EPSc);
    float f0 = tanhf(SCc*nu0) / (SCc*nu0);
    float f1 = tanhf(SCc*nu1) / (SCc*nu1);

    float* y0 = g_y + ((size_t)b*Nd + i0 + r0) * Dd;
    float* y1 = y0 + (size_t)8 * Dd;
    float qq0 = 0.f, qq1 = 0.f;
    #pragma unroll
    for (int q = 0; q < 16; q++) {
        int col = q*8 + cq;
        float v00 = u[q][0]*f0, v01 = u[q][1]*f0;
        float v10 = u[q][2]*f1, v11 = u[q][3]*f1;
        *(float2*)(y0 + col) = make_float2(v00, v01);
        *(float2*)(y1 + col) = make_float2(v10, v11);
        qq0 += v00*v00 + v01*v01;
        qq1 += v10*v10 + v11*v11;
    }
    #pragma unroll
    for (int o = 1; o < 4; o <<= 1) {
        qq0 += __shfl_xor_sync(0xffffffffu, qq0, o);
        qq1 += __shfl_xor_sync(0xffffffffu, qq1, o);
    }
    if ((lane & 3) == 0) {
        g_y2[(size_t)b*Nd + i0 + r0]     = qq0;
        g_y2[(size_t)b*Nd + i0 + r0 + 8] = qq1;
    }
}

// ---------------- kernel 4: Mobius pooling + MLR head (deep prefetch) ------
__global__ void k_pool(const float* __restrict__ Wf,
                       const float* __restrict__ bf,
                       float* __restrict__ out)
{
    const int b    = blockIdx.x;
    const int lane = threadIdx.x;
    const float* yb  = g_y  + (size_t)b*Nd*Dd;
    const float* y2b = g_y2 + (size_t)b*Nd;
    const unsigned char* mb = g_mask + (size_t)b*Nd;

    float a0=0.f, a1=0.f, a2=0.f, a3=0.f;
    int cnt = 0;

    float4 yB[2][8];
    float  y2B[2][8];
    unsigned long long mB[2];

    #pragma unroll
    for (int t = 0; t < 8; t++)
        yB[0][t] = *(const float4*)(yb + (size_t)t*Dd + lane*4);
    {
        float4 q0 = *(const float4*)(y2b + 0);
        float4 q1 = *(const float4*)(y2b + 4);
        y2B[0][0]=q0.x; y2B[0][1]=q0.y; y2B[0][2]=q0.z; y2B[0][3]=q0.w;
        y2B[0][4]=q1.x; y2B[0][5]=q1.y; y2B[0][6]=q1.z; y2B[0][7]=q1.w;
        mB[0] = *(const unsigned long long*)(mb);
    }

    int cur = 0;
    for (int ch = 0; ch < Nd/8; ch++) {
        int nxt = cur ^ 1;
        if (ch + 1 < Nd/8) {
            const float* ybn = yb + (size_t)(ch+1)*8*Dd;
            #pragma unroll
            for (int t = 0; t < 8; t++)
                yB[nxt][t] = *(const float4*)(ybn + (size_t)t*Dd + lane*4);
            float4 q0 = *(const float4*)(y2b + (ch+1)*8);
            float4 q1 = *(const float4*)(y2b + (ch+1)*8 + 4);
            y2B[nxt][0]=q0.x; y2B[nxt][1]=q0.y; y2B[nxt][2]=q0.z; y2B[nxt][3]=q0.w;
            y2B[nxt][4]=q1.x; y2B[nxt][5]=q1.y; y2B[nxt][6]=q1.z; y2B[nxt][7]=q1.w;
            mB[nxt] = *(const unsigned long long*)(mb + (ch+1)*8);
        }
        unsigned long long m8 = mB[cur];
        #pragma unroll
        for (int t = 0; t < 8; t++) {
            if ((m8 >> (t*8)) & 0xFFull) {
                float4 yv = yB[cur][t];
                float yy2 = y2B[cur][t];
                float xy = a0*yv.x + a1*yv.y + a2*yv.z + a3*yv.w;
                float x2 = a0*a0 + a1*a1 + a2*a2 + a3*a3;
                #pragma unroll
                for (int o = 16; o; o >>= 1) {
                    xy += __shfl_xor_sync(0xffffffffu, xy, o);
                    x2 += __shfl_xor_sync(0xffffffffu, x2, o);
                }
                float aa  = 1.f + 2.f*CC*xy + CC*yy2;
                float bb  = 1.f - CC*x2;
                float den = fmaxf(1.f + 2.f*CC*xy + CC*CC*x2*yy2, 1e-12f);
                a0 = (aa*a0 + bb*yv.x) / den;
                a1 = (aa*a1 + bb*yv.y) / den;
                a2 = (aa*a2 + bb*yv.z) / den;
                a3 = (aa*a3 + bb*yv.w) / den;
                cnt++;
            }
        }
        cur = nxt;
    }

    float n2 = a0*a0 + a1*a1 + a2*a2 + a3*a3;
    #pragma unroll
    for (int o = 16; o; o >>= 1) n2 += __shfl_xor_sync(0xffffffffu, n2, o);
    float nrm = sqrtf(n2);
    float t   = fminf(fmaxf(SCc*nrm, EPSc), 1.f - 1e-6f);
    float r   = 1.f / fmaxf((float)cnt, 1.f);
    float fac = tanhf(r * atanhf(t)) / fmaxf(SCc*nrm, EPSc);
    float p0 = fac*a0, p1 = fac*a1, p2 = fac*a2, p3 = fac*a3;
    if (cnt == 0) {
        float4 y0 = *(const float4*)(yb + lane*4);
        p0 = y0.x; p1 = y0.y; p2 = y0.z; p3 = y0.w;
    }

    float pn2 = p0*p0 + p1*p1 + p2*p2 + p3*p3;
    #pragma unroll
    for (int o = 16; o; o >>= 1) pn2 += __shfl_xor_sync(0xffffffffu, pn2, o);
    float npn = fmaxf(sqrtf(pn2), EPSc);
    float t2  = fminf(fmaxf(SCc*npn, EPSc), 1.f - 1e-6f);
    float cf  = atanhf(t2) / (SCc*npn);
    float v0 = cf*p0, v1 = cf*p1, v2 = cf*p2, v3 = cf*p3;

    for (int k = 0; k < NCd; k++) {
        float4 w = *(const float4*)(Wf + (size_t)k*Dd + lane*4);
        float pr = v0*w.x + v1*w.y + v2*w.z + v3*w.w;
        #pragma unroll
        for (int o = 16; o; o >>= 1) pr += __shfl_xor_sync(0xffffffffu, pr, o);
        if (lane == 0) out[b*NCd + k] = pr + bf[k];
    }
}

// ---------------------------- launcher -------------------------------------
extern "C" void kernel_launch(void* const* d_in, const int* in_sizes, int n_in,
                              void* d_out, int out_size)
{
    (void)in_sizes; (void)n_in; (void)out_size;
    const int*   tok  = (const int*)d_in[0];
    const void*  mask = d_in[1];
    const float* emb  = (const float*)d_in[2];
    const float* Wo   = (const float*)d_in[3];
    const float* bo   = (const float*)d_in[4];
    const float* Wf   = (const float*)d_in[5];
    const float* bf   = (const float*)d_in[6];
    float*       out  = (float*)d_out;

    cudaFuncSetAttribute(k_attn_mma, cudaFuncAttributeMaxDynamicSharedMemorySize, ATT_SMEM);

    k_detect   <<<1, 1024>>>((const uint4*)mask);
    k_masknorm <<<(Bd*Nd + 255)/256, 256>>>(mask);
    k_wprep    <<<(Dd*Dd + 255)/256, 256>>>(Wo);
    k_embed    <<<(Bd*Nd)/8, 256>>>(tok, emb);
    k_attn_mma <<<dim3(16, Bd), 128, ATT_SMEM>>>(bo);
    k_pool     <<<Bd, 32>>>(Wf, bf, out);
}